// round 1
// baseline (speedup 1.0000x reference)
#include <cuda_runtime.h>
#include <cstdint>

// ---------------------------------------------------------------------------
// SGCEncoder: out = prop(relu(prop(x) @ W1 + b1)) @ W2 + b2
// with prop = D^-1/2 (A+I) D^-1/2.
//
// Rewrites:
//   prop(x)[d] = dinv[d] * ( sum_{s->d} x[s]*dinv[s]  +  x[d]*dinv[d] )
//   prop(H1) @ W2 = prop(H1 @ W2)        (propagate at D=128, not 256)
// ---------------------------------------------------------------------------

#define N_NODES 50000
#define M_PAD   50048          // 391 * 128, pad so GEMM needs no row guards
#define D0      256
#define D2      128

// scratch (static __device__ globals: allocation-free)
__device__ int   g_deg [M_PAD];
__device__ float g_dinv[M_PAD];
__device__ float g_xs  [M_PAD * D0];   // x * dinv (gather source, hop 1)
__device__ float g_acc0[M_PAD * D0];   // hop-1 accumulator (init = self loop)
__device__ float g_h1  [M_PAD * D0];   // relu(dinv*acc0 @ W1 + b1)
__device__ float g_gs  [M_PAD * D2];   // (H1 @ W2) * dinv (gather source, hop 2)
__device__ float g_acc1[M_PAD * D2];   // hop-2 accumulator

// ---------------------------------------------------------------------------

__global__ void k_zero_deg() {
    int i = blockIdx.x * blockDim.x + threadIdx.x;
    if (i < M_PAD) g_deg[i] = 0;
}

__global__ void k_deg(const int* __restrict__ dst, int E) {
    int i = blockIdx.x * blockDim.x + threadIdx.x;
    if (i < E) atomicAdd(&g_deg[dst[i]], 1);
}

__global__ void k_dinv() {
    int i = blockIdx.x * blockDim.x + threadIdx.x;
    if (i < M_PAD)
        g_dinv[i] = (i < N_NODES) ? rsqrtf((float)(g_deg[i] + 1)) : 0.0f;
}

// xs = x * dinv[row]; acc0 = xs (self-loop init). Padded rows -> 0.
__global__ void k_scale_init(const float* __restrict__ x) {
    int i = blockIdx.x * blockDim.x + threadIdx.x;          // float4 index
    if (i >= M_PAD * (D0 / 4)) return;
    int row = i >> 6;                                       // / (D0/4)
    float4 v = make_float4(0.f, 0.f, 0.f, 0.f);
    if (row < N_NODES) {
        v = ((const float4*)x)[i];
        float s = g_dinv[row];
        v.x *= s; v.y *= s; v.z *= s; v.w *= s;
    }
    ((float4*)g_xs)[i]   = v;
    ((float4*)g_acc0)[i] = v;
}

__device__ __forceinline__ void red_add_f4(float* p, float4 v) {
    asm volatile("red.add.v4.f32 [%0], {%1,%2,%3,%4};"
                 :: "l"(p), "f"(v.x), "f"(v.y), "f"(v.z), "f"(v.w) : "memory");
}

// hop 1 scatter, D=256: one warp per edge, 2 float4 per lane
__global__ void k_scatter256(const int* __restrict__ src, const int* __restrict__ dst, int E) {
    int w = (blockIdx.x * blockDim.x + threadIdx.x) >> 5;
    if (w >= E) return;
    int lane = threadIdx.x & 31;
    int s = __ldg(&src[w]);
    int d = __ldg(&dst[w]);
    const float4* xs  = (const float4*)g_xs + (size_t)s * (D0 / 4);
    float*        acc = g_acc0 + (size_t)d * D0;
    float4 a = __ldg(&xs[lane]);
    float4 b = __ldg(&xs[lane + 32]);
    red_add_f4(acc + lane * 4, a);
    red_add_f4(acc + (lane + 32) * 4, b);
}

// hop 2 scatter, D=128: one warp per edge, 1 float4 per lane
__global__ void k_scatter128(const int* __restrict__ src, const int* __restrict__ dst, int E) {
    int w = (blockIdx.x * blockDim.x + threadIdx.x) >> 5;
    if (w >= E) return;
    int lane = threadIdx.x & 31;
    int s = __ldg(&src[w]);
    int d = __ldg(&dst[w]);
    const float4* gs  = (const float4*)g_gs + (size_t)s * (D2 / 4);
    float*        acc = g_acc1 + (size_t)d * D2;
    float4 a = __ldg(&gs[lane]);
    red_add_f4(acc + lane * 4, a);
}

// ---------------------------------------------------------------------------
// fp32 tiled GEMM: C[M_PAD, Ncols] = A[M_PAD, 256] @ B[256, Ncols]
// BM=128, BN=128, BK=16, 256 threads, 8x8 accum per thread.
// MODE 1: A = g_acc0 scaled by dinv[row]; C = g_h1 = relu(.. + bias)
// MODE 2: A = g_h1;  C = g_gs and g_acc1 = (..) * dinv[row]
// ---------------------------------------------------------------------------
template<int MODE>
__global__ void __launch_bounds__(256, 2)
k_gemm(const float* __restrict__ B, const float* __restrict__ bias, int Ncols) {
    const float* A = (MODE == 1) ? g_acc0 : g_h1;

    __shared__ float As[16][132];   // A^T tile, padded stride (bank spread)
    __shared__ float Bs[16][128];

    float acc[8][8];
#pragma unroll
    for (int i = 0; i < 8; i++)
#pragma unroll
        for (int j = 0; j < 8; j++) acc[i][j] = 0.f;

    const int tid = threadIdx.x;
    const int tx = tid & 15, ty = tid >> 4;
    const int rowBase = blockIdx.y * 128;
    const int colBase = blockIdx.x * 128;

    // A-tile load mapping: this thread owns rows r0, r1 at k-chunk kc
    const int r0 = tid >> 2;
    const int r1 = 64 + r0;
    const int kc = (tid & 3) * 4;
    float s0 = 1.f, s1 = 1.f;
    if (MODE == 1) { s0 = g_dinv[rowBase + r0]; s1 = g_dinv[rowBase + r1]; }
    const float* A0 = A + (size_t)(rowBase + r0) * D0 + kc;
    const float* A1 = A + (size_t)(rowBase + r1) * D0 + kc;
    const float* Bp = B + colBase;

    // B-tile load mapping
    const int br0 = tid >> 5;              // 0..7
    const int bc0 = (tid & 31) * 4;
    const int br1 = br0 + 8;

    for (int kk = 0; kk < 256; kk += 16) {
        float4 va = *(const float4*)(A0 + kk);
        float4 vb = *(const float4*)(A1 + kk);
        As[kc + 0][r0] = va.x * s0; As[kc + 1][r0] = va.y * s0;
        As[kc + 2][r0] = va.z * s0; As[kc + 3][r0] = va.w * s0;
        As[kc + 0][r1] = vb.x * s1; As[kc + 1][r1] = vb.y * s1;
        As[kc + 2][r1] = vb.z * s1; As[kc + 3][r1] = vb.w * s1;

        *(float4*)&Bs[br0][bc0] = *(const float4*)(Bp + (size_t)(kk + br0) * Ncols + bc0);
        *(float4*)&Bs[br1][bc0] = *(const float4*)(Bp + (size_t)(kk + br1) * Ncols + bc0);

        __syncthreads();
#pragma unroll
        for (int k = 0; k < 16; k++) {
            float a[8], b[8];
            *(float4*)(a)     = *(const float4*)&As[k][ty * 8];
            *(float4*)(a + 4) = *(const float4*)&As[k][ty * 8 + 4];
            *(float4*)(b)     = *(const float4*)&Bs[k][tx * 8];
            *(float4*)(b + 4) = *(const float4*)&Bs[k][tx * 8 + 4];
#pragma unroll
            for (int i = 0; i < 8; i++)
#pragma unroll
                for (int j = 0; j < 8; j++)
                    acc[i][j] += a[i] * b[j];
        }
        __syncthreads();
    }

    const int row0 = rowBase + ty * 8;
    const int col0 = colBase + tx * 8;

    if (MODE == 1) {
        float bb[8];
#pragma unroll
        for (int j = 0; j < 8; j++) bb[j] = bias[col0 + j];
#pragma unroll
        for (int i = 0; i < 8; i++) {
            float4 v0, v1;
            v0.x = fmaxf(acc[i][0] + bb[0], 0.f);
            v0.y = fmaxf(acc[i][1] + bb[1], 0.f);
            v0.z = fmaxf(acc[i][2] + bb[2], 0.f);
            v0.w = fmaxf(acc[i][3] + bb[3], 0.f);
            v1.x = fmaxf(acc[i][4] + bb[4], 0.f);
            v1.y = fmaxf(acc[i][5] + bb[5], 0.f);
            v1.z = fmaxf(acc[i][6] + bb[6], 0.f);
            v1.w = fmaxf(acc[i][7] + bb[7], 0.f);
            size_t off = (size_t)(row0 + i) * Ncols + col0;
            *(float4*)(g_h1 + off)     = v0;
            *(float4*)(g_h1 + off + 4) = v1;
        }
    } else {
#pragma unroll
        for (int i = 0; i < 8; i++) {
            float s = g_dinv[row0 + i];
            float4 v0, v1;
            v0.x = acc[i][0] * s; v0.y = acc[i][1] * s;
            v0.z = acc[i][2] * s; v0.w = acc[i][3] * s;
            v1.x = acc[i][4] * s; v1.y = acc[i][5] * s;
            v1.z = acc[i][6] * s; v1.w = acc[i][7] * s;
            size_t off = (size_t)(row0 + i) * Ncols + col0;
            *(float4*)(g_gs + off)       = v0;
            *(float4*)(g_gs + off + 4)   = v1;
            *(float4*)(g_acc1 + off)     = v0;
            *(float4*)(g_acc1 + off + 4) = v1;
        }
    }
}

// out[v] = acc1[v] * dinv[v] + b2
__global__ void k_final(const float* __restrict__ b2, float* __restrict__ out) {
    int i = blockIdx.x * blockDim.x + threadIdx.x;   // float4 index
    if (i >= N_NODES * (D2 / 4)) return;
    int row = i >> 5;
    int c4  = i & 31;
    float4 v = ((const float4*)g_acc1)[i];
    float  s = g_dinv[row];
    float4 b = ((const float4*)b2)[c4];
    float4 o;
    o.x = v.x * s + b.x;
    o.y = v.y * s + b.y;
    o.z = v.z * s + b.z;
    o.w = v.w * s + b.w;
    ((float4*)out)[i] = o;
}

// ---------------------------------------------------------------------------

extern "C" void kernel_launch(void* const* d_in, const int* in_sizes, int n_in,
                              void* d_out, int out_size) {
    const float* x  = (const float*)d_in[0];
    const int*   ei = (const int*)  d_in[1];
    const float* W1 = (const float*)d_in[2];
    const float* b1 = (const float*)d_in[3];
    const float* W2 = (const float*)d_in[4];
    const float* b2 = (const float*)d_in[5];
    float* out = (float*)d_out;

    const int E = in_sizes[1] / 2;
    const int* src = ei;
    const int* dst = ei + E;

    // degree + norm
    k_zero_deg<<<(M_PAD + 255) / 256, 256>>>();
    k_deg<<<(E + 255) / 256, 256>>>(dst, E);
    k_dinv<<<(M_PAD + 255) / 256, 256>>>();

    // hop 1: xs = x*dinv, acc0 = xs + scatter
    k_scale_init<<<(M_PAD * (D0 / 4) + 255) / 256, 256>>>(x);
    k_scatter256<<<(E + 7) / 8, 256>>>(src, dst, E);

    // H1 = relu((dinv*acc0) @ W1 + b1)
    k_gemm<1><<<dim3(2, M_PAD / 128), 256>>>(W1, b1, D0);

    // gs = acc1 = (H1 @ W2) * dinv ; hop 2 scatter
    k_gemm<2><<<dim3(1, M_PAD / 128), 256>>>(W2, nullptr, D2);
    k_scatter128<<<(E + 7) / 8, 256>>>(src, dst, E);

    // out = acc1 * dinv + b2
    k_final<<<(N_NODES * (D2 / 4) + 255) / 256, 256>>>(b2, out);
}

// round 2
// speedup vs baseline: 1.8231x; 1.8231x over previous
#include <cuda_runtime.h>
#include <cstdint>

// ---------------------------------------------------------------------------
// SGCEncoder: out = prop(relu(prop(x) @ W1 + b1)) @ W2 + b2
//   prop = D^-1/2 (A+I) D^-1/2
// Rewrites:
//   prop(x)[d] = dinv[d] * ( sum_{s->d} xs[s] + xs[d] ),  xs = x*dinv
//   prop(H1) @ W2 = prop(H1 @ W2)          (propagate at D=128, not 256)
// Round 2: CSR-by-dst gather-sum (no float atomics), fused epilogues.
// ---------------------------------------------------------------------------

#define N_NODES 50000
#define M_PAD   50048          // 391 * 128, pad so GEMM needs no row guards
#define D0      256
#define D2      128
#define E_MAX   1600000

__device__ int   g_deg   [M_PAD];
__device__ int   g_rowptr[M_PAD + 1];
__device__ int   g_cursor[M_PAD];
__device__ int   g_esrc  [E_MAX];        // CSR: src ids grouped by dst
__device__ float g_dinv  [M_PAD];
__device__ float g_xs    [M_PAD * D0];   // x * dinv (hop-1 gather source)
__device__ float g_acc0  [M_PAD * D0];   // hop-1 result (= dinv * (sum + self))
__device__ float g_h1    [M_PAD * D0];   // relu(acc0 @ W1 + b1)
__device__ float g_gs    [M_PAD * D2];   // (H1 @ W2) * dinv (hop-2 gather source)

// ---------------------------------------------------------------------------

__global__ void k_zero_deg() {
    int i = blockIdx.x * blockDim.x + threadIdx.x;
    if (i < M_PAD) g_deg[i] = 0;
}

__global__ void k_deg(const int* __restrict__ dst, int E) {
    int i = blockIdx.x * blockDim.x + threadIdx.x;
    if (i < E) atomicAdd(&g_deg[dst[i]], 1);
}

__global__ void k_dinv() {
    int i = blockIdx.x * blockDim.x + threadIdx.x;
    if (i < M_PAD)
        g_dinv[i] = (i < N_NODES) ? rsqrtf((float)(g_deg[i] + 1)) : 0.0f;
}

// single-block exclusive scan of g_deg -> g_rowptr / g_cursor
__global__ void __launch_bounds__(1024, 1) k_scan(int E) {
    __shared__ int warp_red[32];
    __shared__ int sh_carry;
    const int tid  = threadIdx.x;
    const int lane = tid & 31;
    const int wid  = tid >> 5;
    if (tid == 0) sh_carry = 0;

    for (int base = 0; base < M_PAD; base += 1024) {
        __syncthreads();
        int carry = sh_carry;
        int idx = base + tid;
        int v = (idx < M_PAD) ? g_deg[idx] : 0;

        // inclusive warp scan
        int inc = v;
#pragma unroll
        for (int off = 1; off < 32; off <<= 1) {
            int t = __shfl_up_sync(0xffffffff, inc, off);
            if (lane >= off) inc += t;
        }
        if (lane == 31) warp_red[wid] = inc;
        __syncthreads();
        if (wid == 0) {
            int w = warp_red[lane];
            int wi = w;
#pragma unroll
            for (int off = 1; off < 32; off <<= 1) {
                int t = __shfl_up_sync(0xffffffff, wi, off);
                if (lane >= off) wi += t;
            }
            warp_red[lane] = wi;   // inclusive scan of warp sums
        }
        __syncthreads();
        int warp_off = (wid > 0) ? warp_red[wid - 1] : 0;
        int excl = carry + warp_off + (inc - v);
        if (idx < M_PAD) { g_rowptr[idx] = excl; g_cursor[idx] = excl; }
        int total = warp_red[31];
        __syncthreads();
        if (tid == 0) sh_carry = carry + total;
    }
    __syncthreads();
    if (tid == 0) g_rowptr[M_PAD] = sh_carry;   // == E
}

__global__ void k_fill(const int* __restrict__ src, const int* __restrict__ dst, int E) {
    int i = blockIdx.x * blockDim.x + threadIdx.x;
    if (i >= E) return;
    int pos = atomicAdd(&g_cursor[dst[i]], 1);
    g_esrc[pos] = src[i];
}

// xs = x * dinv[row]
__global__ void k_scale(const float* __restrict__ x) {
    int i = blockIdx.x * blockDim.x + threadIdx.x;          // float4 index
    if (i >= M_PAD * (D0 / 4)) return;
    int row = i >> 6;
    float4 v = make_float4(0.f, 0.f, 0.f, 0.f);
    if (row < N_NODES) {
        v = ((const float4*)x)[i];
        float s = g_dinv[row];
        v.x *= s; v.y *= s; v.z *= s; v.w *= s;
    }
    ((float4*)g_xs)[i] = v;
}

__device__ __forceinline__ void f4add(float4& a, float4 b) {
    a.x += b.x; a.y += b.y; a.z += b.z; a.w += b.w;
}

// hop-1 gather, D=256: one warp per dst row; acc = xs[d] + sum xs[s]; *dinv[d]
__global__ void __launch_bounds__(256) k_gather256() {
    int w = (blockIdx.x * blockDim.x + threadIdx.x) >> 5;
    if (w >= M_PAD) return;
    const int lane = threadIdx.x & 31;
    float4 a0 = make_float4(0.f, 0.f, 0.f, 0.f);
    float4 a1 = a0;
    if (w < N_NODES) {
        const float4* xs = (const float4*)g_xs;
        const float4* rowd = xs + (size_t)w * 64;
        a0 = __ldg(&rowd[lane]);
        a1 = __ldg(&rowd[lane + 32]);
        int e   = __ldg(&g_rowptr[w]);
        int end = __ldg(&g_rowptr[w + 1]);
        for (; e + 1 < end; e += 2) {
            int s0 = __ldg(&g_esrc[e]);
            int s1 = __ldg(&g_esrc[e + 1]);
            const float4* r0 = xs + (size_t)s0 * 64;
            const float4* r1 = xs + (size_t)s1 * 64;
            float4 v00 = __ldg(&r0[lane]);
            float4 v01 = __ldg(&r0[lane + 32]);
            float4 v10 = __ldg(&r1[lane]);
            float4 v11 = __ldg(&r1[lane + 32]);
            f4add(a0, v00); f4add(a1, v01);
            f4add(a0, v10); f4add(a1, v11);
        }
        if (e < end) {
            int s0 = __ldg(&g_esrc[e]);
            const float4* r0 = xs + (size_t)s0 * 64;
            f4add(a0, __ldg(&r0[lane]));
            f4add(a1, __ldg(&r0[lane + 32]));
        }
        float s = g_dinv[w];
        a0.x *= s; a0.y *= s; a0.z *= s; a0.w *= s;
        a1.x *= s; a1.y *= s; a1.z *= s; a1.w *= s;
    }
    float4* acc = (float4*)g_acc0 + (size_t)w * 64;
    acc[lane]      = a0;
    acc[lane + 32] = a1;
}

// hop-2 gather, D=128: one warp per dst row; out = dinv*(gs[d]+sum gs[s]) + b2
__global__ void __launch_bounds__(256) k_gather128(const float* __restrict__ b2,
                                                   float* __restrict__ out) {
    int w = (blockIdx.x * blockDim.x + threadIdx.x) >> 5;
    if (w >= N_NODES) return;
    const int lane = threadIdx.x & 31;
    const float4* gs = (const float4*)g_gs;
    float4 a0 = __ldg(&gs[(size_t)w * 32 + lane]);
    int e   = __ldg(&g_rowptr[w]);
    int end = __ldg(&g_rowptr[w + 1]);
    for (; e + 1 < end; e += 2) {
        int s0 = __ldg(&g_esrc[e]);
        int s1 = __ldg(&g_esrc[e + 1]);
        float4 v0 = __ldg(&gs[(size_t)s0 * 32 + lane]);
        float4 v1 = __ldg(&gs[(size_t)s1 * 32 + lane]);
        f4add(a0, v0); f4add(a0, v1);
    }
    if (e < end) {
        int s0 = __ldg(&g_esrc[e]);
        f4add(a0, __ldg(&gs[(size_t)s0 * 32 + lane]));
    }
    float s = g_dinv[w];
    float4 b = __ldg(&((const float4*)b2)[lane]);
    float4 o;
    o.x = a0.x * s + b.x;
    o.y = a0.y * s + b.y;
    o.z = a0.z * s + b.z;
    o.w = a0.w * s + b.w;
    ((float4*)out)[(size_t)w * 32 + lane] = o;
}

// ---------------------------------------------------------------------------
// fp32 tiled GEMM: C[M_PAD, Ncols] = A[M_PAD, 256] @ B[256, Ncols]
// BM=128, BN=128, BK=16, 256 threads, 8x8 accum per thread.
// MODE 1: A = g_acc0; C = g_h1 = relu(.. + bias)
// MODE 2: A = g_h1;   C = g_gs = (..) * dinv[row]
// ---------------------------------------------------------------------------
template<int MODE>
__global__ void __launch_bounds__(256, 2)
k_gemm(const float* __restrict__ B, const float* __restrict__ bias, int Ncols) {
    const float* A = (MODE == 1) ? g_acc0 : g_h1;

    __shared__ float As[16][132];
    __shared__ float Bs[16][128];

    float acc[8][8];
#pragma unroll
    for (int i = 0; i < 8; i++)
#pragma unroll
        for (int j = 0; j < 8; j++) acc[i][j] = 0.f;

    const int tid = threadIdx.x;
    const int tx = tid & 15, ty = tid >> 4;
    const int rowBase = blockIdx.y * 128;
    const int colBase = blockIdx.x * 128;

    const int r0 = tid >> 2;
    const int r1 = 64 + r0;
    const int kc = (tid & 3) * 4;
    const float* A0 = A + (size_t)(rowBase + r0) * D0 + kc;
    const float* A1 = A + (size_t)(rowBase + r1) * D0 + kc;
    const float* Bp = B + colBase;

    const int br0 = tid >> 5;
    const int bc0 = (tid & 31) * 4;
    const int br1 = br0 + 8;

    for (int kk = 0; kk < 256; kk += 16) {
        float4 va = *(const float4*)(A0 + kk);
        float4 vb = *(const float4*)(A1 + kk);
        As[kc + 0][r0] = va.x; As[kc + 1][r0] = va.y;
        As[kc + 2][r0] = va.z; As[kc + 3][r0] = va.w;
        As[kc + 0][r1] = vb.x; As[kc + 1][r1] = vb.y;
        As[kc + 2][r1] = vb.z; As[kc + 3][r1] = vb.w;

        *(float4*)&Bs[br0][bc0] = *(const float4*)(Bp + (size_t)(kk + br0) * Ncols + bc0);
        *(float4*)&Bs[br1][bc0] = *(const float4*)(Bp + (size_t)(kk + br1) * Ncols + bc0);

        __syncthreads();
#pragma unroll
        for (int k = 0; k < 16; k++) {
            float a[8], b[8];
            *(float4*)(a)     = *(const float4*)&As[k][ty * 8];
            *(float4*)(a + 4) = *(const float4*)&As[k][ty * 8 + 4];
            *(float4*)(b)     = *(const float4*)&Bs[k][tx * 8];
            *(float4*)(b + 4) = *(const float4*)&Bs[k][tx * 8 + 4];
#pragma unroll
            for (int i = 0; i < 8; i++)
#pragma unroll
                for (int j = 0; j < 8; j++)
                    acc[i][j] += a[i] * b[j];
        }
        __syncthreads();
    }

    const int row0 = rowBase + ty * 8;
    const int col0 = colBase + tx * 8;

    if (MODE == 1) {
        float bb[8];
#pragma unroll
        for (int j = 0; j < 8; j++) bb[j] = bias[col0 + j];
#pragma unroll
        for (int i = 0; i < 8; i++) {
            float4 v0, v1;
            v0.x = fmaxf(acc[i][0] + bb[0], 0.f);
            v0.y = fmaxf(acc[i][1] + bb[1], 0.f);
            v0.z = fmaxf(acc[i][2] + bb[2], 0.f);
            v0.w = fmaxf(acc[i][3] + bb[3], 0.f);
            v1.x = fmaxf(acc[i][4] + bb[4], 0.f);
            v1.y = fmaxf(acc[i][5] + bb[5], 0.f);
            v1.z = fmaxf(acc[i][6] + bb[6], 0.f);
            v1.w = fmaxf(acc[i][7] + bb[7], 0.f);
            size_t off = (size_t)(row0 + i) * Ncols + col0;
            *(float4*)(g_h1 + off)     = v0;
            *(float4*)(g_h1 + off + 4) = v1;
        }
    } else {
#pragma unroll
        for (int i = 0; i < 8; i++) {
            float s = g_dinv[row0 + i];
            float4 v0, v1;
            v0.x = acc[i][0] * s; v0.y = acc[i][1] * s;
            v0.z = acc[i][2] * s; v0.w = acc[i][3] * s;
            v1.x = acc[i][4] * s; v1.y = acc[i][5] * s;
            v1.z = acc[i][6] * s; v1.w = acc[i][7] * s;
            size_t off = (size_t)(row0 + i) * Ncols + col0;
            *(float4*)(g_gs + off)     = v0;
            *(float4*)(g_gs + off + 4) = v1;
        }
    }
}

// ---------------------------------------------------------------------------

extern "C" void kernel_launch(void* const* d_in, const int* in_sizes, int n_in,
                              void* d_out, int out_size) {
    const float* x  = (const float*)d_in[0];
    const int*   ei = (const int*)  d_in[1];
    const float* W1 = (const float*)d_in[2];
    const float* b1 = (const float*)d_in[3];
    const float* W2 = (const float*)d_in[4];
    const float* b2 = (const float*)d_in[5];
    float* out = (float*)d_out;

    const int E = in_sizes[1] / 2;
    const int* src = ei;
    const int* dst = ei + E;

    // CSR build + norms
    k_zero_deg<<<(M_PAD + 255) / 256, 256>>>();
    k_deg<<<(E + 255) / 256, 256>>>(dst, E);
    k_dinv<<<(M_PAD + 255) / 256, 256>>>();
    k_scan<<<1, 1024>>>(E);
    k_fill<<<(E + 255) / 256, 256>>>(src, dst, E);

    // hop 1
    k_scale<<<(M_PAD * (D0 / 4) + 255) / 256, 256>>>(x);
    k_gather256<<<(M_PAD * 32 + 255) / 256, 256>>>();

    // H1 = relu(acc0 @ W1 + b1)
    k_gemm<1><<<dim3(2, M_PAD / 128), 256>>>(W1, b1, D0);

    // gs = (H1 @ W2) * dinv ; hop 2 + bias -> out
    k_gemm<2><<<dim3(1, M_PAD / 128), 256>>>(W2, nullptr, D2);
    k_gather128<<<(N_NODES * 32 + 255) / 256, 256>>>(b2, out);
}

// round 4
// speedup vs baseline: 2.4465x; 1.3419x over previous
#include <cuda_runtime.h>
#include <cuda_bf16.h>
#include <cstdint>

// ---------------------------------------------------------------------------
// SGCEncoder: out = prop(relu(prop(x) @ W1 + b1)) @ W2 + b2
//   prop = D^-1/2 (A+I) D^-1/2
// Rewrites:
//   prop(x)[d] = dinv[d] * ( sum_{s->d} xs[s] + xs[d] ),  xs = x*dinv
//   prop(H1) @ W2 = prop(H1 @ W2)          (propagate at D=128)
// Round 4: mma.sync (HMMA) bf16-split GEMMs -- tcgen05 PTX is rejected by the
// harness toolchain (target sm_103 without 'a'), mma.sync is baseline PTX.
// ---------------------------------------------------------------------------

#define N_NODES 50000
#define M_PAD   50048          // 391 * 128
#define D0      256
#define D2      128
#define E_MAX   1600000
#define NTILE_M 391

__device__ int   g_deg   [M_PAD];
__device__ int   g_rowptr[M_PAD + 1];
__device__ int   g_cursor[M_PAD];
__device__ int   g_esrc  [E_MAX];
__device__ int   g_bsum  [64];
__device__ int   g_boff  [64];
__device__ float g_dinv  [M_PAD];
__device__ float g_xs    [M_PAD * D0];       // x * dinv (hop-1 gather source)
__device__ float g_gs    [M_PAD * D2];       // (H1 @ W2) * dinv (hop-2 source)
__device__ __nv_bfloat16 g_ahi [M_PAD * D0]; // hop-1 result, bf16 hi
__device__ __nv_bfloat16 g_alo [M_PAD * D0]; // hop-1 result, bf16 lo
__device__ __nv_bfloat16 g_h1hi[M_PAD * D0];
__device__ __nv_bfloat16 g_h1lo[M_PAD * D0];
__device__ __nv_bfloat16 g_w1h [D0 * D0];    // W1^T [n][k] bf16 hi
__device__ __nv_bfloat16 g_w1l [D0 * D0];
__device__ __nv_bfloat16 g_w2h [D2 * D0];    // W2^T [n][k]
__device__ __nv_bfloat16 g_w2l [D2 * D0];

// --------------------------- CSR build --------------------------------------

__global__ void k_zero_deg() {
    int i = blockIdx.x * blockDim.x + threadIdx.x;
    if (i < M_PAD) g_deg[i] = 0;
}
__global__ void k_deg(const int* __restrict__ dst, int E) {
    int i = blockIdx.x * blockDim.x + threadIdx.x;
    if (i < E) atomicAdd(&g_deg[dst[i]], 1);
}
__global__ void k_dinv() {
    int i = blockIdx.x * blockDim.x + threadIdx.x;
    if (i < M_PAD)
        g_dinv[i] = (i < N_NODES) ? rsqrtf((float)(g_deg[i] + 1)) : 0.0f;
}

// block-local exclusive scan (1024/block) + block totals
__global__ void __launch_bounds__(1024) k_scan1() {
    __shared__ int warp_red[32];
    const int tid = threadIdx.x, lane = tid & 31, wid = tid >> 5;
    int idx = blockIdx.x * 1024 + tid;
    int v = (idx < M_PAD) ? g_deg[idx] : 0;
    int inc = v;
#pragma unroll
    for (int off = 1; off < 32; off <<= 1) {
        int t = __shfl_up_sync(0xffffffff, inc, off);
        if (lane >= off) inc += t;
    }
    if (lane == 31) warp_red[wid] = inc;
    __syncthreads();
    if (wid == 0) {
        int w = warp_red[lane];
#pragma unroll
        for (int off = 1; off < 32; off <<= 1) {
            int t = __shfl_up_sync(0xffffffff, w, off);
            if (lane >= off) w += t;
        }
        warp_red[lane] = w;
    }
    __syncthreads();
    int excl = ((wid > 0) ? warp_red[wid - 1] : 0) + (inc - v);
    if (idx < M_PAD) g_rowptr[idx] = excl;
    if (tid == 1023) g_bsum[blockIdx.x] = warp_red[31];
}
__global__ void k_scan2(int nb) {
    if (threadIdx.x == 0) {
        int run = 0;
        for (int b = 0; b < nb; b++) { g_boff[b] = run; run += g_bsum[b]; }
    }
}
__global__ void __launch_bounds__(1024) k_scan3(int E) {
    int idx = blockIdx.x * 1024 + threadIdx.x;
    if (idx < M_PAD) {
        int v = g_rowptr[idx] + g_boff[idx >> 10];
        g_rowptr[idx] = v;
        g_cursor[idx] = v;
    } else if (idx == M_PAD) {
        g_rowptr[M_PAD] = E;
    }
}
__global__ void k_fill(const int* __restrict__ src, const int* __restrict__ dst, int E) {
    int i = blockIdx.x * blockDim.x + threadIdx.x;
    if (i >= E) return;
    int pos = atomicAdd(&g_cursor[dst[i]], 1);
    g_esrc[pos] = src[i];
}

// --------------------------- pre/post scale ---------------------------------

__global__ void k_scale(const float* __restrict__ x) {
    int i = blockIdx.x * blockDim.x + threadIdx.x;      // float4 index
    if (i >= M_PAD * (D0 / 4)) return;
    int row = i >> 6;
    float4 v = make_float4(0.f, 0.f, 0.f, 0.f);
    if (row < N_NODES) {
        v = ((const float4*)x)[i];
        float s = g_dinv[row];
        v.x *= s; v.y *= s; v.z *= s; v.w *= s;
    }
    ((float4*)g_xs)[i] = v;
}

// W split + transpose: B[n][k] = W[k][n], bf16 hi/lo
__global__ void k_wsplit(const float* __restrict__ W1, const float* __restrict__ W2) {
    int i = blockIdx.x * blockDim.x + threadIdx.x;
    if (i < D0 * D0) {
        int n = i >> 8, k = i & 255;
        float v = W1[k * D0 + n];
        __nv_bfloat16 h = __float2bfloat16(v);
        g_w1h[n * D0 + k] = h;
        g_w1l[n * D0 + k] = __float2bfloat16(v - __bfloat162float(h));
    } else if (i < D0 * D0 + D2 * D0) {
        int j = i - D0 * D0;
        int n = j >> 8, k = j & 255;
        float v = W2[k * D2 + n];
        __nv_bfloat16 h = __float2bfloat16(v);
        g_w2h[n * D0 + k] = h;
        g_w2l[n * D0 + k] = __float2bfloat16(v - __bfloat162float(h));
    }
}

__device__ __forceinline__ void f4add(float4& a, float4 b) {
    a.x += b.x; a.y += b.y; a.z += b.z; a.w += b.w;
}
__device__ __forceinline__ uint32_t pack2(__nv_bfloat16 a, __nv_bfloat16 b) {
    __nv_bfloat162 t = __nv_bfloat162(a, b);
    return *reinterpret_cast<uint32_t*>(&t);
}
// split pair of floats -> packed hi bf16x2 + lo bf16x2
__device__ __forceinline__ void split2(float v0, float v1, uint32_t& hi, uint32_t& lo) {
    __nv_bfloat16 h0 = __float2bfloat16(v0), h1 = __float2bfloat16(v1);
    hi = pack2(h0, h1);
    lo = pack2(__float2bfloat16(v0 - __bfloat162float(h0)),
               __float2bfloat16(v1 - __bfloat162float(h1)));
}
__device__ __forceinline__ void split4(float4 v, uint2& hi, uint2& lo) {
    split2(v.x, v.y, hi.x, lo.x);
    split2(v.z, v.w, hi.y, lo.y);
}

// --------------------------- gathers ----------------------------------------

// hop-1 gather, D=256: warp per dst row; writes bf16 hi/lo of dinv*(self+sum)
__global__ void __launch_bounds__(256) k_gather256() {
    int w = (blockIdx.x * blockDim.x + threadIdx.x) >> 5;
    if (w >= M_PAD) return;
    const int lane = threadIdx.x & 31;
    float4 a0 = make_float4(0.f, 0.f, 0.f, 0.f);
    float4 a1 = a0;
    if (w < N_NODES) {
        const float4* xs = (const float4*)g_xs;
        const float4* rowd = xs + (size_t)w * 64;
        a0 = __ldg(&rowd[lane]);
        a1 = __ldg(&rowd[lane + 32]);
        int e   = __ldg(&g_rowptr[w]);
        int end = __ldg(&g_rowptr[w + 1]);
        for (; e + 1 < end; e += 2) {
            int s0 = __ldg(&g_esrc[e]);
            int s1 = __ldg(&g_esrc[e + 1]);
            const float4* r0 = xs + (size_t)s0 * 64;
            const float4* r1 = xs + (size_t)s1 * 64;
            float4 v00 = __ldg(&r0[lane]);
            float4 v01 = __ldg(&r0[lane + 32]);
            float4 v10 = __ldg(&r1[lane]);
            float4 v11 = __ldg(&r1[lane + 32]);
            f4add(a0, v00); f4add(a1, v01);
            f4add(a0, v10); f4add(a1, v11);
        }
        if (e < end) {
            int s0 = __ldg(&g_esrc[e]);
            const float4* r0 = xs + (size_t)s0 * 64;
            f4add(a0, __ldg(&r0[lane]));
            f4add(a1, __ldg(&r0[lane + 32]));
        }
        float s = g_dinv[w];
        a0.x *= s; a0.y *= s; a0.z *= s; a0.w *= s;
        a1.x *= s; a1.y *= s; a1.z *= s; a1.w *= s;
    }
    uint2 h, l;
    size_t base = (size_t)w * 64;
    split4(a0, h, l);
    ((uint2*)g_ahi)[base + lane] = h;
    ((uint2*)g_alo)[base + lane] = l;
    split4(a1, h, l);
    ((uint2*)g_ahi)[base + lane + 32] = h;
    ((uint2*)g_alo)[base + lane + 32] = l;
}

// hop-2 gather, D=128: warp per dst row; out = dinv*(gs[d]+sum gs[s]) + b2
__global__ void __launch_bounds__(256) k_gather128(const float* __restrict__ b2,
                                                   float* __restrict__ out) {
    int w = (blockIdx.x * blockDim.x + threadIdx.x) >> 5;
    if (w >= N_NODES) return;
    const int lane = threadIdx.x & 31;
    const float4* gs = (const float4*)g_gs;
    float4 a0 = __ldg(&gs[(size_t)w * 32 + lane]);
    int e   = __ldg(&g_rowptr[w]);
    int end = __ldg(&g_rowptr[w + 1]);
    for (; e + 1 < end; e += 2) {
        int s0 = __ldg(&g_esrc[e]);
        int s1 = __ldg(&g_esrc[e + 1]);
        float4 v0 = __ldg(&gs[(size_t)s0 * 32 + lane]);
        float4 v1 = __ldg(&gs[(size_t)s1 * 32 + lane]);
        f4add(a0, v0); f4add(a0, v1);
    }
    if (e < end) {
        int s0 = __ldg(&g_esrc[e]);
        f4add(a0, __ldg(&gs[(size_t)s0 * 32 + lane]));
    }
    float s = g_dinv[w];
    float4 b = __ldg(&((const float4*)b2)[lane]);
    float4 o;
    o.x = a0.x * s + b.x;
    o.y = a0.y * s + b.y;
    o.z = a0.z * s + b.z;
    o.w = a0.w * s + b.w;
    ((float4*)out)[(size_t)w * 32 + lane] = o;
}

// --------------------------- HMMA GEMM --------------------------------------
// C[128x128] tile of A[M_PAD,256] @ B^T, B stored [n][256] bf16 (hi+lo).
// 3-product bf16 split: Ah*Bh + Al*Bh + Ah*Bl, fp32 accum (mma.sync m16n8k16).
// 8 warps (2x4), warp tile 64x32, BK=32, smem rows padded to 40 elements.
// MODE 1: A = g_ahi/lo, B = W1 split, epi: +b1, relu -> g_h1hi/lo
// MODE 2: A = g_h1hi/lo, B = W2 split, epi: *dinv   -> g_gs (fp32)

__device__ __forceinline__ uint32_t smem_u32(const void* p) {
    return (uint32_t)__cvta_generic_to_shared(p);
}
__device__ __forceinline__ void ldsm_x4(uint32_t& r0, uint32_t& r1,
                                        uint32_t& r2, uint32_t& r3, uint32_t a) {
    asm volatile("ldmatrix.sync.aligned.m8n8.x4.shared.b16 {%0,%1,%2,%3}, [%4];"
                 : "=r"(r0), "=r"(r1), "=r"(r2), "=r"(r3) : "r"(a));
}
__device__ __forceinline__ void mma16816(float* d, const uint32_t* a, const uint32_t* b) {
    asm volatile(
        "mma.sync.aligned.m16n8k16.row.col.f32.bf16.bf16.f32 "
        "{%0,%1,%2,%3}, {%4,%5,%6,%7}, {%8,%9}, {%0,%1,%2,%3};"
        : "+f"(d[0]), "+f"(d[1]), "+f"(d[2]), "+f"(d[3])
        : "r"(a[0]), "r"(a[1]), "r"(a[2]), "r"(a[3]), "r"(b[0]), "r"(b[1]));
}

#define BK   32
#define LDS  40     // padded row stride (elements); 80B, conflict-free ldmatrix

template<int MODE>
__global__ void __launch_bounds__(256)
k_mma(const float* __restrict__ bias) {
    __shared__ __nv_bfloat16 sAh[128][LDS], sAl[128][LDS];
    __shared__ __nv_bfloat16 sBh[128][LDS], sBl[128][LDS];

    const int tid  = threadIdx.x;
    const int lane = tid & 31;
    const int wy   = (tid >> 5) & 1;    // warp m index (0..1)
    const int wx   = (tid >> 5) >> 1;   // warp n index (0..3)
    const size_t rowBase = (size_t)blockIdx.y * 128;
    const int    colBase = blockIdx.x * 128;

    const __nv_bfloat16* Ah = (MODE == 1) ? g_ahi : g_h1hi;
    const __nv_bfloat16* Al = (MODE == 1) ? g_alo : g_h1lo;
    const __nv_bfloat16* Bh = (MODE == 1) ? g_w1h : g_w2h;
    const __nv_bfloat16* Bl = (MODE == 1) ? g_w1l : g_w2l;

    float acc[4][4][4];
#pragma unroll
    for (int i = 0; i < 4; i++)
#pragma unroll
        for (int j = 0; j < 4; j++)
#pragma unroll
            for (int k = 0; k < 4; k++) acc[i][j][k] = 0.f;

    // global->smem fill mapping: row = tid/2, 16-element half = tid%2
    const int fr = tid >> 1;
    const int fh = (tid & 1) * 16;
    const size_t gA = (rowBase + fr) * 256 + fh;
    const size_t gB = ((size_t)colBase + fr) * 256 + fh;

    // ldmatrix lane offsets (bytes)
    const uint32_t aoff = (uint32_t)(((wy * 64 + (lane & 15)) * LDS + (lane >> 4) * 8) * 2);
    const uint32_t boff = (uint32_t)(((wx * 32 + (lane & 7) + ((lane >> 4) << 3)) * LDS
                                      + (((lane >> 3) & 1) * 8)) * 2);
    const uint32_t sAh_b = smem_u32(sAh), sAl_b = smem_u32(sAl);
    const uint32_t sBh_b = smem_u32(sBh), sBl_b = smem_u32(sBl);

#pragma unroll 1
    for (int kc = 0; kc < 8; kc++) {
        const int k0 = kc * BK;
        __syncthreads();
        *(uint4*)&sAh[fr][fh]     = *(const uint4*)(Ah + gA + k0);
        *(uint4*)&sAh[fr][fh + 8] = *(const uint4*)(Ah + gA + k0 + 8);
        *(uint4*)&sAl[fr][fh]     = *(const uint4*)(Al + gA + k0);
        *(uint4*)&sAl[fr][fh + 8] = *(const uint4*)(Al + gA + k0 + 8);
        *(uint4*)&sBh[fr][fh]     = *(const uint4*)(Bh + gB + k0);
        *(uint4*)&sBh[fr][fh + 8] = *(const uint4*)(Bh + gB + k0 + 8);
        *(uint4*)&sBl[fr][fh]     = *(const uint4*)(Bl + gB + k0);
        *(uint4*)&sBl[fr][fh + 8] = *(const uint4*)(Bl + gB + k0 + 8);
        __syncthreads();

#pragma unroll
        for (int ks = 0; ks < 2; ks++) {
            const uint32_t kb = ks * 32;   // 16 cols * 2B
            uint32_t ah[4][4], al[4][4], bh[2][4], bl[2][4];
#pragma unroll
            for (int mi = 0; mi < 4; mi++) {
                uint32_t off = aoff + mi * (16 * LDS * 2) + kb;
                ldsm_x4(ah[mi][0], ah[mi][1], ah[mi][2], ah[mi][3], sAh_b + off);
                ldsm_x4(al[mi][0], al[mi][1], al[mi][2], al[mi][3], sAl_b + off);
            }
#pragma unroll
            for (int p = 0; p < 2; p++) {
                uint32_t off = boff + p * (16 * LDS * 2) + kb;
                ldsm_x4(bh[p][0], bh[p][1], bh[p][2], bh[p][3], sBh_b + off);
                ldsm_x4(bl[p][0], bl[p][1], bl[p][2], bl[p][3], sBl_b + off);
            }
#pragma unroll
            for (int mi = 0; mi < 4; mi++)
#pragma unroll
                for (int ni = 0; ni < 4; ni++) {
                    const int p = ni >> 1, q = (ni & 1) * 2;
                    uint32_t b0[2] = { bh[p][q], bh[p][q + 1] };
                    uint32_t b1[2] = { bl[p][q], bl[p][q + 1] };
                    mma16816(acc[mi][ni], ah[mi], b0);
                    mma16816(acc[mi][ni], al[mi], b0);
                    mma16816(acc[mi][ni], ah[mi], b1);
                }
        }
    }

    // epilogue
    const int gid = lane >> 2, tig = lane & 3;
#pragma unroll
    for (int mi = 0; mi < 4; mi++) {
        const int row = (int)rowBase + wy * 64 + mi * 16 + gid;
#pragma unroll
        for (int ni = 0; ni < 4; ni++) {
            const int col = colBase + wx * 32 + ni * 8 + tig * 2;
            float d0 = acc[mi][ni][0], d1 = acc[mi][ni][1];
            float d2 = acc[mi][ni][2], d3 = acc[mi][ni][3];
            if (MODE == 1) {
                float b0 = __ldg(&bias[col]), b1 = __ldg(&bias[col + 1]);
                float v0 = fmaxf(d0 + b0, 0.f), v1 = fmaxf(d1 + b1, 0.f);
                float v2 = fmaxf(d2 + b0, 0.f), v3 = fmaxf(d3 + b1, 0.f);
                uint32_t hi, lo;
                split2(v0, v1, hi, lo);
                *(uint32_t*)(g_h1hi + (size_t)row * 256 + col) = hi;
                *(uint32_t*)(g_h1lo + (size_t)row * 256 + col) = lo;
                split2(v2, v3, hi, lo);
                *(uint32_t*)(g_h1hi + (size_t)(row + 8) * 256 + col) = hi;
                *(uint32_t*)(g_h1lo + (size_t)(row + 8) * 256 + col) = lo;
            } else {
                float s0 = g_dinv[row], s1 = g_dinv[row + 8];
                *(float2*)(g_gs + (size_t)row * 128 + col)       = make_float2(d0 * s0, d1 * s0);
                *(float2*)(g_gs + (size_t)(row + 8) * 128 + col) = make_float2(d2 * s1, d3 * s1);
            }
        }
    }
}

// ---------------------------------------------------------------------------

extern "C" void kernel_launch(void* const* d_in, const int* in_sizes, int n_in,
                              void* d_out, int out_size) {
    const float* x  = (const float*)d_in[0];
    const int*   ei = (const int*)  d_in[1];
    const float* W1 = (const float*)d_in[2];
    const float* b1 = (const float*)d_in[3];
    const float* W2 = (const float*)d_in[4];
    const float* b2 = (const float*)d_in[5];
    float* out = (float*)d_out;

    const int E = in_sizes[1] / 2;
    const int* src = ei;
    const int* dst = ei + E;
    const int nb = (M_PAD + 1023) / 1024;   // 49

    // CSR build + norms (+ weight split, independent)
    k_zero_deg<<<(M_PAD + 255) / 256, 256>>>();
    k_deg<<<(E + 255) / 256, 256>>>(dst, E);
    k_wsplit<<<(D0 * D0 + D2 * D0 + 255) / 256, 256>>>(W1, W2);
    k_dinv<<<(M_PAD + 255) / 256, 256>>>();
    k_scan1<<<nb, 1024>>>();
    k_scan2<<<1, 32>>>(nb);
    k_scan3<<<nb, 1024>>>(E);
    k_fill<<<(E + 255) / 256, 256>>>(src, dst, E);

    // hop 1
    k_scale<<<(M_PAD * (D0 / 4) + 255) / 256, 256>>>(x);
    k_gather256<<<(M_PAD * 32 + 255) / 256, 256>>>();

    // H1 = relu(prop(x) @ W1 + b1)  (bf16-split HMMA GEMM)
    k_mma<1><<<dim3(2, NTILE_M), 256>>>(b1);

    // gs = (H1 @ W2) * dinv ; hop 2 + bias -> out
    k_mma<2><<<dim3(1, NTILE_M), 256>>>(nullptr);
    k_gather128<<<(N_NODES * 32 + 255) / 256, 256>>>(b2, out);
}

// round 5
// speedup vs baseline: 2.8433x; 1.1622x over previous
#include <cuda_runtime.h>
#include <cuda_bf16.h>
#include <cstdint>

// ---------------------------------------------------------------------------
// SGCEncoder: out = prop(relu(prop(x) @ W1 + b1)) @ W2 + b2
//   prop = D^-1/2 (A+I) D^-1/2
// Rewrites:
//   prop(x)[d] = dinv[d] * ( sum_{s->d} xs[s] + xs[d] ),  xs = x*dinv
//   prop(H1) @ W2 = prop(H1 @ W2)          (propagate at D=128)
// Round 5: cp.async double-buffered HMMA GEMMs, fused setup, MLP-8 gather.
// ---------------------------------------------------------------------------

#define N_NODES 50000
#define M_PAD   50048          // 391 * 128
#define D0      256
#define D2      128
#define E_MAX   1600000
#define NTILE_M 391

__device__ int   g_deg   [M_PAD];      // zero at entry; restored by k_scan1
__device__ int   g_rowptr[M_PAD + 1];
__device__ int   g_cursor[M_PAD];
__device__ int   g_esrc  [E_MAX];
__device__ int   g_bsum  [64];
__device__ int   g_boff  [64];
__device__ float g_dinv  [M_PAD];
__device__ float g_xs    [M_PAD * D0];       // x * dinv (hop-1 gather source)
__device__ float g_gs    [M_PAD * D2];       // (H1 @ W2) * dinv (hop-2 source)
__device__ __nv_bfloat16 g_ahi [M_PAD * D0]; // hop-1 result, bf16 hi
__device__ __nv_bfloat16 g_alo [M_PAD * D0]; // hop-1 result, bf16 lo
__device__ __nv_bfloat16 g_h1hi[M_PAD * D0];
__device__ __nv_bfloat16 g_h1lo[M_PAD * D0];
__device__ __nv_bfloat16 g_w1h [D0 * D0];    // W1^T [n][k] bf16 hi
__device__ __nv_bfloat16 g_w1l [D0 * D0];
__device__ __nv_bfloat16 g_w2h [D2 * D0];    // W2^T [n][k]
__device__ __nv_bfloat16 g_w2l [D2 * D0];

// --------------------------- CSR build --------------------------------------

__global__ void k_deg(const int* __restrict__ dst, int E) {
    int i = blockIdx.x * blockDim.x + threadIdx.x;
    if (i < E) atomicAdd(&g_deg[dst[i]], 1);
}

// fused: read deg, zero deg (restore invariant), compute dinv, block scan
__global__ void __launch_bounds__(1024) k_scan1() {
    __shared__ int warp_red[32];
    const int tid = threadIdx.x, lane = tid & 31, wid = tid >> 5;
    int idx = blockIdx.x * 1024 + tid;
    int v = 0;
    if (idx < M_PAD) {
        v = g_deg[idx];
        g_deg[idx] = 0;
        g_dinv[idx] = (idx < N_NODES) ? rsqrtf((float)(v + 1)) : 0.0f;
    }
    int inc = v;
#pragma unroll
    for (int off = 1; off < 32; off <<= 1) {
        int t = __shfl_up_sync(0xffffffff, inc, off);
        if (lane >= off) inc += t;
    }
    if (lane == 31) warp_red[wid] = inc;
    __syncthreads();
    if (wid == 0) {
        int w = warp_red[lane];
#pragma unroll
        for (int off = 1; off < 32; off <<= 1) {
            int t = __shfl_up_sync(0xffffffff, w, off);
            if (lane >= off) w += t;
        }
        warp_red[lane] = w;
    }
    __syncthreads();
    int excl = ((wid > 0) ? warp_red[wid - 1] : 0) + (inc - v);
    if (idx < M_PAD) g_rowptr[idx] = excl;
    if (tid == 1023) g_bsum[blockIdx.x] = warp_red[31];
}
__global__ void k_scan2(int nb) {
    if (threadIdx.x == 0) {
        int run = 0;
        for (int b = 0; b < nb; b++) { g_boff[b] = run; run += g_bsum[b]; }
    }
}
__global__ void __launch_bounds__(1024) k_scan3(int E) {
    int idx = blockIdx.x * 1024 + threadIdx.x;
    if (idx < M_PAD) {
        int v = g_rowptr[idx] + g_boff[idx >> 10];
        g_rowptr[idx] = v;
        g_cursor[idx] = v;
    } else if (idx == M_PAD) {
        g_rowptr[M_PAD] = E;
    }
}
__global__ void k_fill(const int* __restrict__ src, const int* __restrict__ dst, int E) {
    int i = blockIdx.x * blockDim.x + threadIdx.x;
    if (i >= E) return;
    int pos = atomicAdd(&g_cursor[dst[i]], 1);
    g_esrc[pos] = src[i];
}

// --------------------------- pre/post scale ---------------------------------

__global__ void k_scale(const float* __restrict__ x) {
    int i = blockIdx.x * blockDim.x + threadIdx.x;      // float4 index
    if (i >= M_PAD * (D0 / 4)) return;
    int row = i >> 6;
    float4 v = make_float4(0.f, 0.f, 0.f, 0.f);
    if (row < N_NODES) {
        v = ((const float4*)x)[i];
        float s = g_dinv[row];
        v.x *= s; v.y *= s; v.z *= s; v.w *= s;
    }
    ((float4*)g_xs)[i] = v;
}

// W split + transpose: B[n][k] = W[k][n], bf16 hi/lo
__global__ void k_wsplit(const float* __restrict__ W1, const float* __restrict__ W2) {
    int i = blockIdx.x * blockDim.x + threadIdx.x;
    if (i < D0 * D0) {
        int n = i >> 8, k = i & 255;
        float v = W1[k * D0 + n];
        __nv_bfloat16 h = __float2bfloat16(v);
        g_w1h[n * D0 + k] = h;
        g_w1l[n * D0 + k] = __float2bfloat16(v - __bfloat162float(h));
    } else if (i < D0 * D0 + D2 * D0) {
        int j = i - D0 * D0;
        int n = j >> 8, k = j & 255;
        float v = W2[k * D2 + n];
        __nv_bfloat16 h = __float2bfloat16(v);
        g_w2h[n * D0 + k] = h;
        g_w2l[n * D0 + k] = __float2bfloat16(v - __bfloat162float(h));
    }
}

__device__ __forceinline__ void f4add(float4& a, float4 b) {
    a.x += b.x; a.y += b.y; a.z += b.z; a.w += b.w;
}
__device__ __forceinline__ uint32_t pack2(__nv_bfloat16 a, __nv_bfloat16 b) {
    __nv_bfloat162 t = __nv_bfloat162(a, b);
    return *reinterpret_cast<uint32_t*>(&t);
}
__device__ __forceinline__ void split2(float v0, float v1, uint32_t& hi, uint32_t& lo) {
    __nv_bfloat16 h0 = __float2bfloat16(v0), h1 = __float2bfloat16(v1);
    hi = pack2(h0, h1);
    lo = pack2(__float2bfloat16(v0 - __bfloat162float(h0)),
               __float2bfloat16(v1 - __bfloat162float(h1)));
}
__device__ __forceinline__ void split4(float4 v, uint2& hi, uint2& lo) {
    split2(v.x, v.y, hi.x, lo.x);
    split2(v.z, v.w, hi.y, lo.y);
}

// --------------------------- gathers ----------------------------------------

// hop-1 gather, D=256: warp per dst row; writes bf16 hi/lo of dinv*(self+sum)
__global__ void __launch_bounds__(256) k_gather256() {
    int w = (blockIdx.x * blockDim.x + threadIdx.x) >> 5;
    if (w >= M_PAD) return;
    const int lane = threadIdx.x & 31;
    float4 a0 = make_float4(0.f, 0.f, 0.f, 0.f);
    float4 a1 = a0;
    if (w < N_NODES) {
        const float4* xs = (const float4*)g_xs;
        const float4* rowd = xs + (size_t)w * 64;
        a0 = __ldg(&rowd[lane]);
        a1 = __ldg(&rowd[lane + 32]);
        int e   = __ldg(&g_rowptr[w]);
        int end = __ldg(&g_rowptr[w + 1]);
        for (; e + 3 < end; e += 4) {
            int s0 = __ldg(&g_esrc[e]);
            int s1 = __ldg(&g_esrc[e + 1]);
            int s2 = __ldg(&g_esrc[e + 2]);
            int s3 = __ldg(&g_esrc[e + 3]);
            const float4* r0 = xs + (size_t)s0 * 64;
            const float4* r1 = xs + (size_t)s1 * 64;
            const float4* r2 = xs + (size_t)s2 * 64;
            const float4* r3 = xs + (size_t)s3 * 64;
            float4 v00 = __ldg(&r0[lane]),      v01 = __ldg(&r0[lane + 32]);
            float4 v10 = __ldg(&r1[lane]),      v11 = __ldg(&r1[lane + 32]);
            float4 v20 = __ldg(&r2[lane]),      v21 = __ldg(&r2[lane + 32]);
            float4 v30 = __ldg(&r3[lane]),      v31 = __ldg(&r3[lane + 32]);
            f4add(a0, v00); f4add(a1, v01);
            f4add(a0, v10); f4add(a1, v11);
            f4add(a0, v20); f4add(a1, v21);
            f4add(a0, v30); f4add(a1, v31);
        }
        for (; e < end; e++) {
            int s0 = __ldg(&g_esrc[e]);
            const float4* r0 = xs + (size_t)s0 * 64;
            f4add(a0, __ldg(&r0[lane]));
            f4add(a1, __ldg(&r0[lane + 32]));
        }
        float s = g_dinv[w];
        a0.x *= s; a0.y *= s; a0.z *= s; a0.w *= s;
        a1.x *= s; a1.y *= s; a1.z *= s; a1.w *= s;
    }
    uint2 h, l;
    size_t base = (size_t)w * 64;
    split4(a0, h, l);
    ((uint2*)g_ahi)[base + lane] = h;
    ((uint2*)g_alo)[base + lane] = l;
    split4(a1, h, l);
    ((uint2*)g_ahi)[base + lane + 32] = h;
    ((uint2*)g_alo)[base + lane + 32] = l;
}

// hop-2 gather, D=128: warp per dst row; out = dinv*(gs[d]+sum gs[s]) + b2
__global__ void __launch_bounds__(256) k_gather128(const float* __restrict__ b2,
                                                   float* __restrict__ out) {
    int w = (blockIdx.x * blockDim.x + threadIdx.x) >> 5;
    if (w >= N_NODES) return;
    const int lane = threadIdx.x & 31;
    const float4* gs = (const float4*)g_gs;
    float4 a0 = __ldg(&gs[(size_t)w * 32 + lane]);
    int e   = __ldg(&g_rowptr[w]);
    int end = __ldg(&g_rowptr[w + 1]);
    for (; e + 3 < end; e += 4) {
        int s0 = __ldg(&g_esrc[e]);
        int s1 = __ldg(&g_esrc[e + 1]);
        int s2 = __ldg(&g_esrc[e + 2]);
        int s3 = __ldg(&g_esrc[e + 3]);
        float4 v0 = __ldg(&gs[(size_t)s0 * 32 + lane]);
        float4 v1 = __ldg(&gs[(size_t)s1 * 32 + lane]);
        float4 v2 = __ldg(&gs[(size_t)s2 * 32 + lane]);
        float4 v3 = __ldg(&gs[(size_t)s3 * 32 + lane]);
        f4add(a0, v0); f4add(a0, v1); f4add(a0, v2); f4add(a0, v3);
    }
    for (; e < end; e++) {
        int s0 = __ldg(&g_esrc[e]);
        f4add(a0, __ldg(&gs[(size_t)s0 * 32 + lane]));
    }
    float s = g_dinv[w];
    float4 b = __ldg(&((const float4*)b2)[lane]);
    float4 o;
    o.x = a0.x * s + b.x;
    o.y = a0.y * s + b.y;
    o.z = a0.z * s + b.z;
    o.w = a0.w * s + b.w;
    ((float4*)out)[(size_t)w * 32 + lane] = o;
}

// --------------------------- HMMA GEMM (cp.async pipelined) -----------------
// C[128x128] tile of A[M_PAD,256] @ B^T, B stored [n][256] bf16 (hi+lo).
// 3-product bf16 split: Ah*Bh + Al*Bh + Ah*Bl, fp32 accum (mma.sync m16n8k16).
// 8 warps (2x4), warp tile 64x32, BK=32, double-buffered dynamic smem.

__device__ __forceinline__ uint32_t smem_u32(const void* p) {
    return (uint32_t)__cvta_generic_to_shared(p);
}
__device__ __forceinline__ void cp16(uint32_t s, const void* g) {
    asm volatile("cp.async.cg.shared.global [%0], [%1], 16;" :: "r"(s), "l"(g));
}
#define CP_COMMIT() asm volatile("cp.async.commit_group;" ::: "memory")
#define CP_WAIT(n)  asm volatile("cp.async.wait_group %0;" :: "n"(n) : "memory")

__device__ __forceinline__ void ldsm_x4(uint32_t& r0, uint32_t& r1,
                                        uint32_t& r2, uint32_t& r3, uint32_t a) {
    asm volatile("ldmatrix.sync.aligned.m8n8.x4.shared.b16 {%0,%1,%2,%3}, [%4];"
                 : "=r"(r0), "=r"(r1), "=r"(r2), "=r"(r3) : "r"(a));
}
__device__ __forceinline__ void mma16816(float* d, const uint32_t* a, const uint32_t* b) {
    asm volatile(
        "mma.sync.aligned.m16n8k16.row.col.f32.bf16.bf16.f32 "
        "{%0,%1,%2,%3}, {%4,%5,%6,%7}, {%8,%9}, {%0,%1,%2,%3};"
        : "+f"(d[0]), "+f"(d[1]), "+f"(d[2]), "+f"(d[3])
        : "r"(a[0]), "r"(a[1]), "r"(a[2]), "r"(a[3]), "r"(b[0]), "r"(b[1]));
}

#define BK      32
#define LDS     40                     // padded row stride (elements)
#define BUFB    (128 * LDS * 2)        // 10240 bytes per tile buffer
#define SM_MMA  (8 * BUFB)             // 81920 bytes total (2 stages x 4 bufs)

template<int MODE>
__global__ void __launch_bounds__(256)
k_mma(const float* __restrict__ bias) {
    extern __shared__ char dynsmem[];
    const uint32_t sb = smem_u32(dynsmem);

    const int tid  = threadIdx.x;
    const int lane = tid & 31;
    const int wy   = (tid >> 5) & 1;    // warp m index (0..1)
    const int wx   = (tid >> 5) >> 1;   // warp n index (0..3)
    const size_t rowBase = (size_t)blockIdx.y * 128;
    const int    colBase = blockIdx.x * 128;

    const __nv_bfloat16* Ah = (MODE == 1) ? g_ahi : g_h1hi;
    const __nv_bfloat16* Al = (MODE == 1) ? g_alo : g_h1lo;
    const __nv_bfloat16* Bh = (MODE == 1) ? g_w1h : g_w2h;
    const __nv_bfloat16* Bl = (MODE == 1) ? g_w1l : g_w2l;

    float acc[4][4][4];
#pragma unroll
    for (int i = 0; i < 4; i++)
#pragma unroll
        for (int j = 0; j < 4; j++)
#pragma unroll
            for (int k = 0; k < 4; k++) acc[i][j][k] = 0.f;

    // fill mapping: row = tid/2, 16-element half = tid%2
    const int fr = tid >> 1;
    const int fh = (tid & 1) * 16;
    const size_t gA = (rowBase + fr) * 256 + fh;
    const size_t gB = ((size_t)colBase + fr) * 256 + fh;
    const uint32_t dOff = (uint32_t)((fr * LDS + fh) * 2);

    // ldmatrix lane offsets (bytes, relative to buffer base)
    const uint32_t aoff = (uint32_t)(((wy * 64 + (lane & 15)) * LDS + (lane >> 4) * 8) * 2);
    const uint32_t boff = (uint32_t)(((wx * 32 + (lane & 7) + ((lane >> 4) << 3)) * LDS
                                      + (((lane >> 3) & 1) * 8)) * 2);

    // issue cp.async for k-chunk kc into stage st
    auto issue = [&](int kc, int st) {
        const int k0 = kc * BK;
        uint32_t b = sb + (uint32_t)st * (4 * BUFB);
        cp16(b + dOff,            Ah + gA + k0);
        cp16(b + dOff + 16,       Ah + gA + k0 + 8);
        b += BUFB;
        cp16(b + dOff,            Al + gA + k0);
        cp16(b + dOff + 16,       Al + gA + k0 + 8);
        b += BUFB;
        cp16(b + dOff,            Bh + gB + k0);
        cp16(b + dOff + 16,       Bh + gB + k0 + 8);
        b += BUFB;
        cp16(b + dOff,            Bl + gB + k0);
        cp16(b + dOff + 16,       Bl + gB + k0 + 8);
    };

    issue(0, 0);
    CP_COMMIT();

#pragma unroll 1
    for (int kc = 0; kc < 8; kc++) {
        const int cur = kc & 1;
        if (kc < 7) {
            issue(kc + 1, cur ^ 1);
            CP_COMMIT();
            CP_WAIT(1);
        } else {
            CP_WAIT(0);
        }
        __syncthreads();

        const uint32_t sAh_b = sb + (uint32_t)cur * (4 * BUFB);
        const uint32_t sAl_b = sAh_b + BUFB;
        const uint32_t sBh_b = sAl_b + BUFB;
        const uint32_t sBl_b = sBh_b + BUFB;

#pragma unroll
        for (int ks = 0; ks < 2; ks++) {
            const uint32_t kb = ks * 32;   // 16 cols * 2B
            uint32_t ah[4][4], al[4][4], bh[2][4], bl[2][4];
#pragma unroll
            for (int mi = 0; mi < 4; mi++) {
                uint32_t off = aoff + mi * (16 * LDS * 2) + kb;
                ldsm_x4(ah[mi][0], ah[mi][1], ah[mi][2], ah[mi][3], sAh_b + off);
                ldsm_x4(al[mi][0], al[mi][1], al[mi][2], al[mi][3], sAl_b + off);
            }
#pragma unroll
            for (int p = 0; p < 2; p++) {
                uint32_t off = boff + p * (16 * LDS * 2) + kb;
                ldsm_x4(bh[p][0], bh[p][1], bh[p][2], bh[p][3], sBh_b + off);
                ldsm_x4(bl[p][0], bl[p][1], bl[p][2], bl[p][3], sBl_b + off);
            }
#pragma unroll
            for (int mi = 0; mi < 4; mi++)
#pragma unroll
                for (int ni = 0; ni < 4; ni++) {
                    const int p = ni >> 1, q = (ni & 1) * 2;
                    uint32_t b0[2] = { bh[p][q], bh[p][q + 1] };
                    uint32_t b1[2] = { bl[p][q], bl[p][q + 1] };
                    mma16816(acc[mi][ni], ah[mi], b0);
                    mma16816(acc[mi][ni], al[mi], b0);
                    mma16816(acc[mi][ni], ah[mi], b1);
                }
        }
        __syncthreads();
    }

    // epilogue
    const int gid = lane >> 2, tig = lane & 3;
#pragma unroll
    for (int mi = 0; mi < 4; mi++) {
        const int row = (int)rowBase + wy * 64 + mi * 16 + gid;
#pragma unroll
        for (int ni = 0; ni < 4; ni++) {
            const int col = colBase + wx * 32 + ni * 8 + tig * 2;
            float d0 = acc[mi][ni][0], d1 = acc[mi][ni][1];
            float d2 = acc[mi][ni][2], d3 = acc[mi][ni][3];
            if (MODE == 1) {
                float b0 = __ldg(&bias[col]), b1 = __ldg(&bias[col + 1]);
                float v0 = fmaxf(d0 + b0, 0.f), v1 = fmaxf(d1 + b1, 0.f);
                float v2 = fmaxf(d2 + b0, 0.f), v3 = fmaxf(d3 + b1, 0.f);
                uint32_t hi, lo;
                split2(v0, v1, hi, lo);
                *(uint32_t*)(g_h1hi + (size_t)row * 256 + col) = hi;
                *(uint32_t*)(g_h1lo + (size_t)row * 256 + col) = lo;
                split2(v2, v3, hi, lo);
                *(uint32_t*)(g_h1hi + (size_t)(row + 8) * 256 + col) = hi;
                *(uint32_t*)(g_h1lo + (size_t)(row + 8) * 256 + col) = lo;
            } else {
                float s0 = g_dinv[row], s1 = g_dinv[row + 8];
                *(float2*)(g_gs + (size_t)row * 128 + col)       = make_float2(d0 * s0, d1 * s0);
                *(float2*)(g_gs + (size_t)(row + 8) * 128 + col) = make_float2(d2 * s1, d3 * s1);
            }
        }
    }
}

// ---------------------------------------------------------------------------

extern "C" void kernel_launch(void* const* d_in, const int* in_sizes, int n_in,
                              void* d_out, int out_size) {
    const float* x  = (const float*)d_in[0];
    const int*   ei = (const int*)  d_in[1];
    const float* W1 = (const float*)d_in[2];
    const float* b1 = (const float*)d_in[3];
    const float* W2 = (const float*)d_in[4];
    const float* b2 = (const float*)d_in[5];
    float* out = (float*)d_out;

    const int E = in_sizes[1] / 2;
    const int* src = ei;
    const int* dst = ei + E;
    const int nb = (M_PAD + 1023) / 1024;   // 49

    cudaFuncSetAttribute(k_mma<1>, cudaFuncAttributeMaxDynamicSharedMemorySize, SM_MMA);
    cudaFuncSetAttribute(k_mma<2>, cudaFuncAttributeMaxDynamicSharedMemorySize, SM_MMA);

    // CSR build + norms (+ weight split, independent)
    k_deg<<<(E + 255) / 256, 256>>>(dst, E);
    k_wsplit<<<(D0 * D0 + D2 * D0 + 255) / 256, 256>>>(W1, W2);
    k_scan1<<<nb, 1024>>>();
    k_scan2<<<1, 32>>>(nb);
    k_scan3<<<nb, 1024>>>(E);
    k_fill<<<(E + 255) / 256, 256>>>(src, dst, E);

    // hop 1
    k_scale<<<(M_PAD * (D0 / 4) + 255) / 256, 256>>>(x);
    k_gather256<<<(M_PAD * 32 + 255) / 256, 256>>>();

    // H1 = relu(prop(x) @ W1 + b1)
    k_mma<1><<<dim3(2, NTILE_M), 256, SM_MMA>>>(b1);

    // gs = (H1 @ W2) * dinv ; hop 2 + bias -> out
    k_mma<2><<<dim3(1, NTILE_M), 256, SM_MMA>>>(nullptr);
    k_gather128<<<(N_NODES * 32 + 255) / 256, 256>>>(b2, out);
}

// round 6
// speedup vs baseline: 2.9588x; 1.0406x over previous
#include <cuda_runtime.h>
#include <cuda_bf16.h>
#include <cstdint>

// ---------------------------------------------------------------------------
// SGCEncoder: out = prop(relu(prop(x) @ W1 + b1)) @ W2 + b2
//   prop = D^-1/2 (A+I) D^-1/2
// Rewrites:
//   prop(x)[d] = dinv[d] * ( sum_{s->d} x[s]*dinv[s] + x[d]*dinv[d] )
//   prop(H1) @ W2 = prop(H1 @ W2)          (propagate at D=128)
// Round 6: no xs materialization (dinv folded into gather), scan2 folded into
// scan3, deg+wsplit merged. Gathers sit at the LTS roofline.
// ---------------------------------------------------------------------------

#define N_NODES 50000
#define M_PAD   50048          // 391 * 128
#define D0      256
#define D2      128
#define E_MAX   1600000
#define NTILE_M 391

__device__ int   g_deg   [M_PAD];      // zero at entry; restored by k_scan1
__device__ int   g_rowptr[M_PAD + 1];
__device__ int   g_cursor[M_PAD];
__device__ int   g_esrc  [E_MAX];
__device__ int   g_bsum  [64];
__device__ float g_dinv  [M_PAD];
__device__ float g_gs    [M_PAD * D2];       // (H1 @ W2) * dinv (hop-2 source)
__device__ __nv_bfloat16 g_ahi [M_PAD * D0]; // hop-1 result, bf16 hi
__device__ __nv_bfloat16 g_alo [M_PAD * D0]; // hop-1 result, bf16 lo
__device__ __nv_bfloat16 g_h1hi[M_PAD * D0];
__device__ __nv_bfloat16 g_h1lo[M_PAD * D0];
__device__ __nv_bfloat16 g_w1h [D0 * D0];    // W1^T [n][k] bf16 hi
__device__ __nv_bfloat16 g_w1l [D0 * D0];
__device__ __nv_bfloat16 g_w2h [D2 * D0];    // W2^T [n][k]
__device__ __nv_bfloat16 g_w2l [D2 * D0];

// --------------------------- setup: deg histogram + weight split ------------

__global__ void k_deg_wsplit(const int* __restrict__ dst, int E,
                             const float* __restrict__ W1,
                             const float* __restrict__ W2, int nDegBlocks) {
    if ((int)blockIdx.x < nDegBlocks) {
        int i = blockIdx.x * 256 + threadIdx.x;
        if (i < E) atomicAdd(&g_deg[dst[i]], 1);
    } else {
        int i = (blockIdx.x - nDegBlocks) * 256 + threadIdx.x;
        if (i < D0 * D0) {
            int n = i >> 8, k = i & 255;
            float v = W1[k * D0 + n];
            __nv_bfloat16 h = __float2bfloat16(v);
            g_w1h[n * D0 + k] = h;
            g_w1l[n * D0 + k] = __float2bfloat16(v - __bfloat162float(h));
        } else if (i < D0 * D0 + D2 * D0) {
            int j = i - D0 * D0;
            int n = j >> 8, k = j & 255;
            float v = W2[k * D2 + n];
            __nv_bfloat16 h = __float2bfloat16(v);
            g_w2h[n * D0 + k] = h;
            g_w2l[n * D0 + k] = __float2bfloat16(v - __bfloat162float(h));
        }
    }
}

// fused: read deg, zero deg (restore invariant), compute dinv, block scan
__global__ void __launch_bounds__(1024) k_scan1() {
    __shared__ int warp_red[32];
    const int tid = threadIdx.x, lane = tid & 31, wid = tid >> 5;
    int idx = blockIdx.x * 1024 + tid;
    int v = 0;
    if (idx < M_PAD) {
        v = g_deg[idx];
        g_deg[idx] = 0;
        g_dinv[idx] = (idx < N_NODES) ? rsqrtf((float)(v + 1)) : 0.0f;
    }
    int inc = v;
#pragma unroll
    for (int off = 1; off < 32; off <<= 1) {
        int t = __shfl_up_sync(0xffffffff, inc, off);
        if (lane >= off) inc += t;
    }
    if (lane == 31) warp_red[wid] = inc;
    __syncthreads();
    if (wid == 0) {
        int w = warp_red[lane];
#pragma unroll
        for (int off = 1; off < 32; off <<= 1) {
            int t = __shfl_up_sync(0xffffffff, w, off);
            if (lane >= off) w += t;
        }
        warp_red[lane] = w;
    }
    __syncthreads();
    int excl = ((wid > 0) ? warp_red[wid - 1] : 0) + (inc - v);
    if (idx < M_PAD) g_rowptr[idx] = excl;
    if (tid == 1023) g_bsum[blockIdx.x] = warp_red[31];
}

// apply block offsets (computes own prefix of g_bsum; max 64 blocks)
__global__ void __launch_bounds__(1024) k_scan3(int E) {
    __shared__ int s_off;
    if (threadIdx.x < 32) {
        int b = blockIdx.x;
        int v = 0;
        if ((int)threadIdx.x < b) v = g_bsum[threadIdx.x];
        if ((int)threadIdx.x + 32 < b) v += g_bsum[threadIdx.x + 32];
#pragma unroll
        for (int off = 16; off > 0; off >>= 1)
            v += __shfl_down_sync(0xffffffff, v, off);
        if (threadIdx.x == 0) s_off = v;
    }
    __syncthreads();
    int idx = blockIdx.x * 1024 + threadIdx.x;
    if (idx < M_PAD) {
        int v = g_rowptr[idx] + s_off;
        g_rowptr[idx] = v;
        g_cursor[idx] = v;
    } else if (idx == M_PAD) {
        g_rowptr[M_PAD] = E;
    }
}

__global__ void k_fill(const int* __restrict__ src, const int* __restrict__ dst, int E) {
    int i = blockIdx.x * blockDim.x + threadIdx.x;
    if (i >= E) return;
    int pos = atomicAdd(&g_cursor[dst[i]], 1);
    g_esrc[pos] = src[i];
}

// --------------------------- bf16 split helpers ------------------------------

__device__ __forceinline__ void f4fma(float4& a, float4 b, float s) {
    a.x += b.x * s; a.y += b.y * s; a.z += b.z * s; a.w += b.w * s;
}
__device__ __forceinline__ uint32_t pack2(__nv_bfloat16 a, __nv_bfloat16 b) {
    __nv_bfloat162 t = __nv_bfloat162(a, b);
    return *reinterpret_cast<uint32_t*>(&t);
}
__device__ __forceinline__ void split2(float v0, float v1, uint32_t& hi, uint32_t& lo) {
    __nv_bfloat16 h0 = __float2bfloat16(v0), h1 = __float2bfloat16(v1);
    hi = pack2(h0, h1);
    lo = pack2(__float2bfloat16(v0 - __bfloat162float(h0)),
               __float2bfloat16(v1 - __bfloat162float(h1)));
}
__device__ __forceinline__ void split4(float4 v, uint2& hi, uint2& lo) {
    split2(v.x, v.y, hi.x, lo.x);
    split2(v.z, v.w, hi.y, lo.y);
}

// --------------------------- gathers ----------------------------------------

// hop-1 gather, D=256: warp per dst row, reads raw x with inline dinv scaling;
// writes bf16 hi/lo of dinv[d]*(x[d]*dinv[d] + sum x[s]*dinv[s])
__global__ void __launch_bounds__(256) k_gather256(const float* __restrict__ x) {
    int w = (blockIdx.x * blockDim.x + threadIdx.x) >> 5;
    if (w >= M_PAD) return;
    const int lane = threadIdx.x & 31;
    float4 a0 = make_float4(0.f, 0.f, 0.f, 0.f);
    float4 a1 = a0;
    float sd = 0.f;
    if (w < N_NODES) {
        sd = g_dinv[w];
        const float4* xp = (const float4*)x;
        const float4* rowd = xp + (size_t)w * 64;
        float4 v0 = __ldg(&rowd[lane]);
        float4 v1 = __ldg(&rowd[lane + 32]);
        f4fma(a0, v0, sd);
        f4fma(a1, v1, sd);
        int e   = __ldg(&g_rowptr[w]);
        int end = __ldg(&g_rowptr[w + 1]);
        for (; e + 3 < end; e += 4) {
            int s0 = __ldg(&g_esrc[e]);
            int s1 = __ldg(&g_esrc[e + 1]);
            int s2 = __ldg(&g_esrc[e + 2]);
            int s3 = __ldg(&g_esrc[e + 3]);
            float d0 = __ldg(&g_dinv[s0]);
            float d1 = __ldg(&g_dinv[s1]);
            float d2 = __ldg(&g_dinv[s2]);
            float d3 = __ldg(&g_dinv[s3]);
            const float4* r0 = xp + (size_t)s0 * 64;
            const float4* r1 = xp + (size_t)s1 * 64;
            const float4* r2 = xp + (size_t)s2 * 64;
            const float4* r3 = xp + (size_t)s3 * 64;
            float4 v00 = __ldg(&r0[lane]),      v01 = __ldg(&r0[lane + 32]);
            float4 v10 = __ldg(&r1[lane]),      v11 = __ldg(&r1[lane + 32]);
            float4 v20 = __ldg(&r2[lane]),      v21 = __ldg(&r2[lane + 32]);
            float4 v30 = __ldg(&r3[lane]),      v31 = __ldg(&r3[lane + 32]);
            f4fma(a0, v00, d0); f4fma(a1, v01, d0);
            f4fma(a0, v10, d1); f4fma(a1, v11, d1);
            f4fma(a0, v20, d2); f4fma(a1, v21, d2);
            f4fma(a0, v30, d3); f4fma(a1, v31, d3);
        }
        for (; e < end; e++) {
            int s0 = __ldg(&g_esrc[e]);
            float d0 = __ldg(&g_dinv[s0]);
            const float4* r0 = xp + (size_t)s0 * 64;
            f4fma(a0, __ldg(&r0[lane]), d0);
            f4fma(a1, __ldg(&r0[lane + 32]), d0);
        }
        a0.x *= sd; a0.y *= sd; a0.z *= sd; a0.w *= sd;
        a1.x *= sd; a1.y *= sd; a1.z *= sd; a1.w *= sd;
    }
    uint2 h, l;
    size_t base = (size_t)w * 64;
    split4(a0, h, l);
    ((uint2*)g_ahi)[base + lane] = h;
    ((uint2*)g_alo)[base + lane] = l;
    split4(a1, h, l);
    ((uint2*)g_ahi)[base + lane + 32] = h;
    ((uint2*)g_alo)[base + lane + 32] = l;
}

// hop-2 gather, D=128: warp per dst row; out = dinv*(gs[d]+sum gs[s]) + b2
__global__ void __launch_bounds__(256) k_gather128(const float* __restrict__ b2,
                                                   float* __restrict__ out) {
    int w = (blockIdx.x * blockDim.x + threadIdx.x) >> 5;
    if (w >= N_NODES) return;
    const int lane = threadIdx.x & 31;
    const float4* gs = (const float4*)g_gs;
    float4 a0 = __ldg(&gs[(size_t)w * 32 + lane]);
    int e   = __ldg(&g_rowptr[w]);
    int end = __ldg(&g_rowptr[w + 1]);
    for (; e + 3 < end; e += 4) {
        int s0 = __ldg(&g_esrc[e]);
        int s1 = __ldg(&g_esrc[e + 1]);
        int s2 = __ldg(&g_esrc[e + 2]);
        int s3 = __ldg(&g_esrc[e + 3]);
        float4 v0 = __ldg(&gs[(size_t)s0 * 32 + lane]);
        float4 v1 = __ldg(&gs[(size_t)s1 * 32 + lane]);
        float4 v2 = __ldg(&gs[(size_t)s2 * 32 + lane]);
        float4 v3 = __ldg(&gs[(size_t)s3 * 32 + lane]);
        a0.x += v0.x + v1.x + v2.x + v3.x;
        a0.y += v0.y + v1.y + v2.y + v3.y;
        a0.z += v0.z + v1.z + v2.z + v3.z;
        a0.w += v0.w + v1.w + v2.w + v3.w;
    }
    for (; e < end; e++) {
        int s0 = __ldg(&g_esrc[e]);
        float4 v = __ldg(&gs[(size_t)s0 * 32 + lane]);
        a0.x += v.x; a0.y += v.y; a0.z += v.z; a0.w += v.w;
    }
    float s = g_dinv[w];
    float4 b = __ldg(&((const float4*)b2)[lane]);
    float4 o;
    o.x = a0.x * s + b.x;
    o.y = a0.y * s + b.y;
    o.z = a0.z * s + b.z;
    o.w = a0.w * s + b.w;
    ((float4*)out)[(size_t)w * 32 + lane] = o;
}

// --------------------------- HMMA GEMM (cp.async pipelined) -----------------
// C[128x128] tile of A[M_PAD,256] @ B^T, B stored [n][256] bf16 (hi+lo).
// 3-product bf16 split: Ah*Bh + Al*Bh + Ah*Bl, fp32 accum (mma.sync m16n8k16).
// 8 warps (2x4), warp tile 64x32, BK=32, double-buffered dynamic smem.

__device__ __forceinline__ uint32_t smem_u32(const void* p) {
    return (uint32_t)__cvta_generic_to_shared(p);
}
__device__ __forceinline__ void cp16(uint32_t s, const void* g) {
    asm volatile("cp.async.cg.shared.global [%0], [%1], 16;" :: "r"(s), "l"(g));
}
#define CP_COMMIT() asm volatile("cp.async.commit_group;" ::: "memory")
#define CP_WAIT(n)  asm volatile("cp.async.wait_group %0;" :: "n"(n) : "memory")

__device__ __forceinline__ void ldsm_x4(uint32_t& r0, uint32_t& r1,
                                        uint32_t& r2, uint32_t& r3, uint32_t a) {
    asm volatile("ldmatrix.sync.aligned.m8n8.x4.shared.b16 {%0,%1,%2,%3}, [%4];"
                 : "=r"(r0), "=r"(r1), "=r"(r2), "=r"(r3) : "r"(a));
}
__device__ __forceinline__ void mma16816(float* d, const uint32_t* a, const uint32_t* b) {
    asm volatile(
        "mma.sync.aligned.m16n8k16.row.col.f32.bf16.bf16.f32 "
        "{%0,%1,%2,%3}, {%4,%5,%6,%7}, {%8,%9}, {%0,%1,%2,%3};"
        : "+f"(d[0]), "+f"(d[1]), "+f"(d[2]), "+f"(d[3])
        : "r"(a[0]), "r"(a[1]), "r"(a[2]), "r"(a[3]), "r"(b[0]), "r"(b[1]));
}

#define BK      32
#define LDS     40                     // padded row stride (elements)
#define BUFB    (128 * LDS * 2)        // 10240 bytes per tile buffer
#define SM_MMA  (8 * BUFB)             // 81920 bytes (2 stages x 4 buffers)

template<int MODE>
__global__ void __launch_bounds__(256)
k_mma(const float* __restrict__ bias) {
    extern __shared__ char dynsmem[];
    const uint32_t sb = smem_u32(dynsmem);

    const int tid  = threadIdx.x;
    const int lane = tid & 31;
    const int wy   = (tid >> 5) & 1;
    const int wx   = (tid >> 5) >> 1;
    const size_t rowBase = (size_t)blockIdx.y * 128;
    const int    colBase = blockIdx.x * 128;

    const __nv_bfloat16* Ah = (MODE == 1) ? g_ahi : g_h1hi;
    const __nv_bfloat16* Al = (MODE == 1) ? g_alo : g_h1lo;
    const __nv_bfloat16* Bh = (MODE == 1) ? g_w1h : g_w2h;
    const __nv_bfloat16* Bl = (MODE == 1) ? g_w1l : g_w2l;

    float acc[4][4][4];
#pragma unroll
    for (int i = 0; i < 4; i++)
#pragma unroll
        for (int j = 0; j < 4; j++)
#pragma unroll
            for (int k = 0; k < 4; k++) acc[i][j][k] = 0.f;

    const int fr = tid >> 1;
    const int fh = (tid & 1) * 16;
    const size_t gA = (rowBase + fr) * 256 + fh;
    const size_t gB = ((size_t)colBase + fr) * 256 + fh;
    const uint32_t dOff = (uint32_t)((fr * LDS + fh) * 2);

    const uint32_t aoff = (uint32_t)(((wy * 64 + (lane & 15)) * LDS + (lane >> 4) * 8) * 2);
    const uint32_t boff = (uint32_t)(((wx * 32 + (lane & 7) + ((lane >> 4) << 3)) * LDS
                                      + (((lane >> 3) & 1) * 8)) * 2);

    auto issue = [&](int kc, int st) {
        const int k0 = kc * BK;
        uint32_t b = sb + (uint32_t)st * (4 * BUFB);
        cp16(b + dOff,      Ah + gA + k0);
        cp16(b + dOff + 16, Ah + gA + k0 + 8);
        b += BUFB;
        cp16(b + dOff,      Al + gA + k0);
        cp16(b + dOff + 16, Al + gA + k0 + 8);
        b += BUFB;
        cp16(b + dOff,      Bh + gB + k0);
        cp16(b + dOff + 16, Bh + gB + k0 + 8);
        b += BUFB;
        cp16(b + dOff,      Bl + gB + k0);
        cp16(b + dOff + 16, Bl + gB + k0 + 8);
    };

    issue(0, 0);
    CP_COMMIT();

#pragma unroll 1
    for (int kc = 0; kc < 8; kc++) {
        const int cur = kc & 1;
        if (kc < 7) {
            issue(kc + 1, cur ^ 1);
            CP_COMMIT();
            CP_WAIT(1);
        } else {
            CP_WAIT(0);
        }
        __syncthreads();

        const uint32_t sAh_b = sb + (uint32_t)cur * (4 * BUFB);
        const uint32_t sAl_b = sAh_b + BUFB;
        const uint32_t sBh_b = sAl_b + BUFB;
        const uint32_t sBl_b = sBh_b + BUFB;

#pragma unroll
        for (int ks = 0; ks < 2; ks++) {
            const uint32_t kb = ks * 32;
            uint32_t ah[4][4], al[4][4], bh[2][4], bl[2][4];
#pragma unroll
            for (int mi = 0; mi < 4; mi++) {
                uint32_t off = aoff + mi * (16 * LDS * 2) + kb;
                ldsm_x4(ah[mi][0], ah[mi][1], ah[mi][2], ah[mi][3], sAh_b + off);
                ldsm_x4(al[mi][0], al[mi][1], al[mi][2], al[mi][3], sAl_b + off);
            }
#pragma unroll
            for (int p = 0; p < 2; p++) {
                uint32_t off = boff + p * (16 * LDS * 2) + kb;
                ldsm_x4(bh[p][0], bh[p][1], bh[p][2], bh[p][3], sBh_b + off);
                ldsm_x4(bl[p][0], bl[p][1], bl[p][2], bl[p][3], sBl_b + off);
            }
#pragma unroll
            for (int mi = 0; mi < 4; mi++)
#pragma unroll
                for (int ni = 0; ni < 4; ni++) {
                    const int p = ni >> 1, q = (ni & 1) * 2;
                    uint32_t b0[2] = { bh[p][q], bh[p][q + 1] };
                    uint32_t b1[2] = { bl[p][q], bl[p][q + 1] };
                    mma16816(acc[mi][ni], ah[mi], b0);
                    mma16816(acc[mi][ni], al[mi], b0);
                    mma16816(acc[mi][ni], ah[mi], b1);
                }
        }
        __syncthreads();
    }

    const int gid = lane >> 2, tig = lane & 3;
#pragma unroll
    for (int mi = 0; mi < 4; mi++) {
        const int row = (int)rowBase + wy * 64 + mi * 16 + gid;
#pragma unroll
        for (int ni = 0; ni < 4; ni++) {
            const int col = colBase + wx * 32 + ni * 8 + tig * 2;
            float d0 = acc[mi][ni][0], d1 = acc[mi][ni][1];
            float d2 = acc[mi][ni][2], d3 = acc[mi][ni][3];
            if (MODE == 1) {
                float b0 = __ldg(&bias[col]), b1 = __ldg(&bias[col + 1]);
                float v0 = fmaxf(d0 + b0, 0.f), v1 = fmaxf(d1 + b1, 0.f);
                float v2 = fmaxf(d2 + b0, 0.f), v3 = fmaxf(d3 + b1, 0.f);
                uint32_t hi, lo;
                split2(v0, v1, hi, lo);
                *(uint32_t*)(g_h1hi + (size_t)row * 256 + col) = hi;
                *(uint32_t*)(g_h1lo + (size_t)row * 256 + col) = lo;
                split2(v2, v3, hi, lo);
                *(uint32_t*)(g_h1hi + (size_t)(row + 8) * 256 + col) = hi;
                *(uint32_t*)(g_h1lo + (size_t)(row + 8) * 256 + col) = lo;
            } else {
                float s0 = g_dinv[row], s1 = g_dinv[row + 8];
                *(float2*)(g_gs + (size_t)row * 128 + col)       = make_float2(d0 * s0, d1 * s0);
                *(float2*)(g_gs + (size_t)(row + 8) * 128 + col) = make_float2(d2 * s1, d3 * s1);
            }
        }
    }
}

// ---------------------------------------------------------------------------

extern "C" void kernel_launch(void* const* d_in, const int* in_sizes, int n_in,
                              void* d_out, int out_size) {
    const float* x  = (const float*)d_in[0];
    const int*   ei = (const int*)  d_in[1];
    const float* W1 = (const float*)d_in[2];
    const float* b1 = (const float*)d_in[3];
    const float* W2 = (const float*)d_in[4];
    const float* b2 = (const float*)d_in[5];
    float* out = (float*)d_out;

    const int E = in_sizes[1] / 2;
    const int* src = ei;
    const int* dst = ei + E;
    const int nb = (M_PAD + 1023) / 1024;              // 49
    const int nDegBlocks = (E + 255) / 256;
    const int nSplitBlocks = (D0 * D0 + D2 * D0 + 255) / 256;

    cudaFuncSetAttribute(k_mma<1>, cudaFuncAttributeMaxDynamicSharedMemorySize, SM_MMA);
    cudaFuncSetAttribute(k_mma<2>, cudaFuncAttributeMaxDynamicSharedMemorySize, SM_MMA);

    // CSR build + norms + weight split
    k_deg_wsplit<<<nDegBlocks + nSplitBlocks, 256>>>(dst, E, W1, W2, nDegBlocks);
    k_scan1<<<nb, 1024>>>();
    k_scan3<<<nb, 1024>>>(E);
    k_fill<<<(E + 255) / 256, 256>>>(src, dst, E);

    // hop 1 (dinv folded into gather; no xs materialization)
    k_gather256<<<(M_PAD * 32 + 255) / 256, 256>>>(x);

    // H1 = relu(prop(x) @ W1 + b1)
    k_mma<1><<<dim3(2, NTILE_M), 256, SM_MMA>>>(b1);

    // gs = (H1 @ W2) * dinv ; hop 2 + bias -> out
    k_mma<2><<<dim3(1, NTILE_M), 256, SM_MMA>>>(nullptr);
    k_gather128<<<(N_NODES * 32 + 255) / 256, 256>>>(b2, out);
}

// round 7
// speedup vs baseline: 3.2595x; 1.1016x over previous
#include <cuda_runtime.h>
#include <cuda_bf16.h>
#include <cuda_fp16.h>
#include <cstdint>

// ---------------------------------------------------------------------------
// SGCEncoder: out = prop(relu(prop(x) @ W1 + b1)) @ W2 + b2
//   prop = D^-1/2 (A+I) D^-1/2
// Rewrites:
//   prop(x)[d] = dinv[d] * ( sum_{s->d} xs[s] + xs[d] ),  xs = x*dinv (fp16)
//   prop(H1) @ W2 = prop(H1 @ W2)          (propagate at D=128)
// Round 7: fp16 hop-1 gather source (halves LTS bytes), MLP-4 deg/fill.
// ---------------------------------------------------------------------------

#define N_NODES 50000
#define M_PAD   50048          // 391 * 128
#define D0      256
#define D2      128
#define E_MAX   1600000
#define NTILE_M 391

__device__ int    g_deg   [M_PAD];     // zero at entry; restored by k_scan1
__device__ int    g_rowptr[M_PAD + 1];
__device__ int    g_cursor[M_PAD];
__device__ int    g_esrc  [E_MAX];
__device__ int    g_bsum  [64];
__device__ float  g_dinv  [M_PAD];
__device__ __half g_xh    [M_PAD * D0];      // xs = x * dinv, fp16 (hop-1 src)
__device__ float  g_gs    [M_PAD * D2];      // (H1 @ W2) * dinv (hop-2 source)
__device__ __nv_bfloat16 g_ahi [M_PAD * D0]; // hop-1 result, bf16 hi
__device__ __nv_bfloat16 g_alo [M_PAD * D0]; // hop-1 result, bf16 lo
__device__ __nv_bfloat16 g_h1hi[M_PAD * D0];
__device__ __nv_bfloat16 g_h1lo[M_PAD * D0];
__device__ __nv_bfloat16 g_w1h [D0 * D0];    // W1^T [n][k] bf16 hi
__device__ __nv_bfloat16 g_w1l [D0 * D0];
__device__ __nv_bfloat16 g_w2h [D2 * D0];    // W2^T [n][k]
__device__ __nv_bfloat16 g_w2l [D2 * D0];

// --------------------------- setup: deg histogram + weight split ------------

__global__ void k_deg_wsplit(const int* __restrict__ dst, int E,
                             const float* __restrict__ W1,
                             const float* __restrict__ W2, int nDegBlocks) {
    if ((int)blockIdx.x < nDegBlocks) {
        int base = blockIdx.x * 1024 + threadIdx.x;
        int i0 = base, i1 = base + 256, i2 = base + 512, i3 = base + 768;
        int d0 = (i0 < E) ? __ldg(&dst[i0]) : -1;
        int d1 = (i1 < E) ? __ldg(&dst[i1]) : -1;
        int d2 = (i2 < E) ? __ldg(&dst[i2]) : -1;
        int d3 = (i3 < E) ? __ldg(&dst[i3]) : -1;
        if (d0 >= 0) atomicAdd(&g_deg[d0], 1);
        if (d1 >= 0) atomicAdd(&g_deg[d1], 1);
        if (d2 >= 0) atomicAdd(&g_deg[d2], 1);
        if (d3 >= 0) atomicAdd(&g_deg[d3], 1);
    } else {
        int i = (blockIdx.x - nDegBlocks) * 256 + threadIdx.x;
        if (i < D0 * D0) {
            int n = i >> 8, k = i & 255;
            float v = W1[k * D0 + n];
            __nv_bfloat16 h = __float2bfloat16(v);
            g_w1h[n * D0 + k] = h;
            g_w1l[n * D0 + k] = __float2bfloat16(v - __bfloat162float(h));
        } else if (i < D0 * D0 + D2 * D0) {
            int j = i - D0 * D0;
            int n = j >> 8, k = j & 255;
            float v = W2[k * D2 + n];
            __nv_bfloat16 h = __float2bfloat16(v);
            g_w2h[n * D0 + k] = h;
            g_w2l[n * D0 + k] = __float2bfloat16(v - __bfloat162float(h));
        }
    }
}

// fused: read deg, zero deg (restore invariant), compute dinv, block scan
__global__ void __launch_bounds__(1024) k_scan1() {
    __shared__ int warp_red[32];
    const int tid = threadIdx.x, lane = tid & 31, wid = tid >> 5;
    int idx = blockIdx.x * 1024 + tid;
    int v = 0;
    if (idx < M_PAD) {
        v = g_deg[idx];
        g_deg[idx] = 0;
        g_dinv[idx] = (idx < N_NODES) ? rsqrtf((float)(v + 1)) : 0.0f;
    }
    int inc = v;
#pragma unroll
    for (int off = 1; off < 32; off <<= 1) {
        int t = __shfl_up_sync(0xffffffff, inc, off);
        if (lane >= off) inc += t;
    }
    if (lane == 31) warp_red[wid] = inc;
    __syncthreads();
    if (wid == 0) {
        int w = warp_red[lane];
#pragma unroll
        for (int off = 1; off < 32; off <<= 1) {
            int t = __shfl_up_sync(0xffffffff, w, off);
            if (lane >= off) w += t;
        }
        warp_red[lane] = w;
    }
    __syncthreads();
    int excl = ((wid > 0) ? warp_red[wid - 1] : 0) + (inc - v);
    if (idx < M_PAD) g_rowptr[idx] = excl;
    if (tid == 1023) g_bsum[blockIdx.x] = warp_red[31];
}

// apply block offsets (computes own prefix of g_bsum; max 64 blocks)
__global__ void __launch_bounds__(1024) k_scan3(int E) {
    __shared__ int s_off;
    if (threadIdx.x < 32) {
        int b = blockIdx.x;
        int v = 0;
        if ((int)threadIdx.x < b) v = g_bsum[threadIdx.x];
        if ((int)threadIdx.x + 32 < b) v += g_bsum[threadIdx.x + 32];
#pragma unroll
        for (int off = 16; off > 0; off >>= 1)
            v += __shfl_down_sync(0xffffffff, v, off);
        if (threadIdx.x == 0) s_off = v;
    }
    __syncthreads();
    int idx = blockIdx.x * 1024 + threadIdx.x;
    if (idx < M_PAD) {
        int v = g_rowptr[idx] + s_off;
        g_rowptr[idx] = v;
        g_cursor[idx] = v;
    } else if (idx == M_PAD) {
        g_rowptr[M_PAD] = E;
    }
}

__global__ void k_fill(const int* __restrict__ src, const int* __restrict__ dst, int E) {
    int base = blockIdx.x * 1024 + threadIdx.x;
    int i0 = base, i1 = base + 256, i2 = base + 512, i3 = base + 768;
    int s0 = 0, s1 = 0, s2 = 0, s3 = 0;
    int d0 = -1, d1 = -1, d2 = -1, d3 = -1;
    if (i0 < E) { s0 = __ldg(&src[i0]); d0 = __ldg(&dst[i0]); }
    if (i1 < E) { s1 = __ldg(&src[i1]); d1 = __ldg(&dst[i1]); }
    if (i2 < E) { s2 = __ldg(&src[i2]); d2 = __ldg(&dst[i2]); }
    if (i3 < E) { s3 = __ldg(&src[i3]); d3 = __ldg(&dst[i3]); }
    if (d0 >= 0) g_esrc[atomicAdd(&g_cursor[d0], 1)] = s0;
    if (d1 >= 0) g_esrc[atomicAdd(&g_cursor[d1], 1)] = s1;
    if (d2 >= 0) g_esrc[atomicAdd(&g_cursor[d2], 1)] = s2;
    if (d3 >= 0) g_esrc[atomicAdd(&g_cursor[d3], 1)] = s3;
}

// --------------------------- xs = x*dinv (fp16) ------------------------------

__global__ void k_scale_h(const float* __restrict__ x) {
    int i = blockIdx.x * blockDim.x + threadIdx.x;      // float4 index
    if (i >= M_PAD * (D0 / 4)) return;
    int row = i >> 6;
    float4 v = make_float4(0.f, 0.f, 0.f, 0.f);
    if (row < N_NODES) {
        v = ((const float4*)x)[i];
        float s = g_dinv[row];
        v.x *= s; v.y *= s; v.z *= s; v.w *= s;
    }
    __half2 h0 = __floats2half2_rn(v.x, v.y);
    __half2 h1 = __floats2half2_rn(v.z, v.w);
    uint2 o;
    o.x = *reinterpret_cast<uint32_t*>(&h0);
    o.y = *reinterpret_cast<uint32_t*>(&h1);
    ((uint2*)g_xh)[i] = o;
}

// --------------------------- bf16 split helpers ------------------------------

__device__ __forceinline__ uint32_t pack2(__nv_bfloat16 a, __nv_bfloat16 b) {
    __nv_bfloat162 t = __nv_bfloat162(a, b);
    return *reinterpret_cast<uint32_t*>(&t);
}
__device__ __forceinline__ void split2(float v0, float v1, uint32_t& hi, uint32_t& lo) {
    __nv_bfloat16 h0 = __float2bfloat16(v0), h1 = __float2bfloat16(v1);
    hi = pack2(h0, h1);
    lo = pack2(__float2bfloat16(v0 - __bfloat162float(h0)),
               __float2bfloat16(v1 - __bfloat162float(h1)));
}

// accumulate 8 fp16 values (one uint4) into 8 fp32 accumulators
__device__ __forceinline__ void acc8(float* a, uint4 v) {
    const __half2* h = reinterpret_cast<const __half2*>(&v);
    float2 f0 = __half22float2(h[0]);
    float2 f1 = __half22float2(h[1]);
    float2 f2 = __half22float2(h[2]);
    float2 f3 = __half22float2(h[3]);
    a[0] += f0.x; a[1] += f0.y; a[2] += f1.x; a[3] += f1.y;
    a[4] += f2.x; a[5] += f2.y; a[6] += f3.x; a[7] += f3.y;
}

// --------------------------- gathers ----------------------------------------

// hop-1 gather, D=256: warp per dst row; lane owns 8 consecutive elements.
// acc = xs[d] + sum xs[s]  (all fp16 source), result *dinv[d] -> bf16 hi/lo.
__global__ void __launch_bounds__(256) k_gather256() {
    int w = (blockIdx.x * blockDim.x + threadIdx.x) >> 5;
    if (w >= M_PAD) return;
    const int lane = threadIdx.x & 31;
    float a[8];
#pragma unroll
    for (int j = 0; j < 8; j++) a[j] = 0.f;
    if (w < N_NODES) {
        const uint4* xh = (const uint4*)g_xh;   // row stride 32 uint4
        acc8(a, __ldg(&xh[(size_t)w * 32 + lane]));   // self term
        int e   = __ldg(&g_rowptr[w]);
        int end = __ldg(&g_rowptr[w + 1]);
        for (; e + 3 < end; e += 4) {
            int s0 = __ldg(&g_esrc[e]);
            int s1 = __ldg(&g_esrc[e + 1]);
            int s2 = __ldg(&g_esrc[e + 2]);
            int s3 = __ldg(&g_esrc[e + 3]);
            uint4 v0 = __ldg(&xh[(size_t)s0 * 32 + lane]);
            uint4 v1 = __ldg(&xh[(size_t)s1 * 32 + lane]);
            uint4 v2 = __ldg(&xh[(size_t)s2 * 32 + lane]);
            uint4 v3 = __ldg(&xh[(size_t)s3 * 32 + lane]);
            acc8(a, v0); acc8(a, v1); acc8(a, v2); acc8(a, v3);
        }
        for (; e < end; e++) {
            int s0 = __ldg(&g_esrc[e]);
            acc8(a, __ldg(&xh[(size_t)s0 * 32 + lane]));
        }
        float sd = g_dinv[w];
#pragma unroll
        for (int j = 0; j < 8; j++) a[j] *= sd;
    }
    uint4 hi, lo;
    split2(a[0], a[1], hi.x, lo.x);
    split2(a[2], a[3], hi.y, lo.y);
    split2(a[4], a[5], hi.z, lo.z);
    split2(a[6], a[7], hi.w, lo.w);
    ((uint4*)g_ahi)[(size_t)w * 32 + lane] = hi;
    ((uint4*)g_alo)[(size_t)w * 32 + lane] = lo;
}

// hop-2 gather, D=128 (fp32): warp per dst row; out = dinv*(gs[d]+sum) + b2
__global__ void __launch_bounds__(256) k_gather128(const float* __restrict__ b2,
                                                   float* __restrict__ out) {
    int w = (blockIdx.x * blockDim.x + threadIdx.x) >> 5;
    if (w >= N_NODES) return;
    const int lane = threadIdx.x & 31;
    const float4* gs = (const float4*)g_gs;
    float4 a0 = __ldg(&gs[(size_t)w * 32 + lane]);
    int e   = __ldg(&g_rowptr[w]);
    int end = __ldg(&g_rowptr[w + 1]);
    for (; e + 3 < end; e += 4) {
        int s0 = __ldg(&g_esrc[e]);
        int s1 = __ldg(&g_esrc[e + 1]);
        int s2 = __ldg(&g_esrc[e + 2]);
        int s3 = __ldg(&g_esrc[e + 3]);
        float4 v0 = __ldg(&gs[(size_t)s0 * 32 + lane]);
        float4 v1 = __ldg(&gs[(size_t)s1 * 32 + lane]);
        float4 v2 = __ldg(&gs[(size_t)s2 * 32 + lane]);
        float4 v3 = __ldg(&gs[(size_t)s3 * 32 + lane]);
        a0.x += v0.x + v1.x + v2.x + v3.x;
        a0.y += v0.y + v1.y + v2.y + v3.y;
        a0.z += v0.z + v1.z + v2.z + v3.z;
        a0.w += v0.w + v1.w + v2.w + v3.w;
    }
    for (; e < end; e++) {
        int s0 = __ldg(&g_esrc[e]);
        float4 v = __ldg(&gs[(size_t)s0 * 32 + lane]);
        a0.x += v.x; a0.y += v.y; a0.z += v.z; a0.w += v.w;
    }
    float s = g_dinv[w];
    float4 b = __ldg(&((const float4*)b2)[lane]);
    float4 o;
    o.x = a0.x * s + b.x;
    o.y = a0.y * s + b.y;
    o.z = a0.z * s + b.z;
    o.w = a0.w * s + b.w;
    ((float4*)out)[(size_t)w * 32 + lane] = o;
}

// --------------------------- HMMA GEMM (cp.async pipelined) -----------------

__device__ __forceinline__ uint32_t smem_u32(const void* p) {
    return (uint32_t)__cvta_generic_to_shared(p);
}
__device__ __forceinline__ void cp16(uint32_t s, const void* g) {
    asm volatile("cp.async.cg.shared.global [%0], [%1], 16;" :: "r"(s), "l"(g));
}
#define CP_COMMIT() asm volatile("cp.async.commit_group;" ::: "memory")
#define CP_WAIT(n)  asm volatile("cp.async.wait_group %0;" :: "n"(n) : "memory")

__device__ __forceinline__ void ldsm_x4(uint32_t& r0, uint32_t& r1,
                                        uint32_t& r2, uint32_t& r3, uint32_t a) {
    asm volatile("ldmatrix.sync.aligned.m8n8.x4.shared.b16 {%0,%1,%2,%3}, [%4];"
                 : "=r"(r0), "=r"(r1), "=r"(r2), "=r"(r3) : "r"(a));
}
__device__ __forceinline__ void mma16816(float* d, const uint32_t* a, const uint32_t* b) {
    asm volatile(
        "mma.sync.aligned.m16n8k16.row.col.f32.bf16.bf16.f32 "
        "{%0,%1,%2,%3}, {%4,%5,%6,%7}, {%8,%9}, {%0,%1,%2,%3};"
        : "+f"(d[0]), "+f"(d[1]), "+f"(d[2]), "+f"(d[3])
        : "r"(a[0]), "r"(a[1]), "r"(a[2]), "r"(a[3]), "r"(b[0]), "r"(b[1]));
}

#define BK      32
#define LDS     40                     // padded row stride (elements)
#define BUFB    (128 * LDS * 2)        // 10240 bytes per tile buffer
#define SM_MMA  (8 * BUFB)             // 81920 bytes (2 stages x 4 buffers)

template<int MODE>
__global__ void __launch_bounds__(256)
k_mma(const float* __restrict__ bias) {
    extern __shared__ char dynsmem[];
    const uint32_t sb = smem_u32(dynsmem);

    const int tid  = threadIdx.x;
    const int lane = tid & 31;
    const int wy   = (tid >> 5) & 1;
    const int wx   = (tid >> 5) >> 1;
    const size_t rowBase = (size_t)blockIdx.y * 128;
    const int    colBase = blockIdx.x * 128;

    const __nv_bfloat16* Ah = (MODE == 1) ? g_ahi : g_h1hi;
    const __nv_bfloat16* Al = (MODE == 1) ? g_alo : g_h1lo;
    const __nv_bfloat16* Bh = (MODE == 1) ? g_w1h : g_w2h;
    const __nv_bfloat16* Bl = (MODE == 1) ? g_w1l : g_w2l;

    float acc[4][4][4];
#pragma unroll
    for (int i = 0; i < 4; i++)
#pragma unroll
        for (int j = 0; j < 4; j++)
#pragma unroll
            for (int k = 0; k < 4; k++) acc[i][j][k] = 0.f;

    const int fr = tid >> 1;
    const int fh = (tid & 1) * 16;
    const size_t gA = (rowBase + fr) * 256 + fh;
    const size_t gB = ((size_t)colBase + fr) * 256 + fh;
    const uint32_t dOff = (uint32_t)((fr * LDS + fh) * 2);

    const uint32_t aoff = (uint32_t)(((wy * 64 + (lane & 15)) * LDS + (lane >> 4) * 8) * 2);
    const uint32_t boff = (uint32_t)(((wx * 32 + (lane & 7) + ((lane >> 4) << 3)) * LDS
                                      + (((lane >> 3) & 1) * 8)) * 2);

    auto issue = [&](int kc, int st) {
        const int k0 = kc * BK;
        uint32_t b = sb + (uint32_t)st * (4 * BUFB);
        cp16(b + dOff,      Ah + gA + k0);
        cp16(b + dOff + 16, Ah + gA + k0 + 8);
        b += BUFB;
        cp16(b + dOff,      Al + gA + k0);
        cp16(b + dOff + 16, Al + gA + k0 + 8);
        b += BUFB;
        cp16(b + dOff,      Bh + gB + k0);
        cp16(b + dOff + 16, Bh + gB + k0 + 8);
        b += BUFB;
        cp16(b + dOff,      Bl + gB + k0);
        cp16(b + dOff + 16, Bl + gB + k0 + 8);
    };

    issue(0, 0);
    CP_COMMIT();

#pragma unroll 1
    for (int kc = 0; kc < 8; kc++) {
        const int cur = kc & 1;
        if (kc < 7) {
            issue(kc + 1, cur ^ 1);
            CP_COMMIT();
            CP_WAIT(1);
        } else {
            CP_WAIT(0);
        }
        __syncthreads();

        const uint32_t sAh_b = sb + (uint32_t)cur * (4 * BUFB);
        const uint32_t sAl_b = sAh_b + BUFB;
        const uint32_t sBh_b = sAl_b + BUFB;
        const uint32_t sBl_b = sBh_b + BUFB;

#pragma unroll
        for (int ks = 0; ks < 2; ks++) {
            const uint32_t kb = ks * 32;
            uint32_t ah[4][4], al[4][4], bh[2][4], bl[2][4];
#pragma unroll
            for (int mi = 0; mi < 4; mi++) {
                uint32_t off = aoff + mi * (16 * LDS * 2) + kb;
                ldsm_x4(ah[mi][0], ah[mi][1], ah[mi][2], ah[mi][3], sAh_b + off);
                ldsm_x4(al[mi][0], al[mi][1], al[mi][2], al[mi][3], sAl_b + off);
            }
#pragma unroll
            for (int p = 0; p < 2; p++) {
                uint32_t off = boff + p * (16 * LDS * 2) + kb;
                ldsm_x4(bh[p][0], bh[p][1], bh[p][2], bh[p][3], sBh_b + off);
                ldsm_x4(bl[p][0], bl[p][1], bl[p][2], bl[p][3], sBl_b + off);
            }
#pragma unroll
            for (int mi = 0; mi < 4; mi++)
#pragma unroll
                for (int ni = 0; ni < 4; ni++) {
                    const int p = ni >> 1, q = (ni & 1) * 2;
                    uint32_t b0[2] = { bh[p][q], bh[p][q + 1] };
                    uint32_t b1[2] = { bl[p][q], bl[p][q + 1] };
                    mma16816(acc[mi][ni], ah[mi], b0);
                    mma16816(acc[mi][ni], al[mi], b0);
                    mma16816(acc[mi][ni], ah[mi], b1);
                }
        }
        __syncthreads();
    }

    const int gid = lane >> 2, tig = lane & 3;
#pragma unroll
    for (int mi = 0; mi < 4; mi++) {
        const int row = (int)rowBase + wy * 64 + mi * 16 + gid;
#pragma unroll
        for (int ni = 0; ni < 4; ni++) {
            const int col = colBase + wx * 32 + ni * 8 + tig * 2;
            float d0 = acc[mi][ni][0], d1 = acc[mi][ni][1];
            float d2 = acc[mi][ni][2], d3 = acc[mi][ni][3];
            if (MODE == 1) {
                float b0 = __ldg(&bias[col]), b1 = __ldg(&bias[col + 1]);
                float v0 = fmaxf(d0 + b0, 0.f), v1 = fmaxf(d1 + b1, 0.f);
                float v2 = fmaxf(d2 + b0, 0.f), v3 = fmaxf(d3 + b1, 0.f);
                uint32_t hi, lo;
                split2(v0, v1, hi, lo);
                *(uint32_t*)(g_h1hi + (size_t)row * 256 + col) = hi;
                *(uint32_t*)(g_h1lo + (size_t)row * 256 + col) = lo;
                split2(v2, v3, hi, lo);
                *(uint32_t*)(g_h1hi + (size_t)(row + 8) * 256 + col) = hi;
                *(uint32_t*)(g_h1lo + (size_t)(row + 8) * 256 + col) = lo;
            } else {
                float s0 = g_dinv[row], s1 = g_dinv[row + 8];
                *(float2*)(g_gs + (size_t)row * 128 + col)       = make_float2(d0 * s0, d1 * s0);
                *(float2*)(g_gs + (size_t)(row + 8) * 128 + col) = make_float2(d2 * s1, d3 * s1);
            }
        }
    }
}

// ---------------------------------------------------------------------------

extern "C" void kernel_launch(void* const* d_in, const int* in_sizes, int n_in,
                              void* d_out, int out_size) {
    const float* x  = (const float*)d_in[0];
    const int*   ei = (const int*)  d_in[1];
    const float* W1 = (const float*)d_in[2];
    const float* b1 = (const float*)d_in[3];
    const float* W2 = (const float*)d_in[4];
    const float* b2 = (const float*)d_in[5];
    float* out = (float*)d_out;

    const int E = in_sizes[1] / 2;
    const int* src = ei;
    const int* dst = ei + E;
    const int nb = (M_PAD + 1023) / 1024;              // 49
    const int nDegBlocks = (E + 1023) / 1024;
    const int nSplitBlocks = (D0 * D0 + D2 * D0 + 255) / 256;

    cudaFuncSetAttribute(k_mma<1>, cudaFuncAttributeMaxDynamicSharedMemorySize, SM_MMA);
    cudaFuncSetAttribute(k_mma<2>, cudaFuncAttributeMaxDynamicSharedMemorySize, SM_MMA);

    // CSR build + norms + weight split
    k_deg_wsplit<<<nDegBlocks + nSplitBlocks, 256>>>(dst, E, W1, W2, nDegBlocks);
    k_scan1<<<nb, 1024>>>();
    k_scan3<<<nb, 1024>>>(E);
    k_fill<<<(E + 1023) / 1024, 256>>>(src, dst, E);

    // hop 1: xs fp16, gather at half the bytes
    k_scale_h<<<(M_PAD * (D0 / 4) + 255) / 256, 256>>>(x);
    k_gather256<<<(M_PAD * 32 + 255) / 256, 256>>>();

    // H1 = relu(prop(x) @ W1 + b1)
    k_mma<1><<<dim3(2, NTILE_M), 256, SM_MMA>>>(b1);

    // gs = (H1 @ W2) * dinv ; hop 2 + bias -> out
    k_mma<2><<<dim3(1, NTILE_M), 256, SM_MMA>>>(nullptr);
    k_gather128<<<(N_NODES * 32 + 255) / 256, 256>>>(b2, out);
}

// round 8
// speedup vs baseline: 3.4420x; 1.0560x over previous
#include <cuda_runtime.h>
#include <cuda_bf16.h>
#include <cuda_fp16.h>
#include <cstdint>

// ---------------------------------------------------------------------------
// SGCEncoder: out = prop(relu(prop(x) @ W1 + b1)) @ W2 + b2
//   prop = D^-1/2 (A+I) D^-1/2
// Rewrites:
//   prop(x)[d] = dinv[d] * ( sum_{s->d} xs[s] + xs[d] ),  xs = x*dinv (fp16)
//   prop(H1) @ W2 = prop(H1 @ W2)          (propagate at D=128, fp16 source)
// Round 8: fp16 hop-2 gather source too (halves remaining gather bytes).
// ---------------------------------------------------------------------------

#define N_NODES 50000
#define M_PAD   50048          // 391 * 128
#define D0      256
#define D2      128
#define E_MAX   1600000
#define NTILE_M 391

__device__ int    g_deg   [M_PAD];     // zero at entry; restored by k_scan1
__device__ int    g_rowptr[M_PAD + 1];
__device__ int    g_cursor[M_PAD];
__device__ int    g_esrc  [E_MAX];
__device__ int    g_bsum  [64];
__device__ float  g_dinv  [M_PAD];
__device__ __half g_xh    [M_PAD * D0];      // xs = x * dinv, fp16 (hop-1 src)
__device__ __half g_gsh   [M_PAD * D2];      // (H1 @ W2) * dinv, fp16 (hop-2 src)
__device__ __nv_bfloat16 g_ahi [M_PAD * D0]; // hop-1 result, bf16 hi
__device__ __nv_bfloat16 g_alo [M_PAD * D0]; // hop-1 result, bf16 lo
__device__ __nv_bfloat16 g_h1hi[M_PAD * D0];
__device__ __nv_bfloat16 g_h1lo[M_PAD * D0];
__device__ __nv_bfloat16 g_w1h [D0 * D0];    // W1^T [n][k] bf16 hi
__device__ __nv_bfloat16 g_w1l [D0 * D0];
__device__ __nv_bfloat16 g_w2h [D2 * D0];    // W2^T [n][k]
__device__ __nv_bfloat16 g_w2l [D2 * D0];

// --------------------------- setup: deg histogram + weight split ------------

__global__ void k_deg_wsplit(const int* __restrict__ dst, int E,
                             const float* __restrict__ W1,
                             const float* __restrict__ W2, int nDegBlocks) {
    if ((int)blockIdx.x < nDegBlocks) {
        int base = blockIdx.x * 1024 + threadIdx.x;
        int i0 = base, i1 = base + 256, i2 = base + 512, i3 = base + 768;
        int d0 = (i0 < E) ? __ldg(&dst[i0]) : -1;
        int d1 = (i1 < E) ? __ldg(&dst[i1]) : -1;
        int d2 = (i2 < E) ? __ldg(&dst[i2]) : -1;
        int d3 = (i3 < E) ? __ldg(&dst[i3]) : -1;
        if (d0 >= 0) atomicAdd(&g_deg[d0], 1);
        if (d1 >= 0) atomicAdd(&g_deg[d1], 1);
        if (d2 >= 0) atomicAdd(&g_deg[d2], 1);
        if (d3 >= 0) atomicAdd(&g_deg[d3], 1);
    } else {
        int i = (blockIdx.x - nDegBlocks) * 256 + threadIdx.x;
        if (i < D0 * D0) {
            int n = i >> 8, k = i & 255;
            float v = W1[k * D0 + n];
            __nv_bfloat16 h = __float2bfloat16(v);
            g_w1h[n * D0 + k] = h;
            g_w1l[n * D0 + k] = __float2bfloat16(v - __bfloat162float(h));
        } else if (i < D0 * D0 + D2 * D0) {
            int j = i - D0 * D0;
            int n = j >> 8, k = j & 255;
            float v = W2[k * D2 + n];
            __nv_bfloat16 h = __float2bfloat16(v);
            g_w2h[n * D0 + k] = h;
            g_w2l[n * D0 + k] = __float2bfloat16(v - __bfloat162float(h));
        }
    }
}

// fused: read deg, zero deg (restore invariant), compute dinv, block scan
__global__ void __launch_bounds__(1024) k_scan1() {
    __shared__ int warp_red[32];
    const int tid = threadIdx.x, lane = tid & 31, wid = tid >> 5;
    int idx = blockIdx.x * 1024 + tid;
    int v = 0;
    if (idx < M_PAD) {
        v = g_deg[idx];
        g_deg[idx] = 0;
        g_dinv[idx] = (idx < N_NODES) ? rsqrtf((float)(v + 1)) : 0.0f;
    }
    int inc = v;
#pragma unroll
    for (int off = 1; off < 32; off <<= 1) {
        int t = __shfl_up_sync(0xffffffff, inc, off);
        if (lane >= off) inc += t;
    }
    if (lane == 31) warp_red[wid] = inc;
    __syncthreads();
    if (wid == 0) {
        int w = warp_red[lane];
#pragma unroll
        for (int off = 1; off < 32; off <<= 1) {
            int t = __shfl_up_sync(0xffffffff, w, off);
            if (lane >= off) w += t;
        }
        warp_red[lane] = w;
    }
    __syncthreads();
    int excl = ((wid > 0) ? warp_red[wid - 1] : 0) + (inc - v);
    if (idx < M_PAD) g_rowptr[idx] = excl;
    if (tid == 1023) g_bsum[blockIdx.x] = warp_red[31];
}

// apply block offsets (computes own prefix of g_bsum; max 64 blocks)
__global__ void __launch_bounds__(1024) k_scan3(int E) {
    __shared__ int s_off;
    if (threadIdx.x < 32) {
        int b = blockIdx.x;
        int v = 0;
        if ((int)threadIdx.x < b) v = g_bsum[threadIdx.x];
        if ((int)threadIdx.x + 32 < b) v += g_bsum[threadIdx.x + 32];
#pragma unroll
        for (int off = 16; off > 0; off >>= 1)
            v += __shfl_down_sync(0xffffffff, v, off);
        if (threadIdx.x == 0) s_off = v;
    }
    __syncthreads();
    int idx = blockIdx.x * 1024 + threadIdx.x;
    if (idx < M_PAD) {
        int v = g_rowptr[idx] + s_off;
        g_rowptr[idx] = v;
        g_cursor[idx] = v;
    } else if (idx == M_PAD) {
        g_rowptr[M_PAD] = E;
    }
}

__global__ void k_fill(const int* __restrict__ src, const int* __restrict__ dst, int E) {
    int base = blockIdx.x * 1024 + threadIdx.x;
    int i0 = base, i1 = base + 256, i2 = base + 512, i3 = base + 768;
    int s0 = 0, s1 = 0, s2 = 0, s3 = 0;
    int d0 = -1, d1 = -1, d2 = -1, d3 = -1;
    if (i0 < E) { s0 = __ldg(&src[i0]); d0 = __ldg(&dst[i0]); }
    if (i1 < E) { s1 = __ldg(&src[i1]); d1 = __ldg(&dst[i1]); }
    if (i2 < E) { s2 = __ldg(&src[i2]); d2 = __ldg(&dst[i2]); }
    if (i3 < E) { s3 = __ldg(&src[i3]); d3 = __ldg(&dst[i3]); }
    if (d0 >= 0) g_esrc[atomicAdd(&g_cursor[d0], 1)] = s0;
    if (d1 >= 0) g_esrc[atomicAdd(&g_cursor[d1], 1)] = s1;
    if (d2 >= 0) g_esrc[atomicAdd(&g_cursor[d2], 1)] = s2;
    if (d3 >= 0) g_esrc[atomicAdd(&g_cursor[d3], 1)] = s3;
}

// --------------------------- xs = x*dinv (fp16) ------------------------------

__global__ void k_scale_h(const float* __restrict__ x) {
    int i = blockIdx.x * blockDim.x + threadIdx.x;      // float4 index
    if (i >= M_PAD * (D0 / 4)) return;
    int row = i >> 6;
    float4 v = make_float4(0.f, 0.f, 0.f, 0.f);
    if (row < N_NODES) {
        v = ((const float4*)x)[i];
        float s = g_dinv[row];
        v.x *= s; v.y *= s; v.z *= s; v.w *= s;
    }
    __half2 h0 = __floats2half2_rn(v.x, v.y);
    __half2 h1 = __floats2half2_rn(v.z, v.w);
    uint2 o;
    o.x = *reinterpret_cast<uint32_t*>(&h0);
    o.y = *reinterpret_cast<uint32_t*>(&h1);
    ((uint2*)g_xh)[i] = o;
}

// --------------------------- helpers -----------------------------------------

__device__ __forceinline__ uint32_t pack2(__nv_bfloat16 a, __nv_bfloat16 b) {
    __nv_bfloat162 t = __nv_bfloat162(a, b);
    return *reinterpret_cast<uint32_t*>(&t);
}
__device__ __forceinline__ void split2(float v0, float v1, uint32_t& hi, uint32_t& lo) {
    __nv_bfloat16 h0 = __float2bfloat16(v0), h1 = __float2bfloat16(v1);
    hi = pack2(h0, h1);
    lo = pack2(__float2bfloat16(v0 - __bfloat162float(h0)),
               __float2bfloat16(v1 - __bfloat162float(h1)));
}
// accumulate 8 fp16 values (one uint4) into 8 fp32 accumulators
__device__ __forceinline__ void acc8(float* a, uint4 v) {
    const __half2* h = reinterpret_cast<const __half2*>(&v);
    float2 f0 = __half22float2(h[0]);
    float2 f1 = __half22float2(h[1]);
    float2 f2 = __half22float2(h[2]);
    float2 f3 = __half22float2(h[3]);
    a[0] += f0.x; a[1] += f0.y; a[2] += f1.x; a[3] += f1.y;
    a[4] += f2.x; a[5] += f2.y; a[6] += f3.x; a[7] += f3.y;
}
// accumulate 4 fp16 values (one uint2) into 4 fp32 accumulators
__device__ __forceinline__ void acc4(float* a, uint2 v) {
    const __half2* h = reinterpret_cast<const __half2*>(&v);
    float2 f0 = __half22float2(h[0]);
    float2 f1 = __half22float2(h[1]);
    a[0] += f0.x; a[1] += f0.y; a[2] += f1.x; a[3] += f1.y;
}

// --------------------------- gathers ----------------------------------------

// hop-1 gather, D=256 fp16 src: warp per dst row; lane owns 8 elements.
__global__ void __launch_bounds__(256) k_gather256() {
    int w = (blockIdx.x * blockDim.x + threadIdx.x) >> 5;
    if (w >= M_PAD) return;
    const int lane = threadIdx.x & 31;
    float a[8];
#pragma unroll
    for (int j = 0; j < 8; j++) a[j] = 0.f;
    if (w < N_NODES) {
        const uint4* xh = (const uint4*)g_xh;   // row stride 32 uint4
        acc8(a, __ldg(&xh[(size_t)w * 32 + lane]));   // self term
        int e   = __ldg(&g_rowptr[w]);
        int end = __ldg(&g_rowptr[w + 1]);
        for (; e + 3 < end; e += 4) {
            int s0 = __ldg(&g_esrc[e]);
            int s1 = __ldg(&g_esrc[e + 1]);
            int s2 = __ldg(&g_esrc[e + 2]);
            int s3 = __ldg(&g_esrc[e + 3]);
            uint4 v0 = __ldg(&xh[(size_t)s0 * 32 + lane]);
            uint4 v1 = __ldg(&xh[(size_t)s1 * 32 + lane]);
            uint4 v2 = __ldg(&xh[(size_t)s2 * 32 + lane]);
            uint4 v3 = __ldg(&xh[(size_t)s3 * 32 + lane]);
            acc8(a, v0); acc8(a, v1); acc8(a, v2); acc8(a, v3);
        }
        for (; e < end; e++) {
            int s0 = __ldg(&g_esrc[e]);
            acc8(a, __ldg(&xh[(size_t)s0 * 32 + lane]));
        }
        float sd = g_dinv[w];
#pragma unroll
        for (int j = 0; j < 8; j++) a[j] *= sd;
    }
    uint4 hi, lo;
    split2(a[0], a[1], hi.x, lo.x);
    split2(a[2], a[3], hi.y, lo.y);
    split2(a[4], a[5], hi.z, lo.z);
    split2(a[6], a[7], hi.w, lo.w);
    ((uint4*)g_ahi)[(size_t)w * 32 + lane] = hi;
    ((uint4*)g_alo)[(size_t)w * 32 + lane] = lo;
}

// hop-2 gather, D=128 fp16 src: warp per dst row; lane owns 4 elements.
// out = dinv*(gs[d]+sum gs[s]) + b2  (fp32 accumulation and output)
__global__ void __launch_bounds__(256) k_gather128(const float* __restrict__ b2,
                                                   float* __restrict__ out) {
    int w = (blockIdx.x * blockDim.x + threadIdx.x) >> 5;
    if (w >= N_NODES) return;
    const int lane = threadIdx.x & 31;
    const uint2* gs = (const uint2*)g_gsh;      // row stride 32 uint2
    float a[4] = {0.f, 0.f, 0.f, 0.f};
    acc4(a, __ldg(&gs[(size_t)w * 32 + lane]));
    int e   = __ldg(&g_rowptr[w]);
    int end = __ldg(&g_rowptr[w + 1]);
    for (; e + 3 < end; e += 4) {
        int s0 = __ldg(&g_esrc[e]);
        int s1 = __ldg(&g_esrc[e + 1]);
        int s2 = __ldg(&g_esrc[e + 2]);
        int s3 = __ldg(&g_esrc[e + 3]);
        uint2 v0 = __ldg(&gs[(size_t)s0 * 32 + lane]);
        uint2 v1 = __ldg(&gs[(size_t)s1 * 32 + lane]);
        uint2 v2 = __ldg(&gs[(size_t)s2 * 32 + lane]);
        uint2 v3 = __ldg(&gs[(size_t)s3 * 32 + lane]);
        acc4(a, v0); acc4(a, v1); acc4(a, v2); acc4(a, v3);
    }
    for (; e < end; e++) {
        int s0 = __ldg(&g_esrc[e]);
        acc4(a, __ldg(&gs[(size_t)s0 * 32 + lane]));
    }
    float s = g_dinv[w];
    float4 b = __ldg(&((const float4*)b2)[lane]);
    float4 o;
    o.x = a[0] * s + b.x;
    o.y = a[1] * s + b.y;
    o.z = a[2] * s + b.z;
    o.w = a[3] * s + b.w;
    ((float4*)out)[(size_t)w * 32 + lane] = o;
}

// --------------------------- HMMA GEMM (cp.async pipelined) -----------------

__device__ __forceinline__ uint32_t smem_u32(const void* p) {
    return (uint32_t)__cvta_generic_to_shared(p);
}
__device__ __forceinline__ void cp16(uint32_t s, const void* g) {
    asm volatile("cp.async.cg.shared.global [%0], [%1], 16;" :: "r"(s), "l"(g));
}
#define CP_COMMIT() asm volatile("cp.async.commit_group;" ::: "memory")
#define CP_WAIT(n)  asm volatile("cp.async.wait_group %0;" :: "n"(n) : "memory")

__device__ __forceinline__ void ldsm_x4(uint32_t& r0, uint32_t& r1,
                                        uint32_t& r2, uint32_t& r3, uint32_t a) {
    asm volatile("ldmatrix.sync.aligned.m8n8.x4.shared.b16 {%0,%1,%2,%3}, [%4];"
                 : "=r"(r0), "=r"(r1), "=r"(r2), "=r"(r3) : "r"(a));
}
__device__ __forceinline__ void mma16816(float* d, const uint32_t* a, const uint32_t* b) {
    asm volatile(
        "mma.sync.aligned.m16n8k16.row.col.f32.bf16.bf16.f32 "
        "{%0,%1,%2,%3}, {%4,%5,%6,%7}, {%8,%9}, {%0,%1,%2,%3};"
        : "+f"(d[0]), "+f"(d[1]), "+f"(d[2]), "+f"(d[3])
        : "r"(a[0]), "r"(a[1]), "r"(a[2]), "r"(a[3]), "r"(b[0]), "r"(b[1]));
}

#define BK      32
#define LDS     40                     // padded row stride (elements)
#define BUFB    (128 * LDS * 2)        // 10240 bytes per tile buffer
#define SM_MMA  (8 * BUFB)             // 81920 bytes (2 stages x 4 buffers)

template<int MODE>
__global__ void __launch_bounds__(256)
k_mma(const float* __restrict__ bias) {
    extern __shared__ char dynsmem[];
    const uint32_t sb = smem_u32(dynsmem);

    const int tid  = threadIdx.x;
    const int lane = tid & 31;
    const int wy   = (tid >> 5) & 1;
    const int wx   = (tid >> 5) >> 1;
    const size_t rowBase = (size_t)blockIdx.y * 128;
    const int    colBase = blockIdx.x * 128;

    const __nv_bfloat16* Ah = (MODE == 1) ? g_ahi : g_h1hi;
    const __nv_bfloat16* Al = (MODE == 1) ? g_alo : g_h1lo;
    const __nv_bfloat16* Bh = (MODE == 1) ? g_w1h : g_w2h;
    const __nv_bfloat16* Bl = (MODE == 1) ? g_w1l : g_w2l;

    float acc[4][4][4];
#pragma unroll
    for (int i = 0; i < 4; i++)
#pragma unroll
        for (int j = 0; j < 4; j++)
#pragma unroll
            for (int k = 0; k < 4; k++) acc[i][j][k] = 0.f;

    const int fr = tid >> 1;
    const int fh = (tid & 1) * 16;
    const size_t gA = (rowBase + fr) * 256 + fh;
    const size_t gB = ((size_t)colBase + fr) * 256 + fh;
    const uint32_t dOff = (uint32_t)((fr * LDS + fh) * 2);

    const uint32_t aoff = (uint32_t)(((wy * 64 + (lane & 15)) * LDS + (lane >> 4) * 8) * 2);
    const uint32_t boff = (uint32_t)(((wx * 32 + (lane & 7) + ((lane >> 4) << 3)) * LDS
                                      + (((lane >> 3) & 1) * 8)) * 2);

    auto issue = [&](int kc, int st) {
        const int k0 = kc * BK;
        uint32_t b = sb + (uint32_t)st * (4 * BUFB);
        cp16(b + dOff,      Ah + gA + k0);
        cp16(b + dOff + 16, Ah + gA + k0 + 8);
        b += BUFB;
        cp16(b + dOff,      Al + gA + k0);
        cp16(b + dOff + 16, Al + gA + k0 + 8);
        b += BUFB;
        cp16(b + dOff,      Bh + gB + k0);
        cp16(b + dOff + 16, Bh + gB + k0 + 8);
        b += BUFB;
        cp16(b + dOff,      Bl + gB + k0);
        cp16(b + dOff + 16, Bl + gB + k0 + 8);
    };

    issue(0, 0);
    CP_COMMIT();

#pragma unroll 1
    for (int kc = 0; kc < 8; kc++) {
        const int cur = kc & 1;
        if (kc < 7) {
            issue(kc + 1, cur ^ 1);
            CP_COMMIT();
            CP_WAIT(1);
        } else {
            CP_WAIT(0);
        }
        __syncthreads();

        const uint32_t sAh_b = sb + (uint32_t)cur * (4 * BUFB);
        const uint32_t sAl_b = sAh_b + BUFB;
        const uint32_t sBh_b = sAl_b + BUFB;
        const uint32_t sBl_b = sBh_b + BUFB;

#pragma unroll
        for (int ks = 0; ks < 2; ks++) {
            const uint32_t kb = ks * 32;
            uint32_t ah[4][4], al[4][4], bh[2][4], bl[2][4];
#pragma unroll
            for (int mi = 0; mi < 4; mi++) {
                uint32_t off = aoff + mi * (16 * LDS * 2) + kb;
                ldsm_x4(ah[mi][0], ah[mi][1], ah[mi][2], ah[mi][3], sAh_b + off);
                ldsm_x4(al[mi][0], al[mi][1], al[mi][2], al[mi][3], sAl_b + off);
            }
#pragma unroll
            for (int p = 0; p < 2; p++) {
                uint32_t off = boff + p * (16 * LDS * 2) + kb;
                ldsm_x4(bh[p][0], bh[p][1], bh[p][2], bh[p][3], sBh_b + off);
                ldsm_x4(bl[p][0], bl[p][1], bl[p][2], bl[p][3], sBl_b + off);
            }
#pragma unroll
            for (int mi = 0; mi < 4; mi++)
#pragma unroll
                for (int ni = 0; ni < 4; ni++) {
                    const int p = ni >> 1, q = (ni & 1) * 2;
                    uint32_t b0[2] = { bh[p][q], bh[p][q + 1] };
                    uint32_t b1[2] = { bl[p][q], bl[p][q + 1] };
                    mma16816(acc[mi][ni], ah[mi], b0);
                    mma16816(acc[mi][ni], al[mi], b0);
                    mma16816(acc[mi][ni], ah[mi], b1);
                }
        }
        __syncthreads();
    }

    const int gid = lane >> 2, tig = lane & 3;
#pragma unroll
    for (int mi = 0; mi < 4; mi++) {
        const int row = (int)rowBase + wy * 64 + mi * 16 + gid;
#pragma unroll
        for (int ni = 0; ni < 4; ni++) {
            const int col = colBase + wx * 32 + ni * 8 + tig * 2;
            float d0 = acc[mi][ni][0], d1 = acc[mi][ni][1];
            float d2 = acc[mi][ni][2], d3 = acc[mi][ni][3];
            if (MODE == 1) {
                float b0 = __ldg(&bias[col]), b1 = __ldg(&bias[col + 1]);
                float v0 = fmaxf(d0 + b0, 0.f), v1 = fmaxf(d1 + b1, 0.f);
                float v2 = fmaxf(d2 + b0, 0.f), v3 = fmaxf(d3 + b1, 0.f);
                uint32_t hi, lo;
                split2(v0, v1, hi, lo);
                *(uint32_t*)(g_h1hi + (size_t)row * 256 + col) = hi;
                *(uint32_t*)(g_h1lo + (size_t)row * 256 + col) = lo;
                split2(v2, v3, hi, lo);
                *(uint32_t*)(g_h1hi + (size_t)(row + 8) * 256 + col) = hi;
                *(uint32_t*)(g_h1lo + (size_t)(row + 8) * 256 + col) = lo;
            } else {
                float s0 = g_dinv[row], s1 = g_dinv[row + 8];
                __half2 h0 = __floats2half2_rn(d0 * s0, d1 * s0);
                __half2 h1 = __floats2half2_rn(d2 * s1, d3 * s1);
                *(uint32_t*)(g_gsh + (size_t)row * 128 + col)       = *reinterpret_cast<uint32_t*>(&h0);
                *(uint32_t*)(g_gsh + (size_t)(row + 8) * 128 + col) = *reinterpret_cast<uint32_t*>(&h1);
            }
        }
    }
}

// ---------------------------------------------------------------------------

extern "C" void kernel_launch(void* const* d_in, const int* in_sizes, int n_in,
                              void* d_out, int out_size) {
    const float* x  = (const float*)d_in[0];
    const int*   ei = (const int*)  d_in[1];
    const float* W1 = (const float*)d_in[2];
    const float* b1 = (const float*)d_in[3];
    const float* W2 = (const float*)d_in[4];
    const float* b2 = (const float*)d_in[5];
    float* out = (float*)d_out;

    const int E = in_sizes[1] / 2;
    const int* src = ei;
    const int* dst = ei + E;
    const int nb = (M_PAD + 1023) / 1024;              // 49
    const int nDegBlocks = (E + 1023) / 1024;
    const int nSplitBlocks = (D0 * D0 + D2 * D0 + 255) / 256;

    cudaFuncSetAttribute(k_mma<1>, cudaFuncAttributeMaxDynamicSharedMemorySize, SM_MMA);
    cudaFuncSetAttribute(k_mma<2>, cudaFuncAttributeMaxDynamicSharedMemorySize, SM_MMA);

    // CSR build + norms + weight split
    k_deg_wsplit<<<nDegBlocks + nSplitBlocks, 256>>>(dst, E, W1, W2, nDegBlocks);
    k_scan1<<<nb, 1024>>>();
    k_scan3<<<nb, 1024>>>(E);
    k_fill<<<(E + 1023) / 1024, 256>>>(src, dst, E);

    // hop 1: xs fp16, gather at half the bytes
    k_scale_h<<<(M_PAD * (D0 / 4) + 255) / 256, 256>>>(x);
    k_gather256<<<(M_PAD * 32 + 255) / 256, 256>>>();

    // H1 = relu(prop(x) @ W1 + b1)
    k_mma<1><<<dim3(2, NTILE_M), 256, SM_MMA>>>(b1);

    // gsh = (H1 @ W2) * dinv (fp16) ; hop 2 + bias -> out
    k_mma<2><<<dim3(1, NTILE_M), 256, SM_MMA>>>(nullptr);
    k_gather128<<<(N_NODES * 32 + 255) / 256, 256>>>(b2, out);
}

// round 9
// speedup vs baseline: 3.9790x; 1.1560x over previous
#include <cuda_runtime.h>
#include <cuda_fp16.h>
#include <cstdint>

// ---------------------------------------------------------------------------
// SGCEncoder: out = prop(relu(prop(x) @ W1 + b1)) @ W2 + b2
//   prop = D^-1/2 (A+I) D^-1/2
// Rewrites:
//   prop(x)[d] = dinv[d] * ( sum_{s->d} xs[s] + xs[d] ),  xs = x*dinv (fp16)
//   prop(H1) @ W2 = prop(H1 @ W2)          (propagate at D=128, fp16 source)
// Round 9: fp16-A GEMM with 2-product fp16 B-split (A*Bh + A*Bl),
//          fp16 single A arrays (halved epilogue stores + A smem traffic).
// ---------------------------------------------------------------------------

#define N_NODES 50000
#define M_PAD   50048          // 391 * 128
#define D0      256
#define D2      128
#define E_MAX   1600000
#define NTILE_M 391

__device__ int    g_deg   [M_PAD];     // zero at entry; restored by k_scan1
__device__ int    g_rowptr[M_PAD + 1];
__device__ int    g_cursor[M_PAD];
__device__ int    g_esrc  [E_MAX];
__device__ int    g_bsum  [64];
__device__ float  g_dinv  [M_PAD];
__device__ __half g_xh    [M_PAD * D0];  // xs = x * dinv, fp16 (hop-1 src)
__device__ __half g_gsh   [M_PAD * D2];  // (H1 @ W2) * dinv, fp16 (hop-2 src)
__device__ __half g_ah    [M_PAD * D0];  // hop-1 result (GEMM1 A), fp16
__device__ __half g_h1h   [M_PAD * D0];  // relu(..) (GEMM2 A), fp16
__device__ __half g_w1h   [D0 * D0];     // W1^T [n][k] fp16 hi
__device__ __half g_w1l   [D0 * D0];     // W1^T fp16 lo
__device__ __half g_w2h   [D2 * D0];     // W2^T fp16 hi
__device__ __half g_w2l   [D2 * D0];     // W2^T fp16 lo

// --------------------------- setup: deg histogram + weight split ------------

__global__ void k_deg_wsplit(const int* __restrict__ dst, int E,
                             const float* __restrict__ W1,
                             const float* __restrict__ W2, int nDegBlocks) {
    if ((int)blockIdx.x < nDegBlocks) {
        int base = blockIdx.x * 1024 + threadIdx.x;
        int i0 = base, i1 = base + 256, i2 = base + 512, i3 = base + 768;
        int d0 = (i0 < E) ? __ldg(&dst[i0]) : -1;
        int d1 = (i1 < E) ? __ldg(&dst[i1]) : -1;
        int d2 = (i2 < E) ? __ldg(&dst[i2]) : -1;
        int d3 = (i3 < E) ? __ldg(&dst[i3]) : -1;
        if (d0 >= 0) atomicAdd(&g_deg[d0], 1);
        if (d1 >= 0) atomicAdd(&g_deg[d1], 1);
        if (d2 >= 0) atomicAdd(&g_deg[d2], 1);
        if (d3 >= 0) atomicAdd(&g_deg[d3], 1);
    } else {
        int i = (blockIdx.x - nDegBlocks) * 256 + threadIdx.x;
        if (i < D0 * D0) {
            int n = i >> 8, k = i & 255;
            float v = W1[k * D0 + n];
            __half h = __float2half_rn(v);
            g_w1h[n * D0 + k] = h;
            g_w1l[n * D0 + k] = __float2half_rn(v - __half2float(h));
        } else if (i < D0 * D0 + D2 * D0) {
            int j = i - D0 * D0;
            int n = j >> 8, k = j & 255;
            float v = W2[k * D2 + n];
            __half h = __float2half_rn(v);
            g_w2h[n * D0 + k] = h;
            g_w2l[n * D0 + k] = __float2half_rn(v - __half2float(h));
        }
    }
}

// fused: read deg, zero deg (restore invariant), compute dinv, block scan
__global__ void __launch_bounds__(1024) k_scan1() {
    __shared__ int warp_red[32];
    const int tid = threadIdx.x, lane = tid & 31, wid = tid >> 5;
    int idx = blockIdx.x * 1024 + tid;
    int v = 0;
    if (idx < M_PAD) {
        v = g_deg[idx];
        g_deg[idx] = 0;
        g_dinv[idx] = (idx < N_NODES) ? rsqrtf((float)(v + 1)) : 0.0f;
    }
    int inc = v;
#pragma unroll
    for (int off = 1; off < 32; off <<= 1) {
        int t = __shfl_up_sync(0xffffffff, inc, off);
        if (lane >= off) inc += t;
    }
    if (lane == 31) warp_red[wid] = inc;
    __syncthreads();
    if (wid == 0) {
        int w = warp_red[lane];
#pragma unroll
        for (int off = 1; off < 32; off <<= 1) {
            int t = __shfl_up_sync(0xffffffff, w, off);
            if (lane >= off) w += t;
        }
        warp_red[lane] = w;
    }
    __syncthreads();
    int excl = ((wid > 0) ? warp_red[wid - 1] : 0) + (inc - v);
    if (idx < M_PAD) g_rowptr[idx] = excl;
    if (tid == 1023) g_bsum[blockIdx.x] = warp_red[31];
}

// apply block offsets (computes own prefix of g_bsum; max 64 blocks)
__global__ void __launch_bounds__(1024) k_scan3(int E) {
    __shared__ int s_off;
    if (threadIdx.x < 32) {
        int b = blockIdx.x;
        int v = 0;
        if ((int)threadIdx.x < b) v = g_bsum[threadIdx.x];
        if ((int)threadIdx.x + 32 < b) v += g_bsum[threadIdx.x + 32];
#pragma unroll
        for (int off = 16; off > 0; off >>= 1)
            v += __shfl_down_sync(0xffffffff, v, off);
        if (threadIdx.x == 0) s_off = v;
    }
    __syncthreads();
    int idx = blockIdx.x * 1024 + threadIdx.x;
    if (idx < M_PAD) {
        int v = g_rowptr[idx] + s_off;
        g_rowptr[idx] = v;
        g_cursor[idx] = v;
    } else if (idx == M_PAD) {
        g_rowptr[M_PAD] = E;
    }
}

__global__ void k_fill(const int* __restrict__ src, const int* __restrict__ dst, int E) {
    int base = blockIdx.x * 1024 + threadIdx.x;
    int i0 = base, i1 = base + 256, i2 = base + 512, i3 = base + 768;
    int s0 = 0, s1 = 0, s2 = 0, s3 = 0;
    int d0 = -1, d1 = -1, d2 = -1, d3 = -1;
    if (i0 < E) { s0 = __ldg(&src[i0]); d0 = __ldg(&dst[i0]); }
    if (i1 < E) { s1 = __ldg(&src[i1]); d1 = __ldg(&dst[i1]); }
    if (i2 < E) { s2 = __ldg(&src[i2]); d2 = __ldg(&dst[i2]); }
    if (i3 < E) { s3 = __ldg(&src[i3]); d3 = __ldg(&dst[i3]); }
    if (d0 >= 0) g_esrc[atomicAdd(&g_cursor[d0], 1)] = s0;
    if (d1 >= 0) g_esrc[atomicAdd(&g_cursor[d1], 1)] = s1;
    if (d2 >= 0) g_esrc[atomicAdd(&g_cursor[d2], 1)] = s2;
    if (d3 >= 0) g_esrc[atomicAdd(&g_cursor[d3], 1)] = s3;
}

// --------------------------- xs = x*dinv (fp16) ------------------------------

__global__ void k_scale_h(const float* __restrict__ x) {
    int i = blockIdx.x * blockDim.x + threadIdx.x;      // float4 index
    if (i >= M_PAD * (D0 / 4)) return;
    int row = i >> 6;
    float4 v = make_float4(0.f, 0.f, 0.f, 0.f);
    if (row < N_NODES) {
        v = ((const float4*)x)[i];
        float s = g_dinv[row];
        v.x *= s; v.y *= s; v.z *= s; v.w *= s;
    }
    __half2 h0 = __floats2half2_rn(v.x, v.y);
    __half2 h1 = __floats2half2_rn(v.z, v.w);
    uint2 o;
    o.x = *reinterpret_cast<uint32_t*>(&h0);
    o.y = *reinterpret_cast<uint32_t*>(&h1);
    ((uint2*)g_xh)[i] = o;
}

// --------------------------- helpers -----------------------------------------

__device__ __forceinline__ uint32_t packh2(float a, float b) {
    __half2 h = __floats2half2_rn(a, b);
    return *reinterpret_cast<uint32_t*>(&h);
}
// accumulate 8 fp16 values (one uint4) into 8 fp32 accumulators
__device__ __forceinline__ void acc8(float* a, uint4 v) {
    const __half2* h = reinterpret_cast<const __half2*>(&v);
    float2 f0 = __half22float2(h[0]);
    float2 f1 = __half22float2(h[1]);
    float2 f2 = __half22float2(h[2]);
    float2 f3 = __half22float2(h[3]);
    a[0] += f0.x; a[1] += f0.y; a[2] += f1.x; a[3] += f1.y;
    a[4] += f2.x; a[5] += f2.y; a[6] += f3.x; a[7] += f3.y;
}
// accumulate 4 fp16 values (one uint2) into 4 fp32 accumulators
__device__ __forceinline__ void acc4(float* a, uint2 v) {
    const __half2* h = reinterpret_cast<const __half2*>(&v);
    float2 f0 = __half22float2(h[0]);
    float2 f1 = __half22float2(h[1]);
    a[0] += f0.x; a[1] += f0.y; a[2] += f1.x; a[3] += f1.y;
}

// --------------------------- gathers ----------------------------------------

// hop-1 gather, D=256 fp16 src: warp per dst row; lane owns 8 elements.
// result (fp16) -> g_ah
__global__ void __launch_bounds__(256) k_gather256() {
    int w = (blockIdx.x * blockDim.x + threadIdx.x) >> 5;
    if (w >= M_PAD) return;
    const int lane = threadIdx.x & 31;
    float a[8];
#pragma unroll
    for (int j = 0; j < 8; j++) a[j] = 0.f;
    if (w < N_NODES) {
        const uint4* xh = (const uint4*)g_xh;   // row stride 32 uint4
        acc8(a, __ldg(&xh[(size_t)w * 32 + lane]));   // self term
        int e   = __ldg(&g_rowptr[w]);
        int end = __ldg(&g_rowptr[w + 1]);
        for (; e + 3 < end; e += 4) {
            int s0 = __ldg(&g_esrc[e]);
            int s1 = __ldg(&g_esrc[e + 1]);
            int s2 = __ldg(&g_esrc[e + 2]);
            int s3 = __ldg(&g_esrc[e + 3]);
            uint4 v0 = __ldg(&xh[(size_t)s0 * 32 + lane]);
            uint4 v1 = __ldg(&xh[(size_t)s1 * 32 + lane]);
            uint4 v2 = __ldg(&xh[(size_t)s2 * 32 + lane]);
            uint4 v3 = __ldg(&xh[(size_t)s3 * 32 + lane]);
            acc8(a, v0); acc8(a, v1); acc8(a, v2); acc8(a, v3);
        }
        for (; e < end; e++) {
            int s0 = __ldg(&g_esrc[e]);
            acc8(a, __ldg(&xh[(size_t)s0 * 32 + lane]));
        }
        float sd = g_dinv[w];
#pragma unroll
        for (int j = 0; j < 8; j++) a[j] *= sd;
    }
    uint4 o;
    o.x = packh2(a[0], a[1]);
    o.y = packh2(a[2], a[3]);
    o.z = packh2(a[4], a[5]);
    o.w = packh2(a[6], a[7]);
    ((uint4*)g_ah)[(size_t)w * 32 + lane] = o;
}

// hop-2 gather, D=128 fp16 src: warp per dst row; lane owns 4 elements.
__global__ void __launch_bounds__(256) k_gather128(const float* __restrict__ b2,
                                                   float* __restrict__ out) {
    int w = (blockIdx.x * blockDim.x + threadIdx.x) >> 5;
    if (w >= N_NODES) return;
    const int lane = threadIdx.x & 31;
    const uint2* gs = (const uint2*)g_gsh;      // row stride 32 uint2
    float a[4] = {0.f, 0.f, 0.f, 0.f};
    acc4(a, __ldg(&gs[(size_t)w * 32 + lane]));
    int e   = __ldg(&g_rowptr[w]);
    int end = __ldg(&g_rowptr[w + 1]);
    for (; e + 3 < end; e += 4) {
        int s0 = __ldg(&g_esrc[e]);
        int s1 = __ldg(&g_esrc[e + 1]);
        int s2 = __ldg(&g_esrc[e + 2]);
        int s3 = __ldg(&g_esrc[e + 3]);
        uint2 v0 = __ldg(&gs[(size_t)s0 * 32 + lane]);
        uint2 v1 = __ldg(&gs[(size_t)s1 * 32 + lane]);
        uint2 v2 = __ldg(&gs[(size_t)s2 * 32 + lane]);
        uint2 v3 = __ldg(&gs[(size_t)s3 * 32 + lane]);
        acc4(a, v0); acc4(a, v1); acc4(a, v2); acc4(a, v3);
    }
    for (; e < end; e++) {
        int s0 = __ldg(&g_esrc[e]);
        acc4(a, __ldg(&gs[(size_t)s0 * 32 + lane]));
    }
    float s = g_dinv[w];
    float4 b = __ldg(&((const float4*)b2)[lane]);
    float4 o;
    o.x = a[0] * s + b.x;
    o.y = a[1] * s + b.y;
    o.z = a[2] * s + b.z;
    o.w = a[3] * s + b.w;
    ((float4*)out)[(size_t)w * 32 + lane] = o;
}

// --------------------------- HMMA GEMM (cp.async pipelined) -----------------
// C[128x128] tile of A[M_PAD,256](fp16) @ B^T, B [n][256] fp16 hi+lo.
// 2-product split: A*Bh + A*Bl, fp32 accum (mma.sync m16n8k16 f16).
// 8 warps (2x4), warp tile 64x32, BK=32, double-buffered dynamic smem.

__device__ __forceinline__ uint32_t smem_u32(const void* p) {
    return (uint32_t)__cvta_generic_to_shared(p);
}
__device__ __forceinline__ void cp16(uint32_t s, const void* g) {
    asm volatile("cp.async.cg.shared.global [%0], [%1], 16;" :: "r"(s), "l"(g));
}
#define CP_COMMIT() asm volatile("cp.async.commit_group;" ::: "memory")
#define CP_WAIT(n)  asm volatile("cp.async.wait_group %0;" :: "n"(n) : "memory")

__device__ __forceinline__ void ldsm_x4(uint32_t& r0, uint32_t& r1,
                                        uint32_t& r2, uint32_t& r3, uint32_t a) {
    asm volatile("ldmatrix.sync.aligned.m8n8.x4.shared.b16 {%0,%1,%2,%3}, [%4];"
                 : "=r"(r0), "=r"(r1), "=r"(r2), "=r"(r3) : "r"(a));
}
__device__ __forceinline__ void mma16816(float* d, const uint32_t* a, const uint32_t* b) {
    asm volatile(
        "mma.sync.aligned.m16n8k16.row.col.f32.f16.f16.f32 "
        "{%0,%1,%2,%3}, {%4,%5,%6,%7}, {%8,%9}, {%0,%1,%2,%3};"
        : "+f"(d[0]), "+f"(d[1]), "+f"(d[2]), "+f"(d[3])
        : "r"(a[0]), "r"(a[1]), "r"(a[2]), "r"(a[3]), "r"(b[0]), "r"(b[1]));
}

#define BK      32
#define LDS     40                     // padded row stride (elements)
#define BUFB    (128 * LDS * 2)        // 10240 bytes per tile buffer
#define SM_MMA  (6 * BUFB)             // 61440 bytes (2 stages x 3 buffers)

template<int MODE>
__global__ void __launch_bounds__(256)
k_mma(const float* __restrict__ bias) {
    extern __shared__ char dynsmem[];
    const uint32_t sb = smem_u32(dynsmem);

    const int tid  = threadIdx.x;
    const int lane = tid & 31;
    const int wy   = (tid >> 5) & 1;
    const int wx   = (tid >> 5) >> 1;
    const size_t rowBase = (size_t)blockIdx.y * 128;
    const int    colBase = blockIdx.x * 128;

    const __half* A  = (MODE == 1) ? g_ah  : g_h1h;
    const __half* Bh = (MODE == 1) ? g_w1h : g_w2h;
    const __half* Bl = (MODE == 1) ? g_w1l : g_w2l;

    float acc[4][4][4];
#pragma unroll
    for (int i = 0; i < 4; i++)
#pragma unroll
        for (int j = 0; j < 4; j++)
#pragma unroll
            for (int k = 0; k < 4; k++) acc[i][j][k] = 0.f;

    const int fr = tid >> 1;
    const int fh = (tid & 1) * 16;
    const size_t gA = (rowBase + fr) * 256 + fh;
    const size_t gB = ((size_t)colBase + fr) * 256 + fh;
    const uint32_t dOff = (uint32_t)((fr * LDS + fh) * 2);

    const uint32_t aoff = (uint32_t)(((wy * 64 + (lane & 15)) * LDS + (lane >> 4) * 8) * 2);
    const uint32_t boff = (uint32_t)(((wx * 32 + (lane & 7) + ((lane >> 4) << 3)) * LDS
                                      + (((lane >> 3) & 1) * 8)) * 2);

    auto issue = [&](int kc, int st) {
        const int k0 = kc * BK;
        uint32_t b = sb + (uint32_t)st * (3 * BUFB);
        cp16(b + dOff,      A + gA + k0);
        cp16(b + dOff + 16, A + gA + k0 + 8);
        b += BUFB;
        cp16(b + dOff,      Bh + gB + k0);
        cp16(b + dOff + 16, Bh + gB + k0 + 8);
        b += BUFB;
        cp16(b + dOff,      Bl + gB + k0);
        cp16(b + dOff + 16, Bl + gB + k0 + 8);
    };

    issue(0, 0);
    CP_COMMIT();

#pragma unroll 1
    for (int kc = 0; kc < 8; kc++) {
        const int cur = kc & 1;
        if (kc < 7) {
            issue(kc + 1, cur ^ 1);
            CP_COMMIT();
            CP_WAIT(1);
        } else {
            CP_WAIT(0);
        }
        __syncthreads();

        const uint32_t sA_b  = sb + (uint32_t)cur * (3 * BUFB);
        const uint32_t sBh_b = sA_b + BUFB;
        const uint32_t sBl_b = sBh_b + BUFB;

#pragma unroll
        for (int ks = 0; ks < 2; ks++) {
            const uint32_t kb = ks * 32;
            uint32_t a[4][4], bh[2][4], bl[2][4];
#pragma unroll
            for (int mi = 0; mi < 4; mi++) {
                uint32_t off = aoff + mi * (16 * LDS * 2) + kb;
                ldsm_x4(a[mi][0], a[mi][1], a[mi][2], a[mi][3], sA_b + off);
            }
#pragma unroll
            for (int p = 0; p < 2; p++) {
                uint32_t off = boff + p * (16 * LDS * 2) + kb;
                ldsm_x4(bh[p][0], bh[p][1], bh[p][2], bh[p][3], sBh_b + off);
                ldsm_x4(bl[p][0], bl[p][1], bl[p][2], bl[p][3], sBl_b + off);
            }
#pragma unroll
            for (int mi = 0; mi < 4; mi++)
#pragma unroll
                for (int ni = 0; ni < 4; ni++) {
                    const int p = ni >> 1, q = (ni & 1) * 2;
                    uint32_t b0[2] = { bh[p][q], bh[p][q + 1] };
                    uint32_t b1[2] = { bl[p][q], bl[p][q + 1] };
                    mma16816(acc[mi][ni], a[mi], b0);
                    mma16816(acc[mi][ni], a[mi], b1);
                }
        }
        __syncthreads();
    }

    const int gid = lane >> 2, tig = lane & 3;
#pragma unroll
    for (int mi = 0; mi < 4; mi++) {
        const int row = (int)rowBase + wy * 64 + mi * 16 + gid;
#pragma unroll
        for (int ni = 0; ni < 4; ni++) {
            const int col = colBase + wx * 32 + ni * 8 + tig * 2;
            float d0 = acc[mi][ni][0], d1 = acc[mi][ni][1];
            float d2 = acc[mi][ni][2], d3 = acc[mi][ni][3];
            if (MODE == 1) {
                float b0 = __ldg(&bias[col]), b1 = __ldg(&bias[col + 1]);
                float v0 = fmaxf(d0 + b0, 0.f), v1 = fmaxf(d1 + b1, 0.f);
                float v2 = fmaxf(d2 + b0, 0.f), v3 = fmaxf(d3 + b1, 0.f);
                *(uint32_t*)(g_h1h + (size_t)row * 256 + col)       = packh2(v0, v1);
                *(uint32_t*)(g_h1h + (size_t)(row + 8) * 256 + col) = packh2(v2, v3);
            } else {
                float s0 = g_dinv[row], s1 = g_dinv[row + 8];
                *(uint32_t*)(g_gsh + (size_t)row * 128 + col)       = packh2(d0 * s0, d1 * s0);
                *(uint32_t*)(g_gsh + (size_t)(row + 8) * 128 + col) = packh2(d2 * s1, d3 * s1);
            }
        }
    }
}

// ---------------------------------------------------------------------------

extern "C" void kernel_launch(void* const* d_in, const int* in_sizes, int n_in,
                              void* d_out, int out_size) {
    const float* x  = (const float*)d_in[0];
    const int*   ei = (const int*)  d_in[1];
    const float* W1 = (const float*)d_in[2];
    const float* b1 = (const float*)d_in[3];
    const float* W2 = (const float*)d_in[4];
    const float* b2 = (const float*)d_in[5];
    float* out = (float*)d_out;

    const int E = in_sizes[1] / 2;
    const int* src = ei;
    const int* dst = ei + E;
    const int nb = (M_PAD + 1023) / 1024;              // 49
    const int nDegBlocks = (E + 1023) / 1024;
    const int nSplitBlocks = (D0 * D0 + D2 * D0 + 255) / 256;

    cudaFuncSetAttribute(k_mma<1>, cudaFuncAttributeMaxDynamicSharedMemorySize, SM_MMA);
    cudaFuncSetAttribute(k_mma<2>, cudaFuncAttributeMaxDynamicSharedMemorySize, SM_MMA);

    // CSR build + norms + weight split
    k_deg_wsplit<<<nDegBlocks + nSplitBlocks, 256>>>(dst, E, W1, W2, nDegBlocks);
    k_scan1<<<nb, 1024>>>();
    k_scan3<<<nb, 1024>>>(E);
    k_fill<<<(E + 1023) / 1024, 256>>>(src, dst, E);

    // hop 1: xs fp16, gather at half the bytes
    k_scale_h<<<(M_PAD * (D0 / 4) + 255) / 256, 256>>>(x);
    k_gather256<<<(M_PAD * 32 + 255) / 256, 256>>>();

    // H1 = relu(prop(x) @ W1 + b1)  (fp16-A, 2-product GEMM)
    k_mma<1><<<dim3(2, NTILE_M), 256, SM_MMA>>>(b1);

    // gsh = (H1 @ W2) * dinv (fp16) ; hop 2 + bias -> out
    k_mma<2><<<dim3(1, NTILE_M), 256, SM_MMA>>>(nullptr);
    k_gather128<<<(N_NODES * 32 + 255) / 256, 256>>>(b2, out);
}

// round 10
// speedup vs baseline: 4.5089x; 1.1332x over previous
#include <cuda_runtime.h>
#include <cuda_fp16.h>
#include <cstdint>

// ---------------------------------------------------------------------------
// SGCEncoder: out = prop(relu(prop(x) @ W1 + b1)) @ W2 + b2
//   prop = D^-1/2 (A+I) D^-1/2
// Rewrites:
//   prop(x)[d] = dinv[d] * ( sum_{s->d} xs[s] + xs[d] ),  xs = x*dinv (fp16)
//   prop(H1) @ W2 = prop(H1 @ W2)          (propagate at D=128, fp16 source)
// Round 10: atomic-free CSR fill via rank trick; single-product fp16 GEMM.
// ---------------------------------------------------------------------------

#define N_NODES 50000
#define M_PAD   50048          // 391 * 128
#define D0      256
#define D2      128
#define E_MAX   1600000
#define NTILE_M 391

__device__ int    g_deg   [M_PAD];     // zero at entry; restored by k_scan1
__device__ int    g_rowptr[M_PAD + 1];
__device__ int    g_rank  [E_MAX];     // edge rank within its destination
__device__ int    g_esrc  [E_MAX];
__device__ int    g_bsum  [64];
__device__ float  g_dinv  [M_PAD];
__device__ __half g_xh    [M_PAD * D0];  // xs = x * dinv, fp16 (hop-1 src)
__device__ __half g_gsh   [M_PAD * D2];  // (H1 @ W2) * dinv, fp16 (hop-2 src)
__device__ __half g_ah    [M_PAD * D0];  // hop-1 result (GEMM1 A), fp16
__device__ __half g_h1h   [M_PAD * D0];  // relu(..) (GEMM2 A), fp16
__device__ __half g_w1    [D0 * D0];     // W1^T [n][k] fp16
__device__ __half g_w2    [D2 * D0];     // W2^T [n][k] fp16

// --------------------------- setup: deg histogram (+rank) + weight cvt ------

__global__ void k_deg_wsplit(const int* __restrict__ dst, int E,
                             const float* __restrict__ W1,
                             const float* __restrict__ W2, int nDegBlocks) {
    if ((int)blockIdx.x < nDegBlocks) {
        int base = blockIdx.x * 1024 + threadIdx.x;
#pragma unroll
        for (int u = 0; u < 4; u++) {
            int i = base + u * 256;
            if (i < E) {
                int d = __ldg(&dst[i]);
                g_rank[i] = atomicAdd(&g_deg[d], 1);
            }
        }
    } else {
        int i = (blockIdx.x - nDegBlocks) * 256 + threadIdx.x;
        if (i < D0 * D0) {
            int n = i >> 8, k = i & 255;
            g_w1[n * D0 + k] = __float2half_rn(W1[k * D0 + n]);
        } else if (i < D0 * D0 + D2 * D0) {
            int j = i - D0 * D0;
            int n = j >> 8, k = j & 255;
            g_w2[n * D0 + k] = __float2half_rn(W2[k * D2 + n]);
        }
    }
}

// fused: read deg, zero deg (restore invariant), compute dinv, block scan
__global__ void __launch_bounds__(1024) k_scan1() {
    __shared__ int warp_red[32];
    const int tid = threadIdx.x, lane = tid & 31, wid = tid >> 5;
    int idx = blockIdx.x * 1024 + tid;
    int v = 0;
    if (idx < M_PAD) {
        v = g_deg[idx];
        g_deg[idx] = 0;
        g_dinv[idx] = (idx < N_NODES) ? rsqrtf((float)(v + 1)) : 0.0f;
    }
    int inc = v;
#pragma unroll
    for (int off = 1; off < 32; off <<= 1) {
        int t = __shfl_up_sync(0xffffffff, inc, off);
        if (lane >= off) inc += t;
    }
    if (lane == 31) warp_red[wid] = inc;
    __syncthreads();
    if (wid == 0) {
        int w = warp_red[lane];
#pragma unroll
        for (int off = 1; off < 32; off <<= 1) {
            int t = __shfl_up_sync(0xffffffff, w, off);
            if (lane >= off) w += t;
        }
        warp_red[lane] = w;
    }
    __syncthreads();
    int excl = ((wid > 0) ? warp_red[wid - 1] : 0) + (inc - v);
    if (idx < M_PAD) g_rowptr[idx] = excl;
    if (tid == 1023) g_bsum[blockIdx.x] = warp_red[31];
}

// apply block offsets (computes own prefix of g_bsum; max 64 blocks)
__global__ void __launch_bounds__(1024) k_scan3(int E) {
    __shared__ int s_off;
    if (threadIdx.x < 32) {
        int b = blockIdx.x;
        int v = 0;
        if ((int)threadIdx.x < b) v = g_bsum[threadIdx.x];
        if ((int)threadIdx.x + 32 < b) v += g_bsum[threadIdx.x + 32];
#pragma unroll
        for (int off = 16; off > 0; off >>= 1)
            v += __shfl_down_sync(0xffffffff, v, off);
        if (threadIdx.x == 0) s_off = v;
    }
    __syncthreads();
    int idx = blockIdx.x * 1024 + threadIdx.x;
    if (idx < M_PAD) {
        g_rowptr[idx] += s_off;
    } else if (idx == M_PAD) {
        g_rowptr[M_PAD] = E;
    }
}

// atomic-free fill: pos = rowptr[dst] + rank
__global__ void k_fill(const int* __restrict__ src, const int* __restrict__ dst, int E) {
    int base = blockIdx.x * 1024 + threadIdx.x;
#pragma unroll
    for (int u = 0; u < 4; u++) {
        int i = base + u * 256;
        if (i < E) {
            int d = __ldg(&dst[i]);
            int r = __ldg(&g_rank[i]);
            g_esrc[__ldg(&g_rowptr[d]) + r] = __ldg(&src[i]);
        }
    }
}

// --------------------------- xs = x*dinv (fp16) ------------------------------

__global__ void k_scale_h(const float* __restrict__ x) {
    int i = blockIdx.x * blockDim.x + threadIdx.x;      // float4 index
    if (i >= M_PAD * (D0 / 4)) return;
    int row = i >> 6;
    float4 v = make_float4(0.f, 0.f, 0.f, 0.f);
    if (row < N_NODES) {
        v = ((const float4*)x)[i];
        float s = g_dinv[row];
        v.x *= s; v.y *= s; v.z *= s; v.w *= s;
    }
    __half2 h0 = __floats2half2_rn(v.x, v.y);
    __half2 h1 = __floats2half2_rn(v.z, v.w);
    uint2 o;
    o.x = *reinterpret_cast<uint32_t*>(&h0);
    o.y = *reinterpret_cast<uint32_t*>(&h1);
    ((uint2*)g_xh)[i] = o;
}

// --------------------------- helpers -----------------------------------------

__device__ __forceinline__ uint32_t packh2(float a, float b) {
    __half2 h = __floats2half2_rn(a, b);
    return *reinterpret_cast<uint32_t*>(&h);
}
__device__ __forceinline__ void acc8(float* a, uint4 v) {
    const __half2* h = reinterpret_cast<const __half2*>(&v);
    float2 f0 = __half22float2(h[0]);
    float2 f1 = __half22float2(h[1]);
    float2 f2 = __half22float2(h[2]);
    float2 f3 = __half22float2(h[3]);
    a[0] += f0.x; a[1] += f0.y; a[2] += f1.x; a[3] += f1.y;
    a[4] += f2.x; a[5] += f2.y; a[6] += f3.x; a[7] += f3.y;
}
__device__ __forceinline__ void acc4(float* a, uint2 v) {
    const __half2* h = reinterpret_cast<const __half2*>(&v);
    float2 f0 = __half22float2(h[0]);
    float2 f1 = __half22float2(h[1]);
    a[0] += f0.x; a[1] += f0.y; a[2] += f1.x; a[3] += f1.y;
}

// --------------------------- gathers ----------------------------------------

// hop-1 gather, D=256 fp16 src: warp per dst row; lane owns 8 elements.
__global__ void __launch_bounds__(256) k_gather256() {
    int w = (blockIdx.x * blockDim.x + threadIdx.x) >> 5;
    if (w >= M_PAD) return;
    const int lane = threadIdx.x & 31;
    float a[8];
#pragma unroll
    for (int j = 0; j < 8; j++) a[j] = 0.f;
    if (w < N_NODES) {
        const uint4* xh = (const uint4*)g_xh;   // row stride 32 uint4
        acc8(a, __ldg(&xh[(size_t)w * 32 + lane]));   // self term
        int e   = __ldg(&g_rowptr[w]);
        int end = __ldg(&g_rowptr[w + 1]);
        for (; e + 3 < end; e += 4) {
            int s0 = __ldg(&g_esrc[e]);
            int s1 = __ldg(&g_esrc[e + 1]);
            int s2 = __ldg(&g_esrc[e + 2]);
            int s3 = __ldg(&g_esrc[e + 3]);
            uint4 v0 = __ldg(&xh[(size_t)s0 * 32 + lane]);
            uint4 v1 = __ldg(&xh[(size_t)s1 * 32 + lane]);
            uint4 v2 = __ldg(&xh[(size_t)s2 * 32 + lane]);
            uint4 v3 = __ldg(&xh[(size_t)s3 * 32 + lane]);
            acc8(a, v0); acc8(a, v1); acc8(a, v2); acc8(a, v3);
        }
        for (; e < end; e++) {
            int s0 = __ldg(&g_esrc[e]);
            acc8(a, __ldg(&xh[(size_t)s0 * 32 + lane]));
        }
        float sd = g_dinv[w];
#pragma unroll
        for (int j = 0; j < 8; j++) a[j] *= sd;
    }
    uint4 o;
    o.x = packh2(a[0], a[1]);
    o.y = packh2(a[2], a[3]);
    o.z = packh2(a[4], a[5]);
    o.w = packh2(a[6], a[7]);
    ((uint4*)g_ah)[(size_t)w * 32 + lane] = o;
}

// hop-2 gather, D=128 fp16 src: warp per dst row; lane owns 4 elements.
__global__ void __launch_bounds__(256) k_gather128(const float* __restrict__ b2,
                                                   float* __restrict__ out) {
    int w = (blockIdx.x * blockDim.x + threadIdx.x) >> 5;
    if (w >= N_NODES) return;
    const int lane = threadIdx.x & 31;
    const uint2* gs = (const uint2*)g_gsh;      // row stride 32 uint2
    float a[4] = {0.f, 0.f, 0.f, 0.f};
    acc4(a, __ldg(&gs[(size_t)w * 32 + lane]));
    int e   = __ldg(&g_rowptr[w]);
    int end = __ldg(&g_rowptr[w + 1]);
    for (; e + 3 < end; e += 4) {
        int s0 = __ldg(&g_esrc[e]);
        int s1 = __ldg(&g_esrc[e + 1]);
        int s2 = __ldg(&g_esrc[e + 2]);
        int s3 = __ldg(&g_esrc[e + 3]);
        uint2 v0 = __ldg(&gs[(size_t)s0 * 32 + lane]);
        uint2 v1 = __ldg(&gs[(size_t)s1 * 32 + lane]);
        uint2 v2 = __ldg(&gs[(size_t)s2 * 32 + lane]);
        uint2 v3 = __ldg(&gs[(size_t)s3 * 32 + lane]);
        acc4(a, v0); acc4(a, v1); acc4(a, v2); acc4(a, v3);
    }
    for (; e < end; e++) {
        int s0 = __ldg(&g_esrc[e]);
        acc4(a, __ldg(&gs[(size_t)s0 * 32 + lane]));
    }
    float s = g_dinv[w];
    float4 b = __ldg(&((const float4*)b2)[lane]);
    float4 o;
    o.x = a[0] * s + b.x;
    o.y = a[1] * s + b.y;
    o.z = a[2] * s + b.z;
    o.w = a[3] * s + b.w;
    ((float4*)out)[(size_t)w * 32 + lane] = o;
}

// --------------------------- HMMA GEMM (cp.async pipelined) -----------------
// C[128x128] tile of A[M_PAD,256](fp16) @ B^T, B [n][256] fp16.
// Single product, fp32 accum (mma.sync m16n8k16 f16).
// 8 warps (2x4), warp tile 64x32, BK=32, double-buffered dynamic smem.

__device__ __forceinline__ uint32_t smem_u32(const void* p) {
    return (uint32_t)__cvta_generic_to_shared(p);
}
__device__ __forceinline__ void cp16(uint32_t s, const void* g) {
    asm volatile("cp.async.cg.shared.global [%0], [%1], 16;" :: "r"(s), "l"(g));
}
#define CP_COMMIT() asm volatile("cp.async.commit_group;" ::: "memory")
#define CP_WAIT(n)  asm volatile("cp.async.wait_group %0;" :: "n"(n) : "memory")

__device__ __forceinline__ void ldsm_x4(uint32_t& r0, uint32_t& r1,
                                        uint32_t& r2, uint32_t& r3, uint32_t a) {
    asm volatile("ldmatrix.sync.aligned.m8n8.x4.shared.b16 {%0,%1,%2,%3}, [%4];"
                 : "=r"(r0), "=r"(r1), "=r"(r2), "=r"(r3) : "r"(a));
}
__device__ __forceinline__ void mma16816(float* d, const uint32_t* a, const uint32_t* b) {
    asm volatile(
        "mma.sync.aligned.m16n8k16.row.col.f32.f16.f16.f32 "
        "{%0,%1,%2,%3}, {%4,%5,%6,%7}, {%8,%9}, {%0,%1,%2,%3};"
        : "+f"(d[0]), "+f"(d[1]), "+f"(d[2]), "+f"(d[3])
        : "r"(a[0]), "r"(a[1]), "r"(a[2]), "r"(a[3]), "r"(b[0]), "r"(b[1]));
}

#define BK      32
#define LDS     40                     // padded row stride (elements)
#define BUFB    (128 * LDS * 2)        // 10240 bytes per tile buffer
#define SM_MMA  (4 * BUFB)             // 40960 bytes (2 stages x 2 buffers)

template<int MODE>
__global__ void __launch_bounds__(256)
k_mma(const float* __restrict__ bias) {
    extern __shared__ char dynsmem[];
    const uint32_t sb = smem_u32(dynsmem);

    const int tid  = threadIdx.x;
    const int lane = tid & 31;
    const int wy   = (tid >> 5) & 1;
    const int wx   = (tid >> 5) >> 1;
    const size_t rowBase = (size_t)blockIdx.y * 128;
    const int    colBase = blockIdx.x * 128;

    const __half* A = (MODE == 1) ? g_ah : g_h1h;
    const __half* B = (MODE == 1) ? g_w1 : g_w2;

    float acc[4][4][4];
#pragma unroll
    for (int i = 0; i < 4; i++)
#pragma unroll
        for (int j = 0; j < 4; j++)
#pragma unroll
            for (int k = 0; k < 4; k++) acc[i][j][k] = 0.f;

    const int fr = tid >> 1;
    const int fh = (tid & 1) * 16;
    const size_t gA = (rowBase + fr) * 256 + fh;
    const size_t gB = ((size_t)colBase + fr) * 256 + fh;
    const uint32_t dOff = (uint32_t)((fr * LDS + fh) * 2);

    const uint32_t aoff = (uint32_t)(((wy * 64 + (lane & 15)) * LDS + (lane >> 4) * 8) * 2);
    const uint32_t boff = (uint32_t)(((wx * 32 + (lane & 7) + ((lane >> 4) << 3)) * LDS
                                      + (((lane >> 3) & 1) * 8)) * 2);

    auto issue = [&](int kc, int st) {
        const int k0 = kc * BK;
        uint32_t b = sb + (uint32_t)st * (2 * BUFB);
        cp16(b + dOff,      A + gA + k0);
        cp16(b + dOff + 16, A + gA + k0 + 8);
        b += BUFB;
        cp16(b + dOff,      B + gB + k0);
        cp16(b + dOff + 16, B + gB + k0 + 8);
    };

    issue(0, 0);
    CP_COMMIT();

#pragma unroll 1
    for (int kc = 0; kc < 8; kc++) {
        const int cur = kc & 1;
        if (kc < 7) {
            issue(kc + 1, cur ^ 1);
            CP_COMMIT();
            CP_WAIT(1);
        } else {
            CP_WAIT(0);
        }
        __syncthreads();

        const uint32_t sA_b = sb + (uint32_t)cur * (2 * BUFB);
        const uint32_t sB_b = sA_b + BUFB;

#pragma unroll
        for (int ks = 0; ks < 2; ks++) {
            const uint32_t kb = ks * 32;
            uint32_t a[4][4], bh[2][4];
#pragma unroll
            for (int mi = 0; mi < 4; mi++) {
                uint32_t off = aoff + mi * (16 * LDS * 2) + kb;
                ldsm_x4(a[mi][0], a[mi][1], a[mi][2], a[mi][3], sA_b + off);
            }
#pragma unroll
            for (int p = 0; p < 2; p++) {
                uint32_t off = boff + p * (16 * LDS * 2) + kb;
                ldsm_x4(bh[p][0], bh[p][1], bh[p][2], bh[p][3], sB_b + off);
            }
#pragma unroll
            for (int mi = 0; mi < 4; mi++)
#pragma unroll
                for (int ni = 0; ni < 4; ni++) {
                    const int p = ni >> 1, q = (ni & 1) * 2;
                    uint32_t b0[2] = { bh[p][q], bh[p][q + 1] };
                    mma16816(acc[mi][ni], a[mi], b0);
                }
        }
        __syncthreads();
    }

    const int gid = lane >> 2, tig = lane & 3;
#pragma unroll
    for (int mi = 0; mi < 4; mi++) {
        const int row = (int)rowBase + wy * 64 + mi * 16 + gid;
#pragma unroll
        for (int ni = 0; ni < 4; ni++) {
            const int col = colBase + wx * 32 + ni * 8 + tig * 2;
            float d0 = acc[mi][ni][0], d1 = acc[mi][ni][1];
            float d2 = acc[mi][ni][2], d3 = acc[mi][ni][3];
            if (MODE == 1) {
                float b0 = __ldg(&bias[col]), b1 = __ldg(&bias[col + 1]);
                float v0 = fmaxf(d0 + b0, 0.f), v1 = fmaxf(d1 + b1, 0.f);
                float v2 = fmaxf(d2 + b0, 0.f), v3 = fmaxf(d3 + b1, 0.f);
                *(uint32_t*)(g_h1h + (size_t)row * 256 + col)       = packh2(v0, v1);
                *(uint32_t*)(g_h1h + (size_t)(row + 8) * 256 + col) = packh2(v2, v3);
            } else {
                float s0 = g_dinv[row], s1 = g_dinv[row + 8];
                *(uint32_t*)(g_gsh + (size_t)row * 128 + col)       = packh2(d0 * s0, d1 * s0);
                *(uint32_t*)(g_gsh + (size_t)(row + 8) * 128 + col) = packh2(d2 * s1, d3 * s1);
            }
        }
    }
}

// ---------------------------------------------------------------------------

extern "C" void kernel_launch(void* const* d_in, const int* in_sizes, int n_in,
                              void* d_out, int out_size) {
    const float* x  = (const float*)d_in[0];
    const int*   ei = (const int*)  d_in[1];
    const float* W1 = (const float*)d_in[2];
    const float* b1 = (const float*)d_in[3];
    const float* W2 = (const float*)d_in[4];
    const float* b2 = (const float*)d_in[5];
    float* out = (float*)d_out;

    const int E = in_sizes[1] / 2;
    const int* src = ei;
    const int* dst = ei + E;
    const int nb = (M_PAD + 1023) / 1024;              // 49
    const int nDegBlocks = (E + 1023) / 1024;
    const int nSplitBlocks = (D0 * D0 + D2 * D0 + 255) / 256;

    cudaFuncSetAttribute(k_mma<1>, cudaFuncAttributeMaxDynamicSharedMemorySize, SM_MMA);
    cudaFuncSetAttribute(k_mma<2>, cudaFuncAttributeMaxDynamicSharedMemorySize, SM_MMA);

    // CSR build + norms + weight convert
    k_deg_wsplit<<<nDegBlocks + nSplitBlocks, 256>>>(dst, E, W1, W2, nDegBlocks);
    k_scan1<<<nb, 1024>>>();
    k_scan3<<<nb, 1024>>>(E);
    k_fill<<<(E + 1023) / 1024, 256>>>(src, dst, E);

    // hop 1: xs fp16
    k_scale_h<<<(M_PAD * (D0 / 4) + 255) / 256, 256>>>(x);
    k_gather256<<<(M_PAD * 32 + 255) / 256, 256>>>();

    // H1 = relu(prop(x) @ W1 + b1)  (fp16 single-product GEMM)
    k_mma<1><<<dim3(2, NTILE_M), 256, SM_MMA>>>(b1);

    // gsh = (H1 @ W2) * dinv (fp16) ; hop 2 + bias -> out
    k_mma<2><<<dim3(1, NTILE_M), 256, SM_MMA>>>(nullptr);
    k_gather128<<<(N_NODES * 32 + 255) / 256, 256>>>(b2, out);
}

// round 11
// speedup vs baseline: 4.5514x; 1.0094x over previous
#include <cuda_runtime.h>
#include <cuda_fp16.h>
#include <cstdint>

// ---------------------------------------------------------------------------
// SGCEncoder: out = prop(relu(prop(x) @ W1 + b1)) @ W2 + b2
//   prop = D^-1/2 (A+I) D^-1/2
// Rewrites:
//   prop(x)[d] = dinv[d] * ( sum_{s->d} xs[s] + xs[d] ),  xs = x*dinv (fp16)
//   prop(H1) @ W2 = prop(H1 @ W2)          (propagate at D=128, fp16 source)
// Round 11: stream-fork overlap inside the captured graph
//   - scale_h concurrent with scan3+fill
//   - row-chunked gather256 -> mma1 -> mma2 pipeline (2 chunks)
// ---------------------------------------------------------------------------

#define N_NODES 50000
#define M_PAD   50048          // 391 * 128
#define D0      256
#define D2      128
#define E_MAX   1600000
#define NTILE_M 391
#define TILE0   196            // chunk0 tiles
#define TILE1   (NTILE_M - TILE0)
#define ROWHALF (TILE0 * 128)  // 25088

__device__ int    g_deg   [M_PAD];     // zero at entry; restored by k_scan1
__device__ int    g_rowptr[M_PAD + 1];
__device__ int    g_rank  [E_MAX];     // edge rank within its destination
__device__ int    g_esrc  [E_MAX];
__device__ int    g_bsum  [64];
__device__ float  g_dinv  [M_PAD];
__device__ __half g_xh    [M_PAD * D0];  // xs = x * dinv, fp16 (hop-1 src)
__device__ __half g_gsh   [M_PAD * D2];  // (H1 @ W2) * dinv, fp16 (hop-2 src)
__device__ __half g_ah    [M_PAD * D0];  // hop-1 result (GEMM1 A), fp16
__device__ __half g_h1h   [M_PAD * D0];  // relu(..) (GEMM2 A), fp16
__device__ __half g_w1    [D0 * D0];     // W1^T [n][k] fp16
__device__ __half g_w2    [D2 * D0];     // W2^T [n][k] fp16

__global__ void k_noop() {}

// --------------------------- setup: deg histogram (+rank) + weight cvt ------

__global__ void k_deg_wsplit(const int* __restrict__ dst, int E,
                             const float* __restrict__ W1,
                             const float* __restrict__ W2, int nDegBlocks) {
    if ((int)blockIdx.x < nDegBlocks) {
        int base = blockIdx.x * 1024 + threadIdx.x;
#pragma unroll
        for (int u = 0; u < 4; u++) {
            int i = base + u * 256;
            if (i < E) {
                int d = __ldg(&dst[i]);
                g_rank[i] = atomicAdd(&g_deg[d], 1);
            }
        }
    } else {
        int i = (blockIdx.x - nDegBlocks) * 256 + threadIdx.x;
        if (i < D0 * D0) {
            int n = i >> 8, k = i & 255;
            g_w1[n * D0 + k] = __float2half_rn(W1[k * D0 + n]);
        } else if (i < D0 * D0 + D2 * D0) {
            int j = i - D0 * D0;
            int n = j >> 8, k = j & 255;
            g_w2[n * D0 + k] = __float2half_rn(W2[k * D2 + n]);
        }
    }
}

// fused: read deg, zero deg (restore invariant), compute dinv, block scan
__global__ void __launch_bounds__(1024) k_scan1() {
    __shared__ int warp_red[32];
    const int tid = threadIdx.x, lane = tid & 31, wid = tid >> 5;
    int idx = blockIdx.x * 1024 + tid;
    int v = 0;
    if (idx < M_PAD) {
        v = g_deg[idx];
        g_deg[idx] = 0;
        g_dinv[idx] = (idx < N_NODES) ? rsqrtf((float)(v + 1)) : 0.0f;
    }
    int inc = v;
#pragma unroll
    for (int off = 1; off < 32; off <<= 1) {
        int t = __shfl_up_sync(0xffffffff, inc, off);
        if (lane >= off) inc += t;
    }
    if (lane == 31) warp_red[wid] = inc;
    __syncthreads();
    if (wid == 0) {
        int w = warp_red[lane];
#pragma unroll
        for (int off = 1; off < 32; off <<= 1) {
            int t = __shfl_up_sync(0xffffffff, w, off);
            if (lane >= off) w += t;
        }
        warp_red[lane] = w;
    }
    __syncthreads();
    int excl = ((wid > 0) ? warp_red[wid - 1] : 0) + (inc - v);
    if (idx < M_PAD) g_rowptr[idx] = excl;
    if (tid == 1023) g_bsum[blockIdx.x] = warp_red[31];
}

// apply block offsets (computes own prefix of g_bsum; max 64 blocks)
__global__ void __launch_bounds__(1024) k_scan3(int E) {
    __shared__ int s_off;
    if (threadIdx.x < 32) {
        int b = blockIdx.x;
        int v = 0;
        if ((int)threadIdx.x < b) v = g_bsum[threadIdx.x];
        if ((int)threadIdx.x + 32 < b) v += g_bsum[threadIdx.x + 32];
#pragma unroll
        for (int off = 16; off > 0; off >>= 1)
            v += __shfl_down_sync(0xffffffff, v, off);
        if (threadIdx.x == 0) s_off = v;
    }
    __syncthreads();
    int idx = blockIdx.x * 1024 + threadIdx.x;
    if (idx < M_PAD) {
        g_rowptr[idx] += s_off;
    } else if (idx == M_PAD) {
        g_rowptr[M_PAD] = E;
    }
}

// atomic-free fill: pos = rowptr[dst] + rank
__global__ void k_fill(const int* __restrict__ src, const int* __restrict__ dst, int E) {
    int base = blockIdx.x * 1024 + threadIdx.x;
#pragma unroll
    for (int u = 0; u < 4; u++) {
        int i = base + u * 256;
        if (i < E) {
            int d = __ldg(&dst[i]);
            int r = __ldg(&g_rank[i]);
            g_esrc[__ldg(&g_rowptr[d]) + r] = __ldg(&src[i]);
        }
    }
}

// --------------------------- xs = x*dinv (fp16) ------------------------------

__global__ void k_scale_h(const float* __restrict__ x) {
    int i = blockIdx.x * blockDim.x + threadIdx.x;      // float4 index
    if (i >= M_PAD * (D0 / 4)) return;
    int row = i >> 6;
    float4 v = make_float4(0.f, 0.f, 0.f, 0.f);
    if (row < N_NODES) {
        v = ((const float4*)x)[i];
        float s = g_dinv[row];
        v.x *= s; v.y *= s; v.z *= s; v.w *= s;
    }
    __half2 h0 = __floats2half2_rn(v.x, v.y);
    __half2 h1 = __floats2half2_rn(v.z, v.w);
    uint2 o;
    o.x = *reinterpret_cast<uint32_t*>(&h0);
    o.y = *reinterpret_cast<uint32_t*>(&h1);
    ((uint2*)g_xh)[i] = o;
}

// --------------------------- helpers -----------------------------------------

__device__ __forceinline__ uint32_t packh2(float a, float b) {
    __half2 h = __floats2half2_rn(a, b);
    return *reinterpret_cast<uint32_t*>(&h);
}
__device__ __forceinline__ void acc8(float* a, uint4 v) {
    const __half2* h = reinterpret_cast<const __half2*>(&v);
    float2 f0 = __half22float2(h[0]);
    float2 f1 = __half22float2(h[1]);
    float2 f2 = __half22float2(h[2]);
    float2 f3 = __half22float2(h[3]);
    a[0] += f0.x; a[1] += f0.y; a[2] += f1.x; a[3] += f1.y;
    a[4] += f2.x; a[5] += f2.y; a[6] += f3.x; a[7] += f3.y;
}
__device__ __forceinline__ void acc4(float* a, uint2 v) {
    const __half2* h = reinterpret_cast<const __half2*>(&v);
    float2 f0 = __half22float2(h[0]);
    float2 f1 = __half22float2(h[1]);
    a[0] += f0.x; a[1] += f0.y; a[2] += f1.x; a[3] += f1.y;
}

// --------------------------- gathers ----------------------------------------

// hop-1 gather over rows [rowBeg, rowEnd): warp per dst row; lane owns 8 elems.
__global__ void __launch_bounds__(256) k_gather256(int rowBeg, int rowEnd) {
    int w = rowBeg + ((blockIdx.x * blockDim.x + threadIdx.x) >> 5);
    if (w >= rowEnd) return;
    const int lane = threadIdx.x & 31;
    float a[8];
#pragma unroll
    for (int j = 0; j < 8; j++) a[j] = 0.f;
    if (w < N_NODES) {
        const uint4* xh = (const uint4*)g_xh;   // row stride 32 uint4
        acc8(a, __ldg(&xh[(size_t)w * 32 + lane]));   // self term
        int e   = __ldg(&g_rowptr[w]);
        int end = __ldg(&g_rowptr[w + 1]);
        for (; e + 3 < end; e += 4) {
            int s0 = __ldg(&g_esrc[e]);
            int s1 = __ldg(&g_esrc[e + 1]);
            int s2 = __ldg(&g_esrc[e + 2]);
            int s3 = __ldg(&g_esrc[e + 3]);
            uint4 v0 = __ldg(&xh[(size_t)s0 * 32 + lane]);
            uint4 v1 = __ldg(&xh[(size_t)s1 * 32 + lane]);
            uint4 v2 = __ldg(&xh[(size_t)s2 * 32 + lane]);
            uint4 v3 = __ldg(&xh[(size_t)s3 * 32 + lane]);
            acc8(a, v0); acc8(a, v1); acc8(a, v2); acc8(a, v3);
        }
        for (; e < end; e++) {
            int s0 = __ldg(&g_esrc[e]);
            acc8(a, __ldg(&xh[(size_t)s0 * 32 + lane]));
        }
        float sd = g_dinv[w];
#pragma unroll
        for (int j = 0; j < 8; j++) a[j] *= sd;
    }
    uint4 o;
    o.x = packh2(a[0], a[1]);
    o.y = packh2(a[2], a[3]);
    o.z = packh2(a[4], a[5]);
    o.w = packh2(a[6], a[7]);
    ((uint4*)g_ah)[(size_t)w * 32 + lane] = o;
}

// hop-2 gather, D=128 fp16 src: warp per dst row; lane owns 4 elements.
__global__ void __launch_bounds__(256) k_gather128(const float* __restrict__ b2,
                                                   float* __restrict__ out) {
    int w = (blockIdx.x * blockDim.x + threadIdx.x) >> 5;
    if (w >= N_NODES) return;
    const int lane = threadIdx.x & 31;
    const uint2* gs = (const uint2*)g_gsh;      // row stride 32 uint2
    float a[4] = {0.f, 0.f, 0.f, 0.f};
    acc4(a, __ldg(&gs[(size_t)w * 32 + lane]));
    int e   = __ldg(&g_rowptr[w]);
    int end = __ldg(&g_rowptr[w + 1]);
    for (; e + 3 < end; e += 4) {
        int s0 = __ldg(&g_esrc[e]);
        int s1 = __ldg(&g_esrc[e + 1]);
        int s2 = __ldg(&g_esrc[e + 2]);
        int s3 = __ldg(&g_esrc[e + 3]);
        uint2 v0 = __ldg(&gs[(size_t)s0 * 32 + lane]);
        uint2 v1 = __ldg(&gs[(size_t)s1 * 32 + lane]);
        uint2 v2 = __ldg(&gs[(size_t)s2 * 32 + lane]);
        uint2 v3 = __ldg(&gs[(size_t)s3 * 32 + lane]);
        acc4(a, v0); acc4(a, v1); acc4(a, v2); acc4(a, v3);
    }
    for (; e < end; e++) {
        int s0 = __ldg(&g_esrc[e]);
        acc4(a, __ldg(&gs[(size_t)s0 * 32 + lane]));
    }
    float s = g_dinv[w];
    float4 b = __ldg(&((const float4*)b2)[lane]);
    float4 o;
    o.x = a[0] * s + b.x;
    o.y = a[1] * s + b.y;
    o.z = a[2] * s + b.z;
    o.w = a[3] * s + b.w;
    ((float4*)out)[(size_t)w * 32 + lane] = o;
}

// --------------------------- HMMA GEMM (cp.async pipelined) -----------------
// C[128x128] tile of A[M_PAD,256](fp16) @ B^T, B [n][256] fp16.
// Single product, fp32 accum (mma.sync m16n8k16 f16).
// 8 warps (2x4), warp tile 64x32, BK=32, double-buffered dynamic smem.

__device__ __forceinline__ uint32_t smem_u32(const void* p) {
    return (uint32_t)__cvta_generic_to_shared(p);
}
__device__ __forceinline__ void cp16(uint32_t s, const void* g) {
    asm volatile("cp.async.cg.shared.global [%0], [%1], 16;" :: "r"(s), "l"(g));
}
#define CP_COMMIT() asm volatile("cp.async.commit_group;" ::: "memory")
#define CP_WAIT(n)  asm volatile("cp.async.wait_group %0;" :: "n"(n) : "memory")

__device__ __forceinline__ void ldsm_x4(uint32_t& r0, uint32_t& r1,
                                        uint32_t& r2, uint32_t& r3, uint32_t a) {
    asm volatile("ldmatrix.sync.aligned.m8n8.x4.shared.b16 {%0,%1,%2,%3}, [%4];"
                 : "=r"(r0), "=r"(r1), "=r"(r2), "=r"(r3) : "r"(a));
}
__device__ __forceinline__ void mma16816(float* d, const uint32_t* a, const uint32_t* b) {
    asm volatile(
        "mma.sync.aligned.m16n8k16.row.col.f32.f16.f16.f32 "
        "{%0,%1,%2,%3}, {%4,%5,%6,%7}, {%8,%9}, {%0,%1,%2,%3};"
        : "+f"(d[0]), "+f"(d[1]), "+f"(d[2]), "+f"(d[3])
        : "r"(a[0]), "r"(a[1]), "r"(a[2]), "r"(a[3]), "r"(b[0]), "r"(b[1]));
}

#define BK      32
#define LDS     40                     // padded row stride (elements)
#define BUFB    (128 * LDS * 2)        // 10240 bytes per tile buffer
#define SM_MMA  (4 * BUFB)             // 40960 bytes (2 stages x 2 buffers)

template<int MODE>
__global__ void __launch_bounds__(256)
k_mma(const float* __restrict__ bias, int tileOff) {
    extern __shared__ char dynsmem[];
    const uint32_t sb = smem_u32(dynsmem);

    const int tid  = threadIdx.x;
    const int lane = tid & 31;
    const int wy   = (tid >> 5) & 1;
    const int wx   = (tid >> 5) >> 1;
    const size_t rowBase = (size_t)(tileOff + blockIdx.y) * 128;
    const int    colBase = blockIdx.x * 128;

    const __half* A = (MODE == 1) ? g_ah : g_h1h;
    const __half* B = (MODE == 1) ? g_w1 : g_w2;

    float acc[4][4][4];
#pragma unroll
    for (int i = 0; i < 4; i++)
#pragma unroll
        for (int j = 0; j < 4; j++)
#pragma unroll
            for (int k = 0; k < 4; k++) acc[i][j][k] = 0.f;

    const int fr = tid >> 1;
    const int fh = (tid & 1) * 16;
    const size_t gA = (rowBase + fr) * 256 + fh;
    const size_t gB = ((size_t)colBase + fr) * 256 + fh;
    const uint32_t dOff = (uint32_t)((fr * LDS + fh) * 2);

    const uint32_t aoff = (uint32_t)(((wy * 64 + (lane & 15)) * LDS + (lane >> 4) * 8) * 2);
    const uint32_t boff = (uint32_t)(((wx * 32 + (lane & 7) + ((lane >> 4) << 3)) * LDS
                                      + (((lane >> 3) & 1) * 8)) * 2);

    auto issue = [&](int kc, int st) {
        const int k0 = kc * BK;
        uint32_t b = sb + (uint32_t)st * (2 * BUFB);
        cp16(b + dOff,      A + gA + k0);
        cp16(b + dOff + 16, A + gA + k0 + 8);
        b += BUFB;
        cp16(b + dOff,      B + gB + k0);
        cp16(b + dOff + 16, B + gB + k0 + 8);
    };

    issue(0, 0);
    CP_COMMIT();

#pragma unroll 1
    for (int kc = 0; kc < 8; kc++) {
        const int cur = kc & 1;
        if (kc < 7) {
            issue(kc + 1, cur ^ 1);
            CP_COMMIT();
            CP_WAIT(1);
        } else {
            CP_WAIT(0);
        }
        __syncthreads();

        const uint32_t sA_b = sb + (uint32_t)cur * (2 * BUFB);
        const uint32_t sB_b = sA_b + BUFB;

#pragma unroll
        for (int ks = 0; ks < 2; ks++) {
            const uint32_t kb = ks * 32;
            uint32_t a[4][4], bh[2][4];
#pragma unroll
            for (int mi = 0; mi < 4; mi++) {
                uint32_t off = aoff + mi * (16 * LDS * 2) + kb;
                ldsm_x4(a[mi][0], a[mi][1], a[mi][2], a[mi][3], sA_b + off);
            }
#pragma unroll
            for (int p = 0; p < 2; p++) {
                uint32_t off = boff + p * (16 * LDS * 2) + kb;
                ldsm_x4(bh[p][0], bh[p][1], bh[p][2], bh[p][3], sB_b + off);
            }
#pragma unroll
            for (int mi = 0; mi < 4; mi++)
#pragma unroll
                for (int ni = 0; ni < 4; ni++) {
                    const int p = ni >> 1, q = (ni & 1) * 2;
                    uint32_t b0[2] = { bh[p][q], bh[p][q + 1] };
                    mma16816(acc[mi][ni], a[mi], b0);
                }
        }
        __syncthreads();
    }

    const int gid = lane >> 2, tig = lane & 3;
#pragma unroll
    for (int mi = 0; mi < 4; mi++) {
        const int row = (int)rowBase + wy * 64 + mi * 16 + gid;
#pragma unroll
        for (int ni = 0; ni < 4; ni++) {
            const int col = colBase + wx * 32 + ni * 8 + tig * 2;
            float d0 = acc[mi][ni][0], d1 = acc[mi][ni][1];
            float d2 = acc[mi][ni][2], d3 = acc[mi][ni][3];
            if (MODE == 1) {
                float b0 = __ldg(&bias[col]), b1 = __ldg(&bias[col + 1]);
                float v0 = fmaxf(d0 + b0, 0.f), v1 = fmaxf(d1 + b1, 0.f);
                float v2 = fmaxf(d2 + b0, 0.f), v3 = fmaxf(d3 + b1, 0.f);
                *(uint32_t*)(g_h1h + (size_t)row * 256 + col)       = packh2(v0, v1);
                *(uint32_t*)(g_h1h + (size_t)(row + 8) * 256 + col) = packh2(v2, v3);
            } else {
                float s0 = g_dinv[row], s1 = g_dinv[row + 8];
                *(uint32_t*)(g_gsh + (size_t)row * 128 + col)       = packh2(d0 * s0, d1 * s0);
                *(uint32_t*)(g_gsh + (size_t)(row + 8) * 128 + col) = packh2(d2 * s1, d3 * s1);
            }
        }
    }
}

// ---------------------------------------------------------------------------

struct HxCtx {
    cudaStream_t s2 = nullptr;
    cudaEvent_t evScale = nullptr, evG0 = nullptr, evM0 = nullptr, evFork = nullptr;
    bool ok = false;
    void init() {
        if (cudaStreamCreateWithFlags(&s2, cudaStreamNonBlocking) != cudaSuccess) return;
        cudaEventCreateWithFlags(&evScale, cudaEventDisableTiming);
        cudaEventCreateWithFlags(&evG0, cudaEventDisableTiming);
        cudaEventCreateWithFlags(&evM0, cudaEventDisableTiming);
        cudaEventCreateWithFlags(&evFork, cudaEventDisableTiming);
        // warm both streams outside capture (first call is the correctness run)
        k_noop<<<1, 32>>>();
        k_noop<<<1, 32, 0, s2>>>();
        cudaStreamSynchronize(s2);
        cudaStreamSynchronize(0);
        ok = true;
    }
};

extern "C" void kernel_launch(void* const* d_in, const int* in_sizes, int n_in,
                              void* d_out, int out_size) {
    const float* x  = (const float*)d_in[0];
    const int*   ei = (const int*)  d_in[1];
    const float* W1 = (const float*)d_in[2];
    const float* b1 = (const float*)d_in[3];
    const float* W2 = (const float*)d_in[4];
    const float* b2 = (const float*)d_in[5];
    float* out = (float*)d_out;

    const int E = in_sizes[1] / 2;
    const int* src = ei;
    const int* dst = ei + E;
    const int nb = (M_PAD + 1023) / 1024;              // 49
    const int nDegBlocks = (E + 1023) / 1024;
    const int nSplitBlocks = (D0 * D0 + D2 * D0 + 255) / 256;

    static HxCtx ctx;
    // one-time resource init happens on the correctness call (no capture active)
    cudaStreamCaptureStatus cap = cudaStreamCaptureStatusNone;
    cudaStreamIsCapturing(0, &cap);
    if (!ctx.ok && cap == cudaStreamCaptureStatusNone) ctx.init();

    cudaFuncSetAttribute(k_mma<1>, cudaFuncAttributeMaxDynamicSharedMemorySize, SM_MMA);
    cudaFuncSetAttribute(k_mma<2>, cudaFuncAttributeMaxDynamicSharedMemorySize, SM_MMA);

    if (ctx.ok) {
        // ---- overlapped schedule (identical work every call) ----
        cudaStream_t s2 = ctx.s2;

        k_deg_wsplit<<<nDegBlocks + nSplitBlocks, 256>>>(dst, E, W1, W2, nDegBlocks);
        k_scan1<<<nb, 1024>>>();
        cudaEventRecord(ctx.evFork, 0);

        // s2: scale_h (needs dinv only) overlaps scan3+fill
        cudaStreamWaitEvent(s2, ctx.evFork, 0);
        k_scale_h<<<(M_PAD * (D0 / 4) + 255) / 256, 256, 0, s2>>>(x);
        cudaEventRecord(ctx.evScale, s2);

        k_scan3<<<nb, 1024>>>(E);
        k_fill<<<(E + 1023) / 1024, 256>>>(src, dst, E);
        cudaStreamWaitEvent(0, ctx.evScale, 0);

        // chunk 0 gather, then fork its GEMMs to s2 while chunk 1 gathers
        k_gather256<<<(ROWHALF * 32 + 255) / 256, 256>>>(0, ROWHALF);
        cudaEventRecord(ctx.evG0, 0);

        cudaStreamWaitEvent(s2, ctx.evG0, 0);
        k_mma<1><<<dim3(2, TILE0), 256, SM_MMA, s2>>>(b1, 0);
        k_mma<2><<<dim3(1, TILE0), 256, SM_MMA, s2>>>(nullptr, 0);
        cudaEventRecord(ctx.evM0, s2);

        k_gather256<<<((M_PAD - ROWHALF) * 32 + 255) / 256, 256>>>(ROWHALF, M_PAD);
        k_mma<1><<<dim3(2, TILE1), 256, SM_MMA>>>(b1, TILE0);
        k_mma<2><<<dim3(1, TILE1), 256, SM_MMA>>>(nullptr, TILE0);

        cudaStreamWaitEvent(0, ctx.evM0, 0);
        k_gather128<<<(N_NODES * 32 + 255) / 256, 256>>>(b2, out);
    } else {
        // ---- serial fallback (resource init failed) ----
        k_deg_wsplit<<<nDegBlocks + nSplitBlocks, 256>>>(dst, E, W1, W2, nDegBlocks);
        k_scan1<<<nb, 1024>>>();
        k_scan3<<<nb, 1024>>>(E);
        k_fill<<<(E + 1023) / 1024, 256>>>(src, dst, E);
        k_scale_h<<<(M_PAD * (D0 / 4) + 255) / 256, 256>>>(x);
        k_gather256<<<(M_PAD * 32 + 255) / 256, 256>>>(0, M_PAD);
        k_mma<1><<<dim3(2, NTILE_M), 256, SM_MMA>>>(b1, 0);
        k_mma<2><<<dim3(1, NTILE_M), 256, SM_MMA>>>(nullptr, 0);
        k_gather128<<<(N_NODES * 32 + 255) / 256, 256>>>(b2, out);
    }
}